// round 1
// baseline (speedup 1.0000x reference)
#include <cuda_runtime.h>
#include <math.h>

#define Bv 4
#define Mv 1024
#define Hv 1024
#define NHv 8
#define Dv 128
#define Lv 1024
#define Ev 8
#define Fv 4096
#define NTOK (Bv*Mv)      /* 4096 */
#define LMv (Lv+Mv)       /* 2048 */
#define BHv (Bv*NHv)      /* 32 */

// ---------------- scratch (device globals; no allocation allowed) ----------------
__device__ float g_hall[(size_t)Bv*LMv*Hv];
__device__ float g_q[(size_t)NTOK*Hv];
__device__ float g_k[(size_t)Bv*LMv*Hv];
__device__ float g_v[(size_t)Bv*LMv*Hv];
__device__ float g_scores[(size_t)BHv*Mv*Lv];
__device__ float g_attnout[(size_t)NTOK*Hv];
__device__ float g_proj[(size_t)NTOK*Hv];
__device__ float g_h1[(size_t)NTOK*Hv];
__device__ float g_moe[(size_t)NTOK*Hv];
__device__ float g_act[(size_t)NTOK*Fv];
__device__ int   g_cnt[Ev];
__device__ int   g_elist[Ev*NTOK];
__device__ float g_ew[Ev*NTOK];

// ---------------- concat h_all = [h_cache ; h] per batch ----------------
__global__ void concat_kernel(const float* __restrict__ h_cache, const float* __restrict__ h)
{
    size_t i4 = (size_t)blockIdx.x * blockDim.x + threadIdx.x;
    size_t total4 = (size_t)Bv*LMv*Hv/4;
    if (i4 >= total4) return;
    size_t gi = i4*4;
    int b = (int)(gi / ((size_t)LMv*Hv));
    size_t off = gi - (size_t)b*LMv*Hv;
    float4 val;
    if (off < (size_t)Lv*Hv)
        val = *(const float4*)(h_cache + (size_t)b*Lv*Hv + off);
    else
        val = *(const float4*)(h + (size_t)b*Mv*Hv + (off - (size_t)Lv*Hv));
    *(float4*)(g_hall + gi) = val;
}

// ---------------- generic tiled SGEMM: C[MxN] = A[MxK] @ B[KxN] ----------------
// MODE 0: C = acc
// MODE 1: C = relu(acc + bias[n])                 (A rows gathered via rowidx)
// MODE 2: C[srow[m]*N + n] += wrow[m]*(acc + bias[n])   (scatter-add epilogue)
template<int MODE>
__global__ void sgemm128(const float* __restrict__ A, const float* __restrict__ B,
                         float* __restrict__ C, int M, int N, int K,
                         const int* __restrict__ rowidx, const int* __restrict__ Mptr,
                         const float* __restrict__ bias,
                         const float* __restrict__ wrow, const int* __restrict__ srow)
{
    int Meff = Mptr ? *Mptr : M;
    int m0 = blockIdx.y * 128;
    if (m0 >= Meff) return;
    int n0 = blockIdx.x * 128;
    __shared__ float As[16][132];
    __shared__ float Bs[16][128];
    int tid = threadIdx.x;
    int tr = (tid >> 4) * 8;
    int tc = (tid & 15) * 8;
    float acc[8][8];
    #pragma unroll
    for (int i=0;i<8;i++)
        #pragma unroll
        for (int j=0;j<8;j++) acc[i][j]=0.f;

    for (int k0 = 0; k0 < K; k0 += 16) {
        #pragma unroll
        for (int i = 0; i < 2; i++) {
            int idx = tid + i*256;
            int ar = idx >> 2;
            int ac = (idx & 3) * 4;
            float4 av = make_float4(0.f,0.f,0.f,0.f);
            int gr = m0 + ar;
            if (gr < Meff) {
                int grr = rowidx ? rowidx[gr] : gr;
                av = *(const float4*)(A + (size_t)grr*K + k0 + ac);
            }
            As[ac+0][ar] = av.x; As[ac+1][ar] = av.y;
            As[ac+2][ar] = av.z; As[ac+3][ar] = av.w;
        }
        #pragma unroll
        for (int i = 0; i < 2; i++) {
            int idx = tid + i*256;
            int br = idx >> 5;
            int bc = (idx & 31) * 4;
            *(float4*)&Bs[br][bc] = *(const float4*)(B + (size_t)(k0+br)*N + n0 + bc);
        }
        __syncthreads();
        #pragma unroll
        for (int kk = 0; kk < 16; kk++) {
            float a[8], bb[8];
            *(float4*)&a[0]  = *(float4*)&As[kk][tr];
            *(float4*)&a[4]  = *(float4*)&As[kk][tr+4];
            *(float4*)&bb[0] = *(float4*)&Bs[kk][tc];
            *(float4*)&bb[4] = *(float4*)&Bs[kk][tc+4];
            #pragma unroll
            for (int i=0;i<8;i++)
                #pragma unroll
                for (int j=0;j<8;j++)
                    acc[i][j] = fmaf(a[i], bb[j], acc[i][j]);
        }
        __syncthreads();
    }
    #pragma unroll
    for (int i=0;i<8;i++) {
        int gr = m0 + tr + i;
        if (gr >= Meff) continue;
        if (MODE == 0) {
            float* cp = C + (size_t)gr*N + n0 + tc;
            #pragma unroll
            for (int j=0;j<8;j++) cp[j] = acc[i][j];
        } else if (MODE == 1) {
            float* cp = C + (size_t)gr*N + n0 + tc;
            #pragma unroll
            for (int j=0;j<8;j++) cp[j] = fmaxf(acc[i][j] + bias[n0+tc+j], 0.f);
        } else {
            int tok = srow[gr];
            float w = wrow[gr];
            float* cp = C + (size_t)tok*N + n0 + tc;
            #pragma unroll
            for (int j=0;j<8;j++) cp[j] += w * (acc[i][j] + bias[n0+tc+j]);
        }
    }
}

// ---------------- banded scores: s[bh,m,j] = (q_m . k_{m+j} + q_m . pos[:,j]) / 32 ----------------
__global__ void band_scores_kernel(const float* __restrict__ q, const float* __restrict__ kmat,
                                   const float* __restrict__ pos)
{
    int bh = blockIdx.z, b = bh >> 3, nh = bh & 7;
    int m0 = blockIdx.y * 32, j0 = blockIdx.x * 32;
    __shared__ float qs[64][33];    // [d][m]
    __shared__ float kst[64][65];   // [d][row], rows m0+j0 .. m0+j0+63
    __shared__ float ps[64][36];    // [d][j]
    int tid = threadIdx.x;
    int tm = tid >> 4, tj = tid & 15;
    int ml = tm*2, jl = tj*2;
    float acc00=0.f, acc01=0.f, acc10=0.f, acc11=0.f;
    for (int dc = 0; dc < 128; dc += 64) {
        #pragma unroll
        for (int i=0;i<2;i++){
            int idx = tid + i*256;
            int m = idx >> 4;
            int d4 = (idx & 15) * 4;
            float4 v = *(const float4*)(q + ((size_t)(b*Mv + m0 + m))*Hv + nh*Dv + dc + d4);
            qs[d4+0][m]=v.x; qs[d4+1][m]=v.y; qs[d4+2][m]=v.z; qs[d4+3][m]=v.w;
        }
        #pragma unroll
        for (int i=0;i<4;i++){
            int idx = tid + i*256;
            int r = idx >> 4;
            int d4 = (idx & 15) * 4;
            float4 v = *(const float4*)(kmat + ((size_t)(b*LMv + m0 + j0 + r))*Hv + nh*Dv + dc + d4);
            kst[d4+0][r]=v.x; kst[d4+1][r]=v.y; kst[d4+2][r]=v.z; kst[d4+3][r]=v.w;
        }
        #pragma unroll
        for (int i=0;i<2;i++){
            int idx = tid + i*256;
            int d = idx >> 3;
            int j4 = (idx & 7) * 4;
            *(float4*)&ps[d][j4] = *(const float4*)(pos + (size_t)(dc + d)*Lv + j0 + j4);
        }
        __syncthreads();
        int s = ml + jl;
        #pragma unroll 8
        for (int d = 0; d < 64; d++) {
            float a0 = qs[d][ml], a1 = qs[d][ml+1];
            float p0 = ps[d][jl], p1 = ps[d][jl+1];
            float k0v = kst[d][s], k1v = kst[d][s+1], k2v = kst[d][s+2];
            acc00 = fmaf(a0, k0v + p0, acc00);
            acc01 = fmaf(a0, k1v + p1, acc01);
            acc10 = fmaf(a1, k1v + p0, acc10);
            acc11 = fmaf(a1, k2v + p1, acc11);
        }
        __syncthreads();
    }
    const float sc = 0.03125f;   // 1/sqrt(1024)
    size_t base = ((size_t)bh*Mv + m0+ml)*Lv + j0 + jl;
    g_scores[base]        = acc00*sc;
    g_scores[base+1]      = acc01*sc;
    g_scores[base+Lv]     = acc10*sc;
    g_scores[base+Lv+1]   = acc11*sc;
}

// ---------------- row softmax over L=1024 ----------------
__global__ void softmax_kernel()
{
    size_t row = blockIdx.x;
    float4* p = (float4*)(g_scores + row*Lv);
    int tid = threadIdx.x;
    float4 x = p[tid];
    __shared__ float red[256];
    float m = fmaxf(fmaxf(x.x,x.y), fmaxf(x.z,x.w));
    red[tid] = m; __syncthreads();
    for (int s=128; s>0; s>>=1){ if (tid<s) red[tid]=fmaxf(red[tid],red[tid+s]); __syncthreads(); }
    float mx = red[0]; __syncthreads();
    x.x = expf(x.x-mx); x.y = expf(x.y-mx); x.z = expf(x.z-mx); x.w = expf(x.w-mx);
    red[tid] = x.x+x.y+x.z+x.w; __syncthreads();
    for (int s=128; s>0; s>>=1){ if (tid<s) red[tid]+=red[tid+s]; __syncthreads(); }
    float inv = 1.f/red[0];
    x.x*=inv; x.y*=inv; x.z*=inv; x.w*=inv;
    p[tid] = x;
}

// ---------------- banded attn @ V: out[bh,m,d] = sum_j p[m,j] v[m+j,d] ----------------
__global__ void av_kernel(const float* __restrict__ vmat)
{
    int bh = blockIdx.y, b = bh >> 3, nh = bh & 7;
    int m0 = blockIdx.x * 32;
    int tid = threadIdx.x;
    int lane = tid & 7;
    int m = tid >> 3;
    __shared__ float pt[32][36];
    __shared__ float vs[64][132];
    float acc[16];
    #pragma unroll
    for (int i=0;i<16;i++) acc[i]=0.f;
    for (int j0 = 0; j0 < Lv; j0 += 32) {
        {
            int r = tid >> 3, c4 = (tid & 7)*4;
            *(float4*)&pt[r][c4] = *(const float4*)(g_scores + ((size_t)bh*Mv + m0 + r)*Lv + j0 + c4);
        }
        #pragma unroll
        for (int i=0;i<8;i++){
            int idx = tid + i*256;
            int r = idx >> 5;
            int c4 = (idx & 31)*4;
            *(float4*)&vs[r][c4] = *(const float4*)(vmat + ((size_t)(b*LMv + m0 + j0 + r))*Hv + nh*Dv + c4);
        }
        __syncthreads();
        #pragma unroll 4
        for (int j=0;j<32;j++){
            float pv = pt[m][j];
            const float* vr = &vs[m + j][lane*16];
            float4 v0 = *(const float4*)(vr);
            float4 v1 = *(const float4*)(vr+4);
            float4 v2 = *(const float4*)(vr+8);
            float4 v3 = *(const float4*)(vr+12);
            acc[0]=fmaf(pv,v0.x,acc[0]);  acc[1]=fmaf(pv,v0.y,acc[1]);
            acc[2]=fmaf(pv,v0.z,acc[2]);  acc[3]=fmaf(pv,v0.w,acc[3]);
            acc[4]=fmaf(pv,v1.x,acc[4]);  acc[5]=fmaf(pv,v1.y,acc[5]);
            acc[6]=fmaf(pv,v1.z,acc[6]);  acc[7]=fmaf(pv,v1.w,acc[7]);
            acc[8]=fmaf(pv,v2.x,acc[8]);  acc[9]=fmaf(pv,v2.y,acc[9]);
            acc[10]=fmaf(pv,v2.z,acc[10]); acc[11]=fmaf(pv,v2.w,acc[11]);
            acc[12]=fmaf(pv,v3.x,acc[12]); acc[13]=fmaf(pv,v3.y,acc[13]);
            acc[14]=fmaf(pv,v3.z,acc[14]); acc[15]=fmaf(pv,v3.w,acc[15]);
        }
        __syncthreads();
    }
    float* op = g_attnout + ((size_t)(b*Mv + m0 + m))*Hv + nh*Dv + lane*16;
    #pragma unroll
    for (int i=0;i<16;i++) op[i] = acc[i];
}

// ---------------- h1 = LN(h + proj) ----------------
__global__ void ln1_kernel(const float* __restrict__ h, const float* __restrict__ g,
                           const float* __restrict__ bet)
{
    int row = blockIdx.x;
    int tid = threadIdx.x;
    float4 x = ((const float4*)(h + (size_t)row*Hv))[tid];
    float4 y = ((const float4*)(g_proj + (size_t)row*Hv))[tid];
    x.x+=y.x; x.y+=y.y; x.z+=y.z; x.w+=y.w;
    __shared__ float rs[256], rq[256];
    rs[tid] = x.x+x.y+x.z+x.w;
    rq[tid] = x.x*x.x + x.y*x.y + x.z*x.z + x.w*x.w;
    __syncthreads();
    for (int t=128;t>0;t>>=1){ if(tid<t){rs[tid]+=rs[tid+t]; rq[tid]+=rq[tid+t];} __syncthreads(); }
    float mean = rs[0] * (1.f/(float)Hv);
    float var  = rq[0] * (1.f/(float)Hv) - mean*mean;
    float inv = rsqrtf(var + 1e-5f);
    float4 gg = ((const float4*)g)[tid];
    float4 bb = ((const float4*)bet)[tid];
    float4 o;
    o.x = (x.x-mean)*inv*gg.x + bb.x;
    o.y = (x.y-mean)*inv*gg.y + bb.y;
    o.z = (x.z-mean)*inv*gg.z + bb.z;
    o.w = (x.w-mean)*inv*gg.w + bb.w;
    ((float4*)(g_h1 + (size_t)row*Hv))[tid] = o;
}

// ---------------- zero moe + counters ----------------
__global__ void zero_kernel()
{
    size_t i = (size_t)blockIdx.x*256 + threadIdx.x;
    ((float4*)g_moe)[i] = make_float4(0.f,0.f,0.f,0.f);
    if (i < Ev) g_cnt[i] = 0;
}

// ---------------- gating: top-2 routing ----------------
__global__ void gate_kernel(const float* __restrict__ gw, const float* __restrict__ gb)
{
    int t = blockIdx.x;
    int tid = threadIdx.x;
    float acc[8];
    #pragma unroll
    for (int e=0;e<8;e++) acc[e]=0.f;
    for (int hh = tid; hh < Hv; hh += 256) {
        float x = g_h1[(size_t)t*Hv + hh];
        const float* gr = gw + (size_t)hh*8;
        #pragma unroll
        for (int e=0;e<8;e++) acc[e] = fmaf(x, gr[e], acc[e]);
    }
    #pragma unroll
    for (int e=0;e<8;e++)
        #pragma unroll
        for (int o=16;o>0;o>>=1) acc[e] += __shfl_xor_sync(0xffffffffu, acc[e], o);
    __shared__ float s[8][8];
    int w = tid >> 5, ln = tid & 31;
    if (ln == 0) {
        #pragma unroll
        for (int e=0;e<8;e++) s[w][e] = acc[e];
    }
    __syncthreads();
    if (tid == 0) {
        float lg[8];
        #pragma unroll
        for (int e=0;e<8;e++){
            float v = gb[e];
            #pragma unroll
            for (int w2=0;w2<8;w2++) v += s[w2][e];
            lg[e] = v;
        }
        int i0 = 0;
        #pragma unroll
        for (int e=1;e<8;e++) if (lg[e] > lg[i0]) i0 = e;
        int i1 = (i0 == 0) ? 1 : 0;
        #pragma unroll
        for (int e=0;e<8;e++) if (e != i0 && lg[e] > lg[i1]) i1 = e;
        float e1 = expf(lg[i1]-lg[i0]);
        float inv = 1.f/(1.f+e1);
        float w0 = inv, w1 = e1*inv;
        int p0 = atomicAdd(&g_cnt[i0],1);
        g_elist[i0*NTOK+p0]=t; g_ew[i0*NTOK+p0]=w0;
        int p1 = atomicAdd(&g_cnt[i1],1);
        g_elist[i1*NTOK+p1]=t; g_ew[i1*NTOK+p1]=w1;
    }
}

// ---------------- final: mom_new = .7*mom + moe ; h2 = LN(h1 - mom_new) ----------------
__global__ void final_kernel(const float* __restrict__ mom, const float* __restrict__ g,
                             const float* __restrict__ bet, float* __restrict__ out, int write_mom)
{
    int row = blockIdx.x, tid = threadIdx.x;
    float4 mo = ((const float4*)(g_moe + (size_t)row*Hv))[tid];
    float4 mm = ((const float4*)(mom + (size_t)row*Hv))[tid];
    float4 mn;
    mn.x = 0.7f*mm.x + mo.x; mn.y = 0.7f*mm.y + mo.y;
    mn.z = 0.7f*mm.z + mo.z; mn.w = 0.7f*mm.w + mo.w;
    float4 h1v = ((const float4*)(g_h1 + (size_t)row*Hv))[tid];
    float4 x;
    x.x = h1v.x - mn.x; x.y = h1v.y - mn.y; x.z = h1v.z - mn.z; x.w = h1v.w - mn.w;
    __shared__ float rs[256], rq[256];
    rs[tid] = x.x+x.y+x.z+x.w;
    rq[tid] = x.x*x.x + x.y*x.y + x.z*x.z + x.w*x.w;
    __syncthreads();
    for (int t=128;t>0;t>>=1){ if(tid<t){rs[tid]+=rs[tid+t]; rq[tid]+=rq[tid+t];} __syncthreads(); }
    float mean = rs[0] * (1.f/(float)Hv);
    float var  = rq[0] * (1.f/(float)Hv) - mean*mean;
    float inv = rsqrtf(var + 1e-5f);
    float4 gg = ((const float4*)g)[tid];
    float4 bb = ((const float4*)bet)[tid];
    float4 o;
    o.x = (x.x-mean)*inv*gg.x + bb.x;
    o.y = (x.y-mean)*inv*gg.y + bb.y;
    o.z = (x.z-mean)*inv*gg.z + bb.z;
    o.w = (x.w-mean)*inv*gg.w + bb.w;
    ((float4*)(out + (size_t)row*Hv))[tid] = o;
    if (write_mom)
        ((float4*)(out + (size_t)NTOK*Hv + (size_t)row*Hv))[tid] = mn;
}

extern "C" void kernel_launch(void* const* d_in, const int* in_sizes, int n_in,
                              void* d_out, int out_size)
{
    const float* h       = (const float*)d_in[0];
    const float* h_cache = (const float*)d_in[1];
    const float* pos     = (const float*)d_in[2];
    const float* mom     = (const float*)d_in[3];
    const float* Wq      = (const float*)d_in[4];
    const float* Wk      = (const float*)d_in[5];
    const float* Wv      = (const float*)d_in[6];
    const float* Wo      = (const float*)d_in[7];
    const float* gw      = (const float*)d_in[8];
    const float* gb      = (const float*)d_in[9];
    const float* w1      = (const float*)d_in[10];
    const float* b1      = (const float*)d_in[11];
    const float* w2      = (const float*)d_in[12];
    const float* b2      = (const float*)d_in[13];
    const float* ln1g    = (const float*)d_in[14];
    const float* ln1b    = (const float*)d_in[15];
    const float* ln2g    = (const float*)d_in[16];
    const float* ln2b    = (const float*)d_in[17];
    float* out = (float*)d_out;

    float *p_hall, *p_q, *p_k, *p_v, *p_attn, *p_proj, *p_h1, *p_moe, *p_act, *p_ew;
    int *p_cnt, *p_elist;
    cudaGetSymbolAddress((void**)&p_hall, g_hall);
    cudaGetSymbolAddress((void**)&p_q, g_q);
    cudaGetSymbolAddress((void**)&p_k, g_k);
    cudaGetSymbolAddress((void**)&p_v, g_v);
    cudaGetSymbolAddress((void**)&p_attn, g_attnout);
    cudaGetSymbolAddress((void**)&p_proj, g_proj);
    cudaGetSymbolAddress((void**)&p_h1, g_h1);
    cudaGetSymbolAddress((void**)&p_moe, g_moe);
    cudaGetSymbolAddress((void**)&p_act, g_act);
    cudaGetSymbolAddress((void**)&p_ew, g_ew);
    cudaGetSymbolAddress((void**)&p_cnt, g_cnt);
    cudaGetSymbolAddress((void**)&p_elist, g_elist);

    int write_mom = (out_size >= 2*NTOK*Hv) ? 1 : 0;

    // concat cache+current
    concat_kernel<<<8192, 256>>>(h_cache, h);
    // projections
    sgemm128<0><<<dim3(8,32), 256>>>(h,      Wq, p_q, NTOK,     Hv, Hv, nullptr, nullptr, nullptr, nullptr, nullptr);
    sgemm128<0><<<dim3(8,64), 256>>>(p_hall, Wk, p_k, Bv*LMv,   Hv, Hv, nullptr, nullptr, nullptr, nullptr, nullptr);
    sgemm128<0><<<dim3(8,64), 256>>>(p_hall, Wv, p_v, Bv*LMv,   Hv, Hv, nullptr, nullptr, nullptr, nullptr, nullptr);
    // banded attention
    band_scores_kernel<<<dim3(32,32,32), 256>>>(p_q, p_k, pos);
    softmax_kernel<<<BHv*Mv, 256>>>();
    av_kernel<<<dim3(32,32), 256>>>(p_v);
    // output projection + LN1
    sgemm128<0><<<dim3(8,32), 256>>>(p_attn, Wo, p_proj, NTOK, Hv, Hv, nullptr, nullptr, nullptr, nullptr, nullptr);
    ln1_kernel<<<NTOK, 256>>>(h, ln1g, ln1b);
    // MoE
    zero_kernel<<<NTOK, 256>>>();
    gate_kernel<<<NTOK, 256>>>(gw, gb);
    for (int e = 0; e < Ev; e++) {
        sgemm128<1><<<dim3(32,32), 256>>>(p_h1, w1 + (size_t)e*Hv*Fv, p_act, NTOK, Fv, Hv,
                                          p_elist + e*NTOK, p_cnt + e, b1 + (size_t)e*Fv,
                                          nullptr, nullptr);
        sgemm128<2><<<dim3(8,32), 256>>>(p_act, w2 + (size_t)e*Fv*Hv, p_moe, NTOK, Hv, Fv,
                                         nullptr, p_cnt + e, b2 + (size_t)e*Hv,
                                         p_ew + e*NTOK, p_elist + e*NTOK);
    }
    // momentum + LN2 + outputs
    final_kernel<<<NTOK, 256>>>(mom, ln2g, ln2b, out, write_mom);
}

// round 2
// speedup vs baseline: 1.6928x; 1.6928x over previous
#include <cuda_runtime.h>
#include <math.h>

#define Bv 4
#define Mv 1024
#define Hv 1024
#define NHv 8
#define Dv 128
#define Lv 1024
#define Ev 8
#define Fv 4096
#define NTOK (Bv*Mv)      /* 4096 */
#define LMv (Lv+Mv)       /* 2048 */
#define BHv (Bv*NHv)      /* 32 */

// ---------------- scratch (device globals; no allocation allowed) ----------------
__device__ float g_hall[(size_t)Bv*LMv*Hv];
__device__ float g_q[(size_t)NTOK*Hv];
__device__ float g_k[(size_t)Bv*LMv*Hv];
__device__ float g_v[(size_t)Bv*LMv*Hv];
__device__ float g_scores[(size_t)BHv*Mv*Lv];
__device__ float g_attnout[(size_t)NTOK*Hv];
__device__ float g_proj[(size_t)NTOK*Hv];
__device__ float g_h1[(size_t)NTOK*Hv];
__device__ float g_moe[(size_t)NTOK*Hv];
__device__ float g_act[(size_t)NTOK*Fv];
__device__ int   g_cnt[Ev];
__device__ int   g_elist[Ev*NTOK];
__device__ float g_ew[Ev*NTOK];

__device__ __forceinline__ unsigned f2tf(float x){
    unsigned u; asm("cvt.rna.tf32.f32 %0, %1;" : "=r"(u) : "f"(x)); return u;
}

// ---------------- concat h_all = [h_cache ; h] per batch ----------------
__global__ void concat_kernel(const float* __restrict__ h_cache, const float* __restrict__ h)
{
    size_t i4 = (size_t)blockIdx.x * blockDim.x + threadIdx.x;
    size_t total4 = (size_t)Bv*LMv*Hv/4;
    if (i4 >= total4) return;
    size_t gi = i4*4;
    int b = (int)(gi / ((size_t)LMv*Hv));
    size_t off = gi - (size_t)b*LMv*Hv;
    float4 val;
    if (off < (size_t)Lv*Hv)
        val = *(const float4*)(h_cache + (size_t)b*Lv*Hv + off);
    else
        val = *(const float4*)(h + (size_t)b*Mv*Hv + (off - (size_t)Lv*Hv));
    *(float4*)(g_hall + gi) = val;
}

// ---------------- TF32 tensor-core GEMM: C[MxN] = A[MxK] @ B[KxN] ----------------
// 128x128 tile, BK=32, 256 threads (8 warps as 2x4), warp tile 64x32.
// MODE 0: C = acc
// MODE 1: C = relu(acc + bias[n])                       (A rows gathered via rowidx)
// MODE 2: C[srow[m]*N + n] += wrow[m]*(acc + bias[n])   (scatter-add epilogue)
template<int MODE>
__global__ void tgemm(const float* __restrict__ A, const float* __restrict__ B,
                      float* __restrict__ C, int M, int N, int K,
                      const int* __restrict__ rowidx, const int* __restrict__ Mptr,
                      const float* __restrict__ bias,
                      const float* __restrict__ wrow, const int* __restrict__ srow)
{
    int Meff = Mptr ? *Mptr : M;
    int m0 = blockIdx.y * 128;
    if (m0 >= Meff) return;
    int n0 = blockIdx.x * 128;

    __shared__ unsigned As[32][132];   // [k][m]
    __shared__ unsigned Bs[32][132];   // [k][n]

    int tid  = threadIdx.x;
    int wid  = tid >> 5;
    int lane = tid & 31;
    int wr = wid >> 2;            // 0..1  -> 64-row slab
    int wc = wid & 3;             // 0..3  -> 32-col slab
    int g   = lane >> 2;          // groupID 0..7
    int tig = lane & 3;           // thread-in-group 0..3

    float acc[4][4][4];
    #pragma unroll
    for (int a=0;a<4;a++)
        #pragma unroll
        for (int b=0;b<4;b++)
            #pragma unroll
            for (int c=0;c<4;c++) acc[a][b][c]=0.f;

    for (int k0 = 0; k0 < K; k0 += 32) {
        // load A tile: 128 rows x 32 k  (1024 float4 / 256 thr = 4 each)
        #pragma unroll
        for (int i = 0; i < 4; i++) {
            int lin = tid + i*256;
            int row = lin >> 3;
            int k4  = (lin & 7) * 4;
            float4 av = make_float4(0.f,0.f,0.f,0.f);
            int gr = m0 + row;
            if (gr < Meff) {
                int grr = (MODE==1 && rowidx) ? rowidx[gr] : gr;
                av = *(const float4*)(A + (size_t)grr*K + k0 + k4);
            }
            As[k4+0][row]=f2tf(av.x); As[k4+1][row]=f2tf(av.y);
            As[k4+2][row]=f2tf(av.z); As[k4+3][row]=f2tf(av.w);
        }
        // load B tile: 32 k x 128 n
        #pragma unroll
        for (int i = 0; i < 4; i++) {
            int lin = tid + i*256;
            int kr = lin >> 5;
            int n4 = (lin & 31) * 4;
            float4 bv = *(const float4*)(B + (size_t)(k0+kr)*N + n0 + n4);
            Bs[kr][n4+0]=f2tf(bv.x); Bs[kr][n4+1]=f2tf(bv.y);
            Bs[kr][n4+2]=f2tf(bv.z); Bs[kr][n4+3]=f2tf(bv.w);
        }
        __syncthreads();
        #pragma unroll
        for (int ks = 0; ks < 4; ks++) {
            int kk = ks*8;
            unsigned af[4][4], bf[4][2];
            #pragma unroll
            for (int mt=0;mt<4;mt++){
                int rb = wr*64 + mt*16;
                af[mt][0] = As[kk+tig  ][rb+g  ];
                af[mt][1] = As[kk+tig  ][rb+g+8];
                af[mt][2] = As[kk+tig+4][rb+g  ];
                af[mt][3] = As[kk+tig+4][rb+g+8];
            }
            #pragma unroll
            for (int nt=0;nt<4;nt++){
                int cb = wc*32 + nt*8 + g;
                bf[nt][0] = Bs[kk+tig  ][cb];
                bf[nt][1] = Bs[kk+tig+4][cb];
            }
            #pragma unroll
            for (int mt=0;mt<4;mt++)
                #pragma unroll
                for (int nt=0;nt<4;nt++)
                    asm volatile(
                        "mma.sync.aligned.m16n8k8.row.col.f32.tf32.tf32.f32 "
                        "{%0,%1,%2,%3}, {%4,%5,%6,%7}, {%8,%9}, {%0,%1,%2,%3};"
                        : "+f"(acc[mt][nt][0]), "+f"(acc[mt][nt][1]),
                          "+f"(acc[mt][nt][2]), "+f"(acc[mt][nt][3])
                        : "r"(af[mt][0]), "r"(af[mt][1]), "r"(af[mt][2]), "r"(af[mt][3]),
                          "r"(bf[nt][0]), "r"(bf[nt][1]));
        }
        __syncthreads();
    }

    // epilogue
    #pragma unroll
    for (int mt=0;mt<4;mt++){
        #pragma unroll
        for (int half=0; half<2; half++){
            int rm = m0 + wr*64 + mt*16 + g + half*8;
            if (rm >= Meff) continue;
            #pragma unroll
            for (int nt=0;nt<4;nt++){
                int cn = n0 + wc*32 + nt*8 + tig*2;
                float c0 = acc[mt][nt][half*2+0];
                float c1 = acc[mt][nt][half*2+1];
                if (MODE == 0) {
                    float* cp = C + (size_t)rm*N + cn;
                    cp[0] = c0; cp[1] = c1;
                } else if (MODE == 1) {
                    float* cp = C + (size_t)rm*N + cn;
                    cp[0] = fmaxf(c0 + bias[cn],   0.f);
                    cp[1] = fmaxf(c1 + bias[cn+1], 0.f);
                } else {
                    int tok = srow[rm];
                    float w = wrow[rm];
                    float* cp = C + (size_t)tok*N + cn;
                    cp[0] += w * (c0 + bias[cn]);
                    cp[1] += w * (c1 + bias[cn+1]);
                }
            }
        }
    }
}

// ---------------- banded scores: s[bh,m,j] = (q_m . k_{m+j} + q_m . pos[:,j]) / 32 ----------------
__global__ void band_scores_kernel(const float* __restrict__ q, const float* __restrict__ kmat,
                                   const float* __restrict__ pos)
{
    int bh = blockIdx.z, b = bh >> 3, nh = bh & 7;
    int m0 = blockIdx.y * 32, j0 = blockIdx.x * 32;
    __shared__ float qs[64][33];    // [d][m]
    __shared__ float kst[64][65];   // [d][row], rows m0+j0 .. m0+j0+63
    __shared__ float ps[64][36];    // [d][j]
    int tid = threadIdx.x;
    int tm = tid >> 4, tj = tid & 15;
    int ml = tm*2, jl = tj*2;
    float acc00=0.f, acc01=0.f, acc10=0.f, acc11=0.f;
    for (int dc = 0; dc < 128; dc += 64) {
        #pragma unroll
        for (int i=0;i<2;i++){
            int idx = tid + i*256;
            int m = idx >> 4;
            int d4 = (idx & 15) * 4;
            float4 v = *(const float4*)(q + ((size_t)(b*Mv + m0 + m))*Hv + nh*Dv + dc + d4);
            qs[d4+0][m]=v.x; qs[d4+1][m]=v.y; qs[d4+2][m]=v.z; qs[d4+3][m]=v.w;
        }
        #pragma unroll
        for (int i=0;i<4;i++){
            int idx = tid + i*256;
            int r = idx >> 4;
            int d4 = (idx & 15) * 4;
            float4 v = *(const float4*)(kmat + ((size_t)(b*LMv + m0 + j0 + r))*Hv + nh*Dv + dc + d4);
            kst[d4+0][r]=v.x; kst[d4+1][r]=v.y; kst[d4+2][r]=v.z; kst[d4+3][r]=v.w;
        }
        #pragma unroll
        for (int i=0;i<2;i++){
            int idx = tid + i*256;
            int d = idx >> 3;
            int j4 = (idx & 7) * 4;
            *(float4*)&ps[d][j4] = *(const float4*)(pos + (size_t)(dc + d)*Lv + j0 + j4);
        }
        __syncthreads();
        int s = ml + jl;
        #pragma unroll 8
        for (int d = 0; d < 64; d++) {
            float a0 = qs[d][ml], a1 = qs[d][ml+1];
            float p0 = ps[d][jl], p1 = ps[d][jl+1];
            float k0v = kst[d][s], k1v = kst[d][s+1], k2v = kst[d][s+2];
            acc00 = fmaf(a0, k0v + p0, acc00);
            acc01 = fmaf(a0, k1v + p1, acc01);
            acc10 = fmaf(a1, k1v + p0, acc10);
            acc11 = fmaf(a1, k2v + p1, acc11);
        }
        __syncthreads();
    }
    const float sc = 0.03125f;   // 1/sqrt(1024)
    size_t base = ((size_t)bh*Mv + m0+ml)*Lv + j0 + jl;
    g_scores[base]        = acc00*sc;
    g_scores[base+1]      = acc01*sc;
    g_scores[base+Lv]     = acc10*sc;
    g_scores[base+Lv+1]   = acc11*sc;
}

// ---------------- row softmax over L=1024 ----------------
__global__ void softmax_kernel()
{
    size_t row = blockIdx.x;
    float4* p = (float4*)(g_scores + row*Lv);
    int tid = threadIdx.x;
    float4 x = p[tid];
    __shared__ float red[256];
    float m = fmaxf(fmaxf(x.x,x.y), fmaxf(x.z,x.w));
    red[tid] = m; __syncthreads();
    for (int s=128; s>0; s>>=1){ if (tid<s) red[tid]=fmaxf(red[tid],red[tid+s]); __syncthreads(); }
    float mx = red[0]; __syncthreads();
    x.x = expf(x.x-mx); x.y = expf(x.y-mx); x.z = expf(x.z-mx); x.w = expf(x.w-mx);
    red[tid] = x.x+x.y+x.z+x.w; __syncthreads();
    for (int s=128; s>0; s>>=1){ if (tid<s) red[tid]+=red[tid+s]; __syncthreads(); }
    float inv = 1.f/red[0];
    x.x*=inv; x.y*=inv; x.z*=inv; x.w*=inv;
    p[tid] = x;
}

// ---------------- banded attn @ V: out[bh,m,d] = sum_j p[m,j] v[m+j,d] ----------------
__global__ void av_kernel(const float* __restrict__ vmat)
{
    int bh = blockIdx.y, b = bh >> 3, nh = bh & 7;
    int m0 = blockIdx.x * 32;
    int tid = threadIdx.x;
    int lane = tid & 7;
    int m = tid >> 3;
    __shared__ float pt[32][36];
    __shared__ float vs[64][132];
    float acc[16];
    #pragma unroll
    for (int i=0;i<16;i++) acc[i]=0.f;
    for (int j0 = 0; j0 < Lv; j0 += 32) {
        {
            int r = tid >> 3, c4 = (tid & 7)*4;
            *(float4*)&pt[r][c4] = *(const float4*)(g_scores + ((size_t)bh*Mv + m0 + r)*Lv + j0 + c4);
        }
        #pragma unroll
        for (int i=0;i<8;i++){
            int idx = tid + i*256;
            int r = idx >> 5;
            int c4 = (idx & 31)*4;
            *(float4*)&vs[r][c4] = *(const float4*)(vmat + ((size_t)(b*LMv + m0 + j0 + r))*Hv + nh*Dv + c4);
        }
        __syncthreads();
        #pragma unroll 4
        for (int j=0;j<32;j++){
            float pv = pt[m][j];
            const float* vr = &vs[m + j][lane*16];
            float4 v0 = *(const float4*)(vr);
            float4 v1 = *(const float4*)(vr+4);
            float4 v2 = *(const float4*)(vr+8);
            float4 v3 = *(const float4*)(vr+12);
            acc[0]=fmaf(pv,v0.x,acc[0]);  acc[1]=fmaf(pv,v0.y,acc[1]);
            acc[2]=fmaf(pv,v0.z,acc[2]);  acc[3]=fmaf(pv,v0.w,acc[3]);
            acc[4]=fmaf(pv,v1.x,acc[4]);  acc[5]=fmaf(pv,v1.y,acc[5]);
            acc[6]=fmaf(pv,v1.z,acc[6]);  acc[7]=fmaf(pv,v1.w,acc[7]);
            acc[8]=fmaf(pv,v2.x,acc[8]);  acc[9]=fmaf(pv,v2.y,acc[9]);
            acc[10]=fmaf(pv,v2.z,acc[10]); acc[11]=fmaf(pv,v2.w,acc[11]);
            acc[12]=fmaf(pv,v3.x,acc[12]); acc[13]=fmaf(pv,v3.y,acc[13]);
            acc[14]=fmaf(pv,v3.z,acc[14]); acc[15]=fmaf(pv,v3.w,acc[15]);
        }
        __syncthreads();
    }
    float* op = g_attnout + ((size_t)(b*Mv + m0 + m))*Hv + nh*Dv + lane*16;
    #pragma unroll
    for (int i=0;i<16;i++) op[i] = acc[i];
}

// ---------------- h1 = LN(h + proj) ----------------
__global__ void ln1_kernel(const float* __restrict__ h, const float* __restrict__ g,
                           const float* __restrict__ bet)
{
    int row = blockIdx.x;
    int tid = threadIdx.x;
    float4 x = ((const float4*)(h + (size_t)row*Hv))[tid];
    float4 y = ((const float4*)(g_proj + (size_t)row*Hv))[tid];
    x.x+=y.x; x.y+=y.y; x.z+=y.z; x.w+=y.w;
    __shared__ float rs[256], rq[256];
    rs[tid] = x.x+x.y+x.z+x.w;
    rq[tid] = x.x*x.x + x.y*x.y + x.z*x.z + x.w*x.w;
    __syncthreads();
    for (int t=128;t>0;t>>=1){ if(tid<t){rs[tid]+=rs[tid+t]; rq[tid]+=rq[tid+t];} __syncthreads(); }
    float mean = rs[0] * (1.f/(float)Hv);
    float var  = rq[0] * (1.f/(float)Hv) - mean*mean;
    float inv = rsqrtf(var + 1e-5f);
    float4 gg = ((const float4*)g)[tid];
    float4 bb = ((const float4*)bet)[tid];
    float4 o;
    o.x = (x.x-mean)*inv*gg.x + bb.x;
    o.y = (x.y-mean)*inv*gg.y + bb.y;
    o.z = (x.z-mean)*inv*gg.z + bb.z;
    o.w = (x.w-mean)*inv*gg.w + bb.w;
    ((float4*)(g_h1 + (size_t)row*Hv))[tid] = o;
}

// ---------------- zero moe + counters ----------------
__global__ void zero_kernel()
{
    size_t i = (size_t)blockIdx.x*256 + threadIdx.x;
    ((float4*)g_moe)[i] = make_float4(0.f,0.f,0.f,0.f);
    if (i < Ev) g_cnt[i] = 0;
}

// ---------------- gating: top-2 routing ----------------
__global__ void gate_kernel(const float* __restrict__ gw, const float* __restrict__ gb)
{
    int t = blockIdx.x;
    int tid = threadIdx.x;
    float acc[8];
    #pragma unroll
    for (int e=0;e<8;e++) acc[e]=0.f;
    for (int hh = tid; hh < Hv; hh += 256) {
        float x = g_h1[(size_t)t*Hv + hh];
        const float* gr = gw + (size_t)hh*8;
        #pragma unroll
        for (int e=0;e<8;e++) acc[e] = fmaf(x, gr[e], acc[e]);
    }
    #pragma unroll
    for (int e=0;e<8;e++)
        #pragma unroll
        for (int o=16;o>0;o>>=1) acc[e] += __shfl_xor_sync(0xffffffffu, acc[e], o);
    __shared__ float s[8][8];
    int w = tid >> 5, ln = tid & 31;
    if (ln == 0) {
        #pragma unroll
        for (int e=0;e<8;e++) s[w][e] = acc[e];
    }
    __syncthreads();
    if (tid == 0) {
        float lg[8];
        #pragma unroll
        for (int e=0;e<8;e++){
            float v = gb[e];
            #pragma unroll
            for (int w2=0;w2<8;w2++) v += s[w2][e];
            lg[e] = v;
        }
        int i0 = 0;
        #pragma unroll
        for (int e=1;e<8;e++) if (lg[e] > lg[i0]) i0 = e;
        int i1 = (i0 == 0) ? 1 : 0;
        #pragma unroll
        for (int e=0;e<8;e++) if (e != i0 && lg[e] > lg[i1]) i1 = e;
        float e1 = expf(lg[i1]-lg[i0]);
        float inv = 1.f/(1.f+e1);
        float w0 = inv, w1 = e1*inv;
        int p0 = atomicAdd(&g_cnt[i0],1);
        g_elist[i0*NTOK+p0]=t; g_ew[i0*NTOK+p0]=w0;
        int p1 = atomicAdd(&g_cnt[i1],1);
        g_elist[i1*NTOK+p1]=t; g_ew[i1*NTOK+p1]=w1;
    }
}

// ---------------- final: mom_new = .7*mom + moe ; h2 = LN(h1 - mom_new) ----------------
__global__ void final_kernel(const float* __restrict__ mom, const float* __restrict__ g,
                             const float* __restrict__ bet, float* __restrict__ out, int write_mom)
{
    int row = blockIdx.x, tid = threadIdx.x;
    float4 mo = ((const float4*)(g_moe + (size_t)row*Hv))[tid];
    float4 mm = ((const float4*)(mom + (size_t)row*Hv))[tid];
    float4 mn;
    mn.x = 0.7f*mm.x + mo.x; mn.y = 0.7f*mm.y + mo.y;
    mn.z = 0.7f*mm.z + mo.z; mn.w = 0.7f*mm.w + mo.w;
    float4 h1v = ((const float4*)(g_h1 + (size_t)row*Hv))[tid];
    float4 x;
    x.x = h1v.x - mn.x; x.y = h1v.y - mn.y; x.z = h1v.z - mn.z; x.w = h1v.w - mn.w;
    __shared__ float rs[256], rq[256];
    rs[tid] = x.x+x.y+x.z+x.w;
    rq[tid] = x.x*x.x + x.y*x.y + x.z*x.z + x.w*x.w;
    __syncthreads();
    for (int t=128;t>0;t>>=1){ if(tid<t){rs[tid]+=rs[tid+t]; rq[tid]+=rq[tid+t];} __syncthreads(); }
    float mean = rs[0] * (1.f/(float)Hv);
    float var  = rq[0] * (1.f/(float)Hv) - mean*mean;
    float inv = rsqrtf(var + 1e-5f);
    float4 gg = ((const float4*)g)[tid];
    float4 bb = ((const float4*)bet)[tid];
    float4 o;
    o.x = (x.x-mean)*inv*gg.x + bb.x;
    o.y = (x.y-mean)*inv*gg.y + bb.y;
    o.z = (x.z-mean)*inv*gg.z + bb.z;
    o.w = (x.w-mean)*inv*gg.w + bb.w;
    ((float4*)(out + (size_t)row*Hv))[tid] = o;
    if (write_mom)
        ((float4*)(out + (size_t)NTOK*Hv + (size_t)row*Hv))[tid] = mn;
}

extern "C" void kernel_launch(void* const* d_in, const int* in_sizes, int n_in,
                              void* d_out, int out_size)
{
    const float* h       = (const float*)d_in[0];
    const float* h_cache = (const float*)d_in[1];
    const float* pos     = (const float*)d_in[2];
    const float* mom     = (const float*)d_in[3];
    const float* Wq      = (const float*)d_in[4];
    const float* Wk      = (const float*)d_in[5];
    const float* Wv      = (const float*)d_in[6];
    const float* Wo      = (const float*)d_in[7];
    const float* gw      = (const float*)d_in[8];
    const float* gb      = (const float*)d_in[9];
    const float* w1      = (const float*)d_in[10];
    const float* b1      = (const float*)d_in[11];
    const float* w2      = (const float*)d_in[12];
    const float* b2      = (const float*)d_in[13];
    const float* ln1g    = (const float*)d_in[14];
    const float* ln1b    = (const float*)d_in[15];
    const float* ln2g    = (const float*)d_in[16];
    const float* ln2b    = (const float*)d_in[17];
    float* out = (float*)d_out;

    float *p_hall, *p_q, *p_k, *p_v, *p_attn, *p_proj, *p_h1, *p_moe, *p_act, *p_ew;
    int *p_cnt, *p_elist;
    cudaGetSymbolAddress((void**)&p_hall, g_hall);
    cudaGetSymbolAddress((void**)&p_q, g_q);
    cudaGetSymbolAddress((void**)&p_k, g_k);
    cudaGetSymbolAddress((void**)&p_v, g_v);
    cudaGetSymbolAddress((void**)&p_attn, g_attnout);
    cudaGetSymbolAddress((void**)&p_proj, g_proj);
    cudaGetSymbolAddress((void**)&p_h1, g_h1);
    cudaGetSymbolAddress((void**)&p_moe, g_moe);
    cudaGetSymbolAddress((void**)&p_act, g_act);
    cudaGetSymbolAddress((void**)&p_ew, g_ew);
    cudaGetSymbolAddress((void**)&p_cnt, g_cnt);
    cudaGetSymbolAddress((void**)&p_elist, g_elist);

    int write_mom = (out_size >= 2*NTOK*Hv) ? 1 : 0;

    // concat cache+current
    concat_kernel<<<8192, 256>>>(h_cache, h);
    // projections (tensor cores, tf32)
    tgemm<0><<<dim3(8,32), 256>>>(h,      Wq, p_q, NTOK,   Hv, Hv, nullptr, nullptr, nullptr, nullptr, nullptr);
    tgemm<0><<<dim3(8,64), 256>>>(p_hall, Wk, p_k, Bv*LMv, Hv, Hv, nullptr, nullptr, nullptr, nullptr, nullptr);
    tgemm<0><<<dim3(8,64), 256>>>(p_hall, Wv, p_v, Bv*LMv, Hv, Hv, nullptr, nullptr, nullptr, nullptr, nullptr);
    // banded attention
    band_scores_kernel<<<dim3(32,32,32), 256>>>(p_q, p_k, pos);
    softmax_kernel<<<BHv*Mv, 256>>>();
    av_kernel<<<dim3(32,32), 256>>>(p_v);
    // output projection + LN1
    tgemm<0><<<dim3(8,32), 256>>>(p_attn, Wo, p_proj, NTOK, Hv, Hv, nullptr, nullptr, nullptr, nullptr, nullptr);
    ln1_kernel<<<NTOK, 256>>>(h, ln1g, ln1b);
    // MoE
    zero_kernel<<<NTOK, 256>>>();
    gate_kernel<<<NTOK, 256>>>(gw, gb);
    for (int e = 0; e < Ev; e++) {
        tgemm<1><<<dim3(32,32), 256>>>(p_h1, w1 + (size_t)e*Hv*Fv, p_act, NTOK, Fv, Hv,
                                       p_elist + e*NTOK, p_cnt + e, b1 + (size_t)e*Fv,
                                       nullptr, nullptr);
        tgemm<2><<<dim3(8,32), 256>>>(p_act, w2 + (size_t)e*Fv*Hv, p_moe, NTOK, Hv, Fv,
                                      nullptr, p_cnt + e, b2 + (size_t)e*Hv,
                                      p_ew + e*NTOK, p_elist + e*NTOK);
    }
    // momentum + LN2 + outputs
    final_kernel<<<NTOK, 256>>>(mom, ln2g, ln2b, out, write_mom);
}

// round 4
// speedup vs baseline: 2.6462x; 1.5632x over previous
#include <cuda_runtime.h>
#include <cuda_fp16.h>
#include <math.h>

#define Bv 4
#define Mv 1024
#define Hv 1024
#define NHv 8
#define Dv 128
#define Lv 1024
#define Ev 8
#define Fv 4096
#define NTOK (Bv*Mv)      /* 4096 */
#define LMv (Lv+Mv)       /* 2048 */
#define BHv (Bv*NHv)      /* 32 */

// ---------------- scratch (device globals; no allocation allowed) ----------------
__device__ float  g_q[(size_t)NTOK*Hv];
__device__ float  g_k[(size_t)Bv*LMv*Hv];
__device__ float  g_v[(size_t)Bv*LMv*Hv];
__device__ float  g_scores[(size_t)BHv*Mv*Lv];
__device__ float  g_proj[(size_t)NTOK*Hv];
__device__ float  g_h1[(size_t)NTOK*Hv];
__device__ float  g_moe[(size_t)NTOK*Hv];
__device__ int    g_cnt[Ev];
__device__ int    g_elist[Ev*NTOK];
__device__ float  g_ew[Ev*NTOK];
// fp16 operand copies
__device__ __half g_hall16[(size_t)Bv*LMv*Hv];
__device__ __half g_h16[(size_t)NTOK*Hv];
__device__ __half g_wq16[(size_t)Hv*Hv];
__device__ __half g_wk16[(size_t)Hv*Hv];
__device__ __half g_wv16[(size_t)Hv*Hv];
__device__ __half g_wo16[(size_t)Hv*Hv];
__device__ __half g_w1h[(size_t)Ev*Hv*Fv];
__device__ __half g_w2h[(size_t)Ev*Fv*Hv];
__device__ __half g_attn16[(size_t)NTOK*Hv];
__device__ __half g_h1h[(size_t)NTOK*Hv];
__device__ __half g_act16[(size_t)NTOK*Fv];

__device__ __forceinline__ unsigned sptr(const void* p){
    unsigned r;
    asm("{.reg .u64 t; cvta.to.shared.u64 t, %1; cvt.u32.u64 %0, t;}" : "=r"(r) : "l"(p));
    return r;
}

// ---------------- fp32 -> fp16 conversion (8 elems/thread) ----------------
__global__ void cvt_kernel(const float* __restrict__ src, __half* __restrict__ dst, size_t n)
{
    size_t i = ((size_t)blockIdx.x*256 + threadIdx.x)*8;
    if (i >= n) return;
    float4 a = *(const float4*)(src+i);
    float4 b = *(const float4*)(src+i+4);
    __half2 h0 = __floats2half2_rn(a.x,a.y);
    __half2 h1 = __floats2half2_rn(a.z,a.w);
    __half2 h2 = __floats2half2_rn(b.x,b.y);
    __half2 h3 = __floats2half2_rn(b.z,b.w);
    uint4 o;
    o.x = *(unsigned*)&h0; o.y = *(unsigned*)&h1;
    o.z = *(unsigned*)&h2; o.w = *(unsigned*)&h3;
    *(uint4*)(dst+i) = o;
}

// ---------------- concat h_all = [h_cache ; h] -> fp16 ----------------
__global__ void concat_kernel(const float* __restrict__ h_cache, const float* __restrict__ h)
{
    size_t i4 = (size_t)blockIdx.x * blockDim.x + threadIdx.x;
    size_t total4 = (size_t)Bv*LMv*Hv/4;
    if (i4 >= total4) return;
    size_t gi = i4*4;
    int b = (int)(gi / ((size_t)LMv*Hv));
    size_t off = gi - (size_t)b*LMv*Hv;
    float4 val;
    if (off < (size_t)Lv*Hv)
        val = *(const float4*)(h_cache + (size_t)b*Lv*Hv + off);
    else
        val = *(const float4*)(h + (size_t)b*Mv*Hv + (off - (size_t)Lv*Hv));
    __half2 h0 = __floats2half2_rn(val.x,val.y);
    __half2 h1 = __floats2half2_rn(val.z,val.w);
    uint2 o; o.x = *(unsigned*)&h0; o.y = *(unsigned*)&h1;
    *(uint2*)(g_hall16 + gi) = o;
}

// ---------------- fp16 tensor-core GEMM, 128x128x32, cp.async double buffer ----------
// A fp16 [M,K] row-major (MODE1: rows gathered via rowidx), B fp16 [K,N] row-major.
// MODE 0: C(f32) = acc
// MODE 1: C16(f16) = relu(acc + bias[n])
// MODE 2: C(f32)[srow[m]*N + n] += wrow[m]*(acc + bias[n])
#define ASTR 40
#define BSTR 136
template<int MODE>
__global__ void __launch_bounds__(256,2) hgemm(
    const __half* __restrict__ A, const __half* __restrict__ B,
    float* __restrict__ C, int M, int N, int K,
    const int* __restrict__ rowidx, const int* __restrict__ Mptr,
    const float* __restrict__ bias,
    const float* __restrict__ wrow, const int* __restrict__ srow,
    __half* __restrict__ C16)
{
    int Meff = Mptr ? *Mptr : M;
    int m0 = blockIdx.y * 128;
    if (m0 >= Meff) return;
    int n0 = blockIdx.x * 128;

    __shared__ __half As[2][128*ASTR];
    __shared__ __half Bs[2][32*BSTR];

    int tid = threadIdx.x;
    int wid = tid >> 5, lane = tid & 31;
    int wr = wid >> 2, wc = wid & 3;
    int g = lane >> 2, tig = lane & 3;

    // --- per-thread load slots (constant across k-tiles) ---
    int arow0 = tid >> 2,           ach0 = tid & 3;
    int arow1 = (tid+256) >> 2,     ach1 = (tid+256) & 3;
    int gr0 = m0 + arow0, gr1 = m0 + arow1;
    bool v0 = gr0 < Meff, v1 = gr1 < Meff;
    int grr0 = gr0, grr1 = gr1;
    if (MODE == 1 && rowidx) { grr0 = v0 ? rowidx[gr0] : 0; grr1 = v1 ? rowidx[gr1] : 0; }
    const __half* asrc0 = A + (size_t)grr0*K + ach0*8;
    const __half* asrc1 = A + (size_t)grr1*K + ach1*8;
    unsigned adst0[2], adst1[2];
    adst0[0] = sptr(&As[0][arow0*ASTR + ach0*8]);
    adst0[1] = sptr(&As[1][arow0*ASTR + ach0*8]);
    adst1[0] = sptr(&As[0][arow1*ASTR + ach1*8]);
    adst1[1] = sptr(&As[1][arow1*ASTR + ach1*8]);
    int asz0 = v0 ? 16 : 0, asz1 = v1 ? 16 : 0;
    int bk0 = tid >> 4,         bc0 = tid & 15;
    int bk1 = (tid+256) >> 4,   bc1 = (tid+256) & 15;
    const __half* bsrc0 = B + (size_t)bk0*N + n0 + bc0*8;
    const __half* bsrc1 = B + (size_t)bk1*N + n0 + bc1*8;
    unsigned bdst0[2], bdst1[2];
    bdst0[0] = sptr(&Bs[0][bk0*BSTR + bc0*8]);
    bdst0[1] = sptr(&Bs[1][bk0*BSTR + bc0*8]);
    bdst1[0] = sptr(&Bs[0][bk1*BSTR + bc1*8]);
    bdst1[1] = sptr(&Bs[1][bk1*BSTR + bc1*8]);

    float acc[4][4][4];
    #pragma unroll
    for (int a=0;a<4;a++)
        #pragma unroll
        for (int b=0;b<4;b++)
            #pragma unroll
            for (int c=0;c<4;c++) acc[a][b][c]=0.f;

    #define ISSUE(s, kt) do { \
        size_t ka = (size_t)(kt)*32; \
        size_t kb = (size_t)(kt)*32*N; \
        asm volatile("cp.async.cg.shared.global [%0], [%1], 16, %2;" :: "r"(adst0[s]), "l"(asrc0 + ka), "r"(asz0)); \
        asm volatile("cp.async.cg.shared.global [%0], [%1], 16, %2;" :: "r"(adst1[s]), "l"(asrc1 + ka), "r"(asz1)); \
        asm volatile("cp.async.cg.shared.global [%0], [%1], 16;" :: "r"(bdst0[s]), "l"(bsrc0 + kb)); \
        asm volatile("cp.async.cg.shared.global [%0], [%1], 16;" :: "r"(bdst1[s]), "l"(bsrc1 + kb)); \
        asm volatile("cp.async.commit_group;"); \
    } while(0)

    int nK = K >> 5;
    ISSUE(0, 0);
    unsigned abase[2] = { sptr(&As[0][0]), sptr(&As[1][0]) };
    unsigned bbase[2] = { sptr(&Bs[0][0]), sptr(&Bs[1][0]) };
    int arow = wr*64 + (lane & 15);
    int acolbase = (lane >> 4) * 8;
    int brow = lane & 15;

    for (int kt = 0; kt < nK; kt++) {
        int s = kt & 1;
        if (kt + 1 < nK) {
            ISSUE(1-s, kt+1);
            asm volatile("cp.async.wait_group 1;");
        } else {
            asm volatile("cp.async.wait_group 0;");
        }
        __syncthreads();
        #pragma unroll
        for (int ks = 0; ks < 2; ks++) {
            unsigned a[4][4], bfr[2][4];
            int acol = ks*16 + acolbase;
            #pragma unroll
            for (int mt=0;mt<4;mt++){
                unsigned ad = abase[s] + (unsigned)(((arow + mt*16)*ASTR + acol)*2);
                asm volatile("ldmatrix.sync.aligned.m8n8.x4.shared.b16 {%0,%1,%2,%3}, [%4];"
                    : "=r"(a[mt][0]), "=r"(a[mt][1]), "=r"(a[mt][2]), "=r"(a[mt][3]) : "r"(ad));
            }
            #pragma unroll
            for (int pr=0;pr<2;pr++){
                int bcol = wc*32 + pr*16 + acolbase;
                unsigned bd = bbase[s] + (unsigned)(((ks*16 + brow)*BSTR + bcol)*2);
                asm volatile("ldmatrix.sync.aligned.m8n8.x4.trans.shared.b16 {%0,%1,%2,%3}, [%4];"
                    : "=r"(bfr[pr][0]), "=r"(bfr[pr][1]), "=r"(bfr[pr][2]), "=r"(bfr[pr][3]) : "r"(bd));
            }
            #pragma unroll
            for (int mt=0;mt<4;mt++)
                #pragma unroll
                for (int nt=0;nt<4;nt++){
                    unsigned b0 = bfr[nt>>1][(nt&1)*2+0];
                    unsigned b1 = bfr[nt>>1][(nt&1)*2+1];
                    asm volatile(
                        "mma.sync.aligned.m16n8k16.row.col.f32.f16.f16.f32 "
                        "{%0,%1,%2,%3}, {%4,%5,%6,%7}, {%8,%9}, {%0,%1,%2,%3};"
                        : "+f"(acc[mt][nt][0]), "+f"(acc[mt][nt][1]),
                          "+f"(acc[mt][nt][2]), "+f"(acc[mt][nt][3])
                        : "r"(a[mt][0]), "r"(a[mt][1]), "r"(a[mt][2]), "r"(a[mt][3]),
                          "r"(b0), "r"(b1));
                }
        }
        __syncthreads();
    }

    // epilogue
    #pragma unroll
    for (int mt=0;mt<4;mt++){
        #pragma unroll
        for (int half=0; half<2; half++){
            int rm = m0 + wr*64 + mt*16 + g + half*8;
            if (rm >= Meff) continue;
            #pragma unroll
            for (int nt=0;nt<4;nt++){
                int cn = n0 + wc*32 + nt*8 + tig*2;
                float c0 = acc[mt][nt][half*2+0];
                float c1 = acc[mt][nt][half*2+1];
                if (MODE == 0) {
                    float* cp = C + (size_t)rm*N + cn;
                    cp[0] = c0; cp[1] = c1;
                } else if (MODE == 1) {
                    __half* cp = C16 + (size_t)rm*N + cn;
                    cp[0] = __float2half_rn(fmaxf(c0 + bias[cn],   0.f));
                    cp[1] = __float2half_rn(fmaxf(c1 + bias[cn+1], 0.f));
                } else {
                    int tok = srow[rm];
                    float w = wrow[rm];
                    float* cp = C + (size_t)tok*N + cn;
                    cp[0] += w * (c0 + bias[cn]);
                    cp[1] += w * (c1 + bias[cn+1]);
                }
            }
        }
    }
}

// ---------------- banded scores: s[bh,m,j] = (q_m . k_{m+j} + q_m . pos[:,j]) / 32 ----------------
__global__ void band_scores_kernel(const float* __restrict__ q, const float* __restrict__ kmat,
                                   const float* __restrict__ pos)
{
    int bh = blockIdx.z, b = bh >> 3, nh = bh & 7;
    int m0 = blockIdx.y * 32, j0 = blockIdx.x * 32;
    __shared__ float qs[64][33];
    __shared__ float kst[64][65];
    __shared__ float ps[64][36];
    int tid = threadIdx.x;
    int tm = tid >> 4, tj = tid & 15;
    int ml = tm*2, jl = tj*2;
    float acc00=0.f, acc01=0.f, acc10=0.f, acc11=0.f;
    for (int dc = 0; dc < 128; dc += 64) {
        #pragma unroll
        for (int i=0;i<2;i++){
            int idx = tid + i*256;
            int m = idx >> 4;
            int d4 = (idx & 15) * 4;
            float4 v = *(const float4*)(q + ((size_t)(b*Mv + m0 + m))*Hv + nh*Dv + dc + d4);
            qs[d4+0][m]=v.x; qs[d4+1][m]=v.y; qs[d4+2][m]=v.z; qs[d4+3][m]=v.w;
        }
        #pragma unroll
        for (int i=0;i<4;i++){
            int idx = tid + i*256;
            int r = idx >> 4;
            int d4 = (idx & 15) * 4;
            float4 v = *(const float4*)(kmat + ((size_t)(b*LMv + m0 + j0 + r))*Hv + nh*Dv + dc + d4);
            kst[d4+0][r]=v.x; kst[d4+1][r]=v.y; kst[d4+2][r]=v.z; kst[d4+3][r]=v.w;
        }
        #pragma unroll
        for (int i=0;i<2;i++){
            int idx = tid + i*256;
            int d = idx >> 3;
            int j4 = (idx & 7) * 4;
            *(float4*)&ps[d][j4] = *(const float4*)(pos + (size_t)(dc + d)*Lv + j0 + j4);
        }
        __syncthreads();
        int s = ml + jl;
        #pragma unroll 8
        for (int d = 0; d < 64; d++) {
            float a0 = qs[d][ml], a1 = qs[d][ml+1];
            float p0 = ps[d][jl], p1 = ps[d][jl+1];
            float k0v = kst[d][s], k1v = kst[d][s+1], k2v = kst[d][s+2];
            acc00 = fmaf(a0, k0v + p0, acc00);
            acc01 = fmaf(a0, k1v + p1, acc01);
            acc10 = fmaf(a1, k1v + p0, acc10);
            acc11 = fmaf(a1, k2v + p1, acc11);
        }
        __syncthreads();
    }
    const float sc = 0.03125f;
    size_t base = ((size_t)bh*Mv + m0+ml)*Lv + j0 + jl;
    g_scores[base]        = acc00*sc;
    g_scores[base+1]      = acc01*sc;
    g_scores[base+Lv]     = acc10*sc;
    g_scores[base+Lv+1]   = acc11*sc;
}

// ---------------- row softmax over L=1024 ----------------
__global__ void softmax_kernel()
{
    size_t row = blockIdx.x;
    float4* p = (float4*)(g_scores + row*Lv);
    int tid = threadIdx.x;
    float4 x = p[tid];
    __shared__ float red[256];
    float m = fmaxf(fmaxf(x.x,x.y), fmaxf(x.z,x.w));
    red[tid] = m; __syncthreads();
    for (int s=128; s>0; s>>=1){ if (tid<s) red[tid]=fmaxf(red[tid],red[tid+s]); __syncthreads(); }
    float mx = red[0]; __syncthreads();
    x.x = expf(x.x-mx); x.y = expf(x.y-mx); x.z = expf(x.z-mx); x.w = expf(x.w-mx);
    red[tid] = x.x+x.y+x.z+x.w; __syncthreads();
    for (int s=128; s>0; s>>=1){ if (tid<s) red[tid]+=red[tid+s]; __syncthreads(); }
    float inv = 1.f/red[0];
    x.x*=inv; x.y*=inv; x.z*=inv; x.w*=inv;
    p[tid] = x;
}

// ---------------- banded attn @ V -> fp16 attn out ----------------
__global__ void av_kernel(const float* __restrict__ vmat)
{
    int bh = blockIdx.y, b = bh >> 3, nh = bh & 7;
    int m0 = blockIdx.x * 32;
    int tid = threadIdx.x;
    int lane = tid & 7;
    int m = tid >> 3;
    __shared__ float pt[32][36];
    __shared__ float vs[64][132];
    float acc[16];
    #pragma unroll
    for (int i=0;i<16;i++) acc[i]=0.f;
    for (int j0 = 0; j0 < Lv; j0 += 32) {
        {
            int r = tid >> 3, c4 = (tid & 7)*4;
            *(float4*)&pt[r][c4] = *(const float4*)(g_scores + ((size_t)bh*Mv + m0 + r)*Lv + j0 + c4);
        }
        #pragma unroll
        for (int i=0;i<8;i++){
            int idx = tid + i*256;
            int r = idx >> 5;
            int c4 = (idx & 31)*4;
            *(float4*)&vs[r][c4] = *(const float4*)(vmat + ((size_t)(b*LMv + m0 + j0 + r))*Hv + nh*Dv + c4);
        }
        __syncthreads();
        #pragma unroll 4
        for (int j=0;j<32;j++){
            float pv = pt[m][j];
            const float* vr = &vs[m + j][lane*16];
            float4 v0 = *(const float4*)(vr);
            float4 v1 = *(const float4*)(vr+4);
            float4 v2 = *(const float4*)(vr+8);
            float4 v3 = *(const float4*)(vr+12);
            acc[0]=fmaf(pv,v0.x,acc[0]);  acc[1]=fmaf(pv,v0.y,acc[1]);
            acc[2]=fmaf(pv,v0.z,acc[2]);  acc[3]=fmaf(pv,v0.w,acc[3]);
            acc[4]=fmaf(pv,v1.x,acc[4]);  acc[5]=fmaf(pv,v1.y,acc[5]);
            acc[6]=fmaf(pv,v1.z,acc[6]);  acc[7]=fmaf(pv,v1.w,acc[7]);
            acc[8]=fmaf(pv,v2.x,acc[8]);  acc[9]=fmaf(pv,v2.y,acc[9]);
            acc[10]=fmaf(pv,v2.z,acc[10]); acc[11]=fmaf(pv,v2.w,acc[11]);
            acc[12]=fmaf(pv,v3.x,acc[12]); acc[13]=fmaf(pv,v3.y,acc[13]);
            acc[14]=fmaf(pv,v3.z,acc[14]); acc[15]=fmaf(pv,v3.w,acc[15]);
        }
        __syncthreads();
    }
    __half* op = g_attn16 + ((size_t)(b*Mv + m0 + m))*Hv + nh*Dv + lane*16;
    #pragma unroll
    for (int i=0;i<16;i++) op[i] = __float2half_rn(acc[i]);
}

// ---------------- h1 = LN(h + proj); writes fp32 + fp16 ----------------
__global__ void ln1_kernel(const float* __restrict__ h, const float* __restrict__ g,
                           const float* __restrict__ bet)
{
    int row = blockIdx.x;
    int tid = threadIdx.x;
    float4 x = ((const float4*)(h + (size_t)row*Hv))[tid];
    float4 y = ((const float4*)(g_proj + (size_t)row*Hv))[tid];
    x.x+=y.x; x.y+=y.y; x.z+=y.z; x.w+=y.w;
    __shared__ float rs[256], rq[256];
    rs[tid] = x.x+x.y+x.z+x.w;
    rq[tid] = x.x*x.x + x.y*x.y + x.z*x.z + x.w*x.w;
    __syncthreads();
    for (int t=128;t>0;t>>=1){ if(tid<t){rs[tid]+=rs[tid+t]; rq[tid]+=rq[tid+t];} __syncthreads(); }
    float mean = rs[0] * (1.f/(float)Hv);
    float var  = rq[0] * (1.f/(float)Hv) - mean*mean;
    float inv = rsqrtf(var + 1e-5f);
    float4 gg = ((const float4*)g)[tid];
    float4 bb = ((const float4*)bet)[tid];
    float4 o;
    o.x = (x.x-mean)*inv*gg.x + bb.x;
    o.y = (x.y-mean)*inv*gg.y + bb.y;
    o.z = (x.z-mean)*inv*gg.z + bb.z;
    o.w = (x.w-mean)*inv*gg.w + bb.w;
    ((float4*)(g_h1 + (size_t)row*Hv))[tid] = o;
    __half2 h0 = __floats2half2_rn(o.x,o.y);
    __half2 h1 = __floats2half2_rn(o.z,o.w);
    uint2 u; u.x = *(unsigned*)&h0; u.y = *(unsigned*)&h1;
    ((uint2*)(g_h1h + (size_t)row*Hv))[tid] = u;
}

// ---------------- zero moe + counters ----------------
__global__ void zero_kernel()
{
    size_t i = (size_t)blockIdx.x*256 + threadIdx.x;
    ((float4*)g_moe)[i] = make_float4(0.f,0.f,0.f,0.f);
    if (i < Ev) g_cnt[i] = 0;
}

// ---------------- gating: top-2 routing ----------------
__global__ void gate_kernel(const float* __restrict__ gw, const float* __restrict__ gb)
{
    int t = blockIdx.x;
    int tid = threadIdx.x;
    float acc[8];
    #pragma unroll
    for (int e=0;e<8;e++) acc[e]=0.f;
    for (int hh = tid; hh < Hv; hh += 256) {
        float x = g_h1[(size_t)t*Hv + hh];
        const float* gr = gw + (size_t)hh*8;
        #pragma unroll
        for (int e=0;e<8;e++) acc[e] = fmaf(x, gr[e], acc[e]);
    }
    #pragma unroll
    for (int e=0;e<8;e++)
        #pragma unroll
        for (int o=16;o>0;o>>=1) acc[e] += __shfl_xor_sync(0xffffffffu, acc[e], o);
    __shared__ float s[8][8];
    int w = tid >> 5, ln = tid & 31;
    if (ln == 0) {
        #pragma unroll
        for (int e=0;e<8;e++) s[w][e] = acc[e];
    }
    __syncthreads();
    if (tid == 0) {
        float lg[8];
        #pragma unroll
        for (int e=0;e<8;e++){
            float v = gb[e];
            #pragma unroll
            for (int w2=0;w2<8;w2++) v += s[w2][e];
            lg[e] = v;
        }
        int i0 = 0;
        #pragma unroll
        for (int e=1;e<8;e++) if (lg[e] > lg[i0]) i0 = e;
        int i1 = (i0 == 0) ? 1 : 0;
        #pragma unroll
        for (int e=0;e<8;e++) if (e != i0 && lg[e] > lg[i1]) i1 = e;
        float e1 = expf(lg[i1]-lg[i0]);
        float inv = 1.f/(1.f+e1);
        float w0 = inv, w1 = e1*inv;
        int p0 = atomicAdd(&g_cnt[i0],1);
        g_elist[i0*NTOK+p0]=t; g_ew[i0*NTOK+p0]=w0;
        int p1 = atomicAdd(&g_cnt[i1],1);
        g_elist[i1*NTOK+p1]=t; g_ew[i1*NTOK+p1]=w1;
    }
}

// ---------------- final: mom_new = .7*mom + moe ; h2 = LN(h1 - mom_new) ----------------
__global__ void final_kernel(const float* __restrict__ mom, const float* __restrict__ g,
                             const float* __restrict__ bet, float* __restrict__ out, int write_mom)
{
    int row = blockIdx.x, tid = threadIdx.x;
    float4 mo = ((const float4*)(g_moe + (size_t)row*Hv))[tid];
    float4 mm = ((const float4*)(mom + (size_t)row*Hv))[tid];
    float4 mn;
    mn.x = 0.7f*mm.x + mo.x; mn.y = 0.7f*mm.y + mo.y;
    mn.z = 0.7f*mm.z + mo.z; mn.w = 0.7f*mm.w + mo.w;
    float4 h1v = ((const float4*)(g_h1 + (size_t)row*Hv))[tid];
    float4 x;
    x.x = h1v.x - mn.x; x.y = h1v.y - mn.y; x.z = h1v.z - mn.z; x.w = h1v.w - mn.w;
    __shared__ float rs[256], rq[256];
    rs[tid] = x.x+x.y+x.z+x.w;
    rq[tid] = x.x*x.x + x.y*x.y + x.z*x.z + x.w*x.w;
    __syncthreads();
    for (int t=128;t>0;t>>=1){ if(tid<t){rs[tid]+=rs[tid+t]; rq[tid]+=rq[tid+t];} __syncthreads(); }
    float mean = rs[0] * (1.f/(float)Hv);
    float var  = rq[0] * (1.f/(float)Hv) - mean*mean;
    float inv = rsqrtf(var + 1e-5f);
    float4 gg = ((const float4*)g)[tid];
    float4 bb = ((const float4*)bet)[tid];
    float4 o;
    o.x = (x.x-mean)*inv*gg.x + bb.x;
    o.y = (x.y-mean)*inv*gg.y + bb.y;
    o.z = (x.z-mean)*inv*gg.z + bb.z;
    o.w = (x.w-mean)*inv*gg.w + bb.w;
    ((float4*)(out + (size_t)row*Hv))[tid] = o;
    if (write_mom)
        ((float4*)(out + (size_t)NTOK*Hv + (size_t)row*Hv))[tid] = mn;
}

extern "C" void kernel_launch(void* const* d_in, const int* in_sizes, int n_in,
                              void* d_out, int out_size)
{
    const float* h       = (const float*)d_in[0];
    const float* h_cache = (const float*)d_in[1];
    const float* pos     = (const float*)d_in[2];
    const float* mom     = (const float*)d_in[3];
    const float* Wq      = (const float*)d_in[4];
    const float* Wk      = (const float*)d_in[5];
    const float* Wv      = (const float*)d_in[6];
    const float* Wo      = (const float*)d_in[7];
    const float* gw      = (const float*)d_in[8];
    const float* gb      = (const float*)d_in[9];
    const float* w1      = (const float*)d_in[10];
    const float* b1      = (const float*)d_in[11];
    const float* w2      = (const float*)d_in[12];
    const float* b2      = (const float*)d_in[13];
    const float* ln1g    = (const float*)d_in[14];
    const float* ln1b    = (const float*)d_in[15];
    const float* ln2g    = (const float*)d_in[16];
    const float* ln2b    = (const float*)d_in[17];
    float* out = (float*)d_out;

    float *p_q, *p_k, *p_v, *p_moe, *p_ew;
    __half *p_h16, *p_hall16, *p_wq, *p_wk, *p_wv, *p_wo, *p_w1h, *p_w2h, *p_attn16, *p_h1h, *p_act16;
    int *p_cnt, *p_elist;
    cudaGetSymbolAddress((void**)&p_q, g_q);
    cudaGetSymbolAddress((void**)&p_k, g_k);
    cudaGetSymbolAddress((void**)&p_v, g_v);
    cudaGetSymbolAddress((void**)&p_moe, g_moe);
    cudaGetSymbolAddress((void**)&p_ew, g_ew);
    cudaGetSymbolAddress((void**)&p_cnt, g_cnt);
    cudaGetSymbolAddress((void**)&p_elist, g_elist);
    cudaGetSymbolAddress((void**)&p_h16, g_h16);
    cudaGetSymbolAddress((void**)&p_hall16, g_hall16);
    cudaGetSymbolAddress((void**)&p_wq, g_wq16);
    cudaGetSymbolAddress((void**)&p_wk, g_wk16);
    cudaGetSymbolAddress((void**)&p_wv, g_wv16);
    cudaGetSymbolAddress((void**)&p_wo, g_wo16);
    cudaGetSymbolAddress((void**)&p_w1h, g_w1h);
    cudaGetSymbolAddress((void**)&p_w2h, g_w2h);
    cudaGetSymbolAddress((void**)&p_attn16, g_attn16);
    cudaGetSymbolAddress((void**)&p_h1h, g_h1h);
    cudaGetSymbolAddress((void**)&p_act16, g_act16);
    float* p_proj; cudaGetSymbolAddress((void**)&p_proj, g_proj);

    int write_mom = (out_size >= 2*NTOK*Hv) ? 1 : 0;

    // fp16 operand prep
    concat_kernel<<<8192, 256>>>(h_cache, h);
    cvt_kernel<<<2048, 256>>>(h,  p_h16, (size_t)NTOK*Hv);
    cvt_kernel<<<512,  256>>>(Wq, p_wq, (size_t)Hv*Hv);
    cvt_kernel<<<512,  256>>>(Wk, p_wk, (size_t)Hv*Hv);
    cvt_kernel<<<512,  256>>>(Wv, p_wv, (size_t)Hv*Hv);
    cvt_kernel<<<512,  256>>>(Wo, p_wo, (size_t)Hv*Hv);
    cvt_kernel<<<16384,256>>>(w1, p_w1h, (size_t)Ev*Hv*Fv);
    cvt_kernel<<<16384,256>>>(w2, p_w2h, (size_t)Ev*Fv*Hv);
    // projections (fp16 tensor cores)
    hgemm<0><<<dim3(8,32), 256>>>(p_h16,    p_wq, p_q, NTOK,   Hv, Hv, nullptr, nullptr, nullptr, nullptr, nullptr, nullptr);
    hgemm<0><<<dim3(8,64), 256>>>(p_hall16, p_wk, p_k, Bv*LMv, Hv, Hv, nullptr, nullptr, nullptr, nullptr, nullptr, nullptr);
    hgemm<0><<<dim3(8,64), 256>>>(p_hall16, p_wv, p_v, Bv*LMv, Hv, Hv, nullptr, nullptr, nullptr, nullptr, nullptr, nullptr);
    // banded attention
    band_scores_kernel<<<dim3(32,32,32), 256>>>(p_q, p_k, pos);
    softmax_kernel<<<BHv*Mv, 256>>>();
    av_kernel<<<dim3(32,32), 256>>>(p_v);
    // output projection + LN1
    hgemm<0><<<dim3(8,32), 256>>>(p_attn16, p_wo, p_proj, NTOK, Hv, Hv, nullptr, nullptr, nullptr, nullptr, nullptr, nullptr);
    ln1_kernel<<<NTOK, 256>>>(h, ln1g, ln1b);
    // MoE
    zero_kernel<<<NTOK, 256>>>();
    gate_kernel<<<NTOK, 256>>>(gw, gb);
    for (int e = 0; e < Ev; e++) {
        hgemm<1><<<dim3(32,32), 256>>>(p_h1h, p_w1h + (size_t)e*Hv*Fv, nullptr, NTOK, Fv, Hv,
                                       p_elist + e*NTOK, p_cnt + e, b1 + (size_t)e*Fv,
                                       nullptr, nullptr, p_act16);
        hgemm<2><<<dim3(8,32), 256>>>(p_act16, p_w2h + (size_t)e*Fv*Hv, p_moe, NTOK, Hv, Fv,
                                      nullptr, p_cnt + e, b2 + (size_t)e*Hv,
                                      p_ew + e*NTOK, p_elist + e*NTOK, nullptr);
    }
    // momentum + LN2 + outputs
    final_kernel<<<NTOK, 256>>>(mom, ln2g, ln2b, out, write_mom);
}

// round 5
// speedup vs baseline: 6.1580x; 2.3271x over previous
#include <cuda_runtime.h>
#include <cuda_fp16.h>
#include <math.h>

#define Bv 4
#define Mv 1024
#define Hv 1024
#define NHv 8
#define Dv 128
#define Lv 1024
#define Ev 8
#define Fv 4096
#define NTOK (Bv*Mv)      /* 4096 */
#define LMv (Lv+Mv)       /* 2048 */
#define BHv (Bv*NHv)      /* 32 */
#define SKW 1152          /* skewed row width = 1024 + 128 */

// ---------------- scratch (device globals; no allocation allowed) ----------------
__device__ float  g_sskew[(size_t)BHv*Mv*SKW];   // skewed scores (fp32)
__device__ __half g_p16[(size_t)BHv*Mv*SKW];     // skewed probabilities (fp16, OOB zeros)
__device__ float  g_proj[(size_t)NTOK*Hv];
__device__ float  g_h1[(size_t)NTOK*Hv];
__device__ float  g_moe[(size_t)NTOK*Hv];
__device__ int    g_cnt[Ev];
__device__ int    g_elist[Ev*NTOK];
__device__ float  g_ew[Ev*NTOK];
// fp16 operands
__device__ __half g_hall16[(size_t)Bv*LMv*Hv];
__device__ __half g_h16[(size_t)NTOK*Hv];
__device__ __half g_q16[(size_t)NTOK*Hv];
__device__ __half g_k16[(size_t)Bv*LMv*Hv];
__device__ __half g_v16[(size_t)Bv*LMv*Hv];
__device__ __half g_pos16[(size_t)Dv*Lv];
__device__ __half g_wq16[(size_t)Hv*Hv];
__device__ __half g_wk16[(size_t)Hv*Hv];
__device__ __half g_wv16[(size_t)Hv*Hv];
__device__ __half g_wo16[(size_t)Hv*Hv];
__device__ __half g_w1h[(size_t)Ev*Hv*Fv];
__device__ __half g_w2h[(size_t)Ev*Fv*Hv];
__device__ __half g_attn16[(size_t)NTOK*Hv];
__device__ __half g_h1h[(size_t)NTOK*Hv];
__device__ __half g_act16[(size_t)NTOK*Fv];

__device__ __forceinline__ unsigned sptr(const void* p){
    unsigned r;
    asm("{.reg .u64 t; cvta.to.shared.u64 t, %1; cvt.u32.u64 %0, t;}" : "=r"(r) : "l"(p));
    return r;
}

// ---------------- fp32 -> fp16 conversion (8 elems/thread) ----------------
__global__ void cvt_kernel(const float* __restrict__ src, __half* __restrict__ dst, size_t n)
{
    size_t i = ((size_t)blockIdx.x*256 + threadIdx.x)*8;
    if (i >= n) return;
    float4 a = *(const float4*)(src+i);
    float4 b = *(const float4*)(src+i+4);
    __half2 h0 = __floats2half2_rn(a.x,a.y);
    __half2 h1 = __floats2half2_rn(a.z,a.w);
    __half2 h2 = __floats2half2_rn(b.x,b.y);
    __half2 h3 = __floats2half2_rn(b.z,b.w);
    uint4 o;
    o.x = *(unsigned*)&h0; o.y = *(unsigned*)&h1;
    o.z = *(unsigned*)&h2; o.w = *(unsigned*)&h3;
    *(uint4*)(dst+i) = o;
}

// ---------------- concat h_all = [h_cache ; h] -> fp16 ----------------
__global__ void concat_kernel(const float* __restrict__ h_cache, const float* __restrict__ h)
{
    size_t i4 = (size_t)blockIdx.x * blockDim.x + threadIdx.x;
    size_t total4 = (size_t)Bv*LMv*Hv/4;
    if (i4 >= total4) return;
    size_t gi = i4*4;
    int b = (int)(gi / ((size_t)LMv*Hv));
    size_t off = gi - (size_t)b*LMv*Hv;
    float4 val;
    if (off < (size_t)Lv*Hv)
        val = *(const float4*)(h_cache + (size_t)b*Lv*Hv + off);
    else
        val = *(const float4*)(h + (size_t)b*Mv*Hv + (off - (size_t)Lv*Hv));
    __half2 h0 = __floats2half2_rn(val.x,val.y);
    __half2 h1 = __floats2half2_rn(val.z,val.w);
    uint2 o; o.x = *(unsigned*)&h0; o.y = *(unsigned*)&h1;
    *(uint2*)(g_hall16 + gi) = o;
}

// ---------------- fp16 tensor-core GEMM, 128x128x32 tile, cp.async double buffer ----
// MODE 0: C(f32) = acc
// MODE 1: C16 = relu(acc + bias[n]), A rows gathered via rowidx
// MODE 2: C(f32)[srow[m]*N + n] += wrow[m]*(acc + bias[n])
// MODE 3: batched pos GEMM: z=bh; A=q16 slice (lda=Hv); C=sskew, skewed store *1/32
// MODE 4: C16 = acc
// MODE 5: batched AV GEMM: z=bh; A=p16skew (lda=SKW); B=v16 (+m0 rows, guarded); C16=attn
#define ASTR 40
#define BSTR 136
template<int MODE>
__global__ void __launch_bounds__(256,2) hgemm(
    const __half* __restrict__ A, const __half* __restrict__ B,
    float* __restrict__ C, __half* __restrict__ C16,
    int M, int N, int K, int lda,
    const int* __restrict__ rowidx, const int* __restrict__ Mptr,
    const float* __restrict__ bias,
    const float* __restrict__ wrow, const int* __restrict__ srow)
{
    int m0 = blockIdx.y * 128;
    int n0 = blockIdx.x * 128;
    int Klim = 1 << 30;
    const __half* Ap = A; const __half* Bp = B;
    float* Cp = C; __half* C16p = C16;
    if (MODE == 3) {
        int z = blockIdx.z;
        Ap  += ((size_t)(z>>3)*Mv)*Hv + (size_t)(z&7)*Dv;
        Cp  += (size_t)z*Mv*SKW;
    }
    if (MODE == 5) {
        int z = blockIdx.z;
        Ap  += (size_t)z*Mv*SKW;
        Bp  += ((size_t)(z>>3)*LMv + m0)*Hv;
        n0   = (z&7)*Dv;
        C16p += (size_t)(z>>3)*Mv*Hv;
        Klim = LMv - m0;
    }
    int Meff = Mptr ? *Mptr : M;
    if (m0 >= Meff) return;

    __shared__ __half As[2][128*ASTR];
    __shared__ __half Bs[2][32*BSTR];

    int tid = threadIdx.x;
    int wid = tid >> 5, lane = tid & 31;
    int wr = wid >> 2, wc = wid & 3;
    int g = lane >> 2, tig = lane & 3;

    int arow0 = tid >> 2,           ach0 = tid & 3;
    int arow1 = (tid+256) >> 2,     ach1 = (tid+256) & 3;
    int gr0 = m0 + arow0, gr1 = m0 + arow1;
    bool v0 = gr0 < Meff, v1 = gr1 < Meff;
    int grr0 = gr0, grr1 = gr1;
    if (MODE == 1 && rowidx) { grr0 = v0 ? rowidx[gr0] : 0; grr1 = v1 ? rowidx[gr1] : 0; }
    const __half* asrc0 = Ap + (size_t)grr0*lda + ach0*8;
    const __half* asrc1 = Ap + (size_t)grr1*lda + ach1*8;
    unsigned adst0[2], adst1[2];
    adst0[0] = sptr(&As[0][arow0*ASTR + ach0*8]);
    adst0[1] = sptr(&As[1][arow0*ASTR + ach0*8]);
    adst1[0] = sptr(&As[0][arow1*ASTR + ach1*8]);
    adst1[1] = sptr(&As[1][arow1*ASTR + ach1*8]);
    int asz0 = v0 ? 16 : 0, asz1 = v1 ? 16 : 0;
    int bk0 = tid >> 4,         bc0 = tid & 15;
    int bk1 = (tid+256) >> 4,   bc1 = (tid+256) & 15;
    const __half* bsrc0 = Bp + (size_t)bk0*N + n0 + bc0*8;
    const __half* bsrc1 = Bp + (size_t)bk1*N + n0 + bc1*8;
    unsigned bdst0[2], bdst1[2];
    bdst0[0] = sptr(&Bs[0][bk0*BSTR + bc0*8]);
    bdst0[1] = sptr(&Bs[1][bk0*BSTR + bc0*8]);
    bdst1[0] = sptr(&Bs[0][bk1*BSTR + bc1*8]);
    bdst1[1] = sptr(&Bs[1][bk1*BSTR + bc1*8]);

    float acc[4][4][4];
    #pragma unroll
    for (int a=0;a<4;a++)
        #pragma unroll
        for (int b=0;b<4;b++)
            #pragma unroll
            for (int c=0;c<4;c++) acc[a][b][c]=0.f;

    #define ISSUE(s, kt) do { \
        size_t ka = (size_t)(kt)*32; \
        size_t kb = (size_t)(kt)*32*N; \
        int bs0 = ((kt)*32 + bk0 < Klim) ? 16 : 0; \
        int bs1 = ((kt)*32 + bk1 < Klim) ? 16 : 0; \
        asm volatile("cp.async.cg.shared.global [%0], [%1], 16, %2;" :: "r"(adst0[s]), "l"(asrc0 + ka), "r"(asz0)); \
        asm volatile("cp.async.cg.shared.global [%0], [%1], 16, %2;" :: "r"(adst1[s]), "l"(asrc1 + ka), "r"(asz1)); \
        asm volatile("cp.async.cg.shared.global [%0], [%1], 16, %2;" :: "r"(bdst0[s]), "l"(bsrc0 + kb), "r"(bs0)); \
        asm volatile("cp.async.cg.shared.global [%0], [%1], 16, %2;" :: "r"(bdst1[s]), "l"(bsrc1 + kb), "r"(bs1)); \
        asm volatile("cp.async.commit_group;"); \
    } while(0)

    int nK = K >> 5;
    ISSUE(0, 0);
    unsigned abase[2] = { sptr(&As[0][0]), sptr(&As[1][0]) };
    unsigned bbase[2] = { sptr(&Bs[0][0]), sptr(&Bs[1][0]) };
    int arow = wr*64 + (lane & 15);
    int acolbase = (lane >> 4) * 8;
    int brow = lane & 15;

    for (int kt = 0; kt < nK; kt++) {
        int s = kt & 1;
        if (kt + 1 < nK) {
            ISSUE(1-s, kt+1);
            asm volatile("cp.async.wait_group 1;");
        } else {
            asm volatile("cp.async.wait_group 0;");
        }
        __syncthreads();
        #pragma unroll
        for (int ks = 0; ks < 2; ks++) {
            unsigned a[4][4], bfr[2][4];
            int acol = ks*16 + acolbase;
            #pragma unroll
            for (int mt=0;mt<4;mt++){
                unsigned ad = abase[s] + (unsigned)(((arow + mt*16)*ASTR + acol)*2);
                asm volatile("ldmatrix.sync.aligned.m8n8.x4.shared.b16 {%0,%1,%2,%3}, [%4];"
                    : "=r"(a[mt][0]), "=r"(a[mt][1]), "=r"(a[mt][2]), "=r"(a[mt][3]) : "r"(ad));
            }
            #pragma unroll
            for (int pr=0;pr<2;pr++){
                int bcol = wc*32 + pr*16 + acolbase;
                unsigned bd = bbase[s] + (unsigned)(((ks*16 + brow)*BSTR + bcol)*2);
                asm volatile("ldmatrix.sync.aligned.m8n8.x4.trans.shared.b16 {%0,%1,%2,%3}, [%4];"
                    : "=r"(bfr[pr][0]), "=r"(bfr[pr][1]), "=r"(bfr[pr][2]), "=r"(bfr[pr][3]) : "r"(bd));
            }
            #pragma unroll
            for (int mt=0;mt<4;mt++)
                #pragma unroll
                for (int nt=0;nt<4;nt++){
                    unsigned b0 = bfr[nt>>1][(nt&1)*2+0];
                    unsigned b1 = bfr[nt>>1][(nt&1)*2+1];
                    asm volatile(
                        "mma.sync.aligned.m16n8k16.row.col.f32.f16.f16.f32 "
                        "{%0,%1,%2,%3}, {%4,%5,%6,%7}, {%8,%9}, {%0,%1,%2,%3};"
                        : "+f"(acc[mt][nt][0]), "+f"(acc[mt][nt][1]),
                          "+f"(acc[mt][nt][2]), "+f"(acc[mt][nt][3])
                        : "r"(a[mt][0]), "r"(a[mt][1]), "r"(a[mt][2]), "r"(a[mt][3]),
                          "r"(b0), "r"(b1));
                }
        }
        __syncthreads();
    }

    // epilogue
    #pragma unroll
    for (int mt=0;mt<4;mt++){
        #pragma unroll
        for (int half=0; half<2; half++){
            int rm = m0 + wr*64 + mt*16 + g + half*8;
            if (rm >= Meff) continue;
            #pragma unroll
            for (int nt=0;nt<4;nt++){
                int cn = n0 + wc*32 + nt*8 + tig*2;
                float c0 = acc[mt][nt][half*2+0];
                float c1 = acc[mt][nt][half*2+1];
                if (MODE == 0) {
                    float* cp = Cp + (size_t)rm*N + cn;
                    cp[0] = c0; cp[1] = c1;
                } else if (MODE == 1) {
                    __half* cp = C16p + (size_t)rm*N + cn;
                    cp[0] = __float2half_rn(fmaxf(c0 + bias[cn],   0.f));
                    cp[1] = __float2half_rn(fmaxf(c1 + bias[cn+1], 0.f));
                } else if (MODE == 2) {
                    int tok = srow[rm];
                    float w = wrow[rm];
                    float* cp = Cp + (size_t)tok*N + cn;
                    cp[0] += w * (c0 + bias[cn]);
                    cp[1] += w * (c1 + bias[cn+1]);
                } else if (MODE == 3) {
                    float* cp = Cp + (size_t)rm*SKW + cn + (rm & 127);
                    cp[0] = c0 * 0.03125f;
                    cp[1] = c1 * 0.03125f;
                } else if (MODE == 4) {
                    __half* cp = C16p + (size_t)rm*N + cn;
                    cp[0] = __float2half_rn(c0);
                    cp[1] = __float2half_rn(c1);
                } else { // MODE 5
                    __half* cp = C16p + (size_t)rm*Hv + cn;
                    cp[0] = __float2half_rn(c0);
                    cp[1] = __float2half_rn(c1);
                }
            }
        }
    }
}

// ---------------- banded QK^T via tensor cores, adds into skewed scores ----------------
// grid (8 mtiles, 32 bh), 256 thr, smem: Qs[128][136] + Ks[64][136] halfs (dynamic)
__global__ void __launch_bounds__(256) band_kernel(const __half* __restrict__ q16,
                                                   const __half* __restrict__ k16,
                                                   float* __restrict__ sskew)
{
    extern __shared__ __half dyn[];
    __half* Qs = dyn;               // [128][136]
    __half* Ks = dyn + 128*136;     // [64][136]
    int m0 = blockIdx.x * 128;
    int bh = blockIdx.y;
    int b = bh >> 3, nh = bh & 7;
    int tid = threadIdx.x, wid = tid >> 5, lane = tid & 31;
    int wr = wid >> 2, wc = wid & 3;
    int g = lane >> 2, tig = lane & 3;

    // load Q tile (once)
    {
        int row = tid >> 1, seg = tid & 1;
        const uint4* src = (const uint4*)(q16 + ((size_t)(b*Mv + m0 + row))*Hv + nh*Dv + seg*64);
        uint4* dst = (uint4*)(Qs + row*136 + seg*64);
        #pragma unroll
        for (int i=0;i<8;i++) dst[i] = src[i];
    }
    unsigned qbase = sptr(Qs);
    unsigned kbase = sptr(Ks);
    int a_row = wr*64 + (lane & 15);
    int a_colsel = (lane >> 4) * 8;
    int b_row = wc*16 + (lane & 7) + ((lane >> 4) << 3);
    int b_colsel = ((lane >> 3) & 1) * 8;
    __syncthreads();

    for (int c = 0; c < 18; c++) {
        // load K rows m0+64c .. m0+64c+63 (zero-fill OOB)
        {
            int row = tid >> 2, seg = tid & 3;
            int kr = m0 + c*64 + row;
            uint4 z4 = make_uint4(0,0,0,0);
            const uint4* src = (const uint4*)(k16 + ((size_t)(b*LMv + kr))*Hv + nh*Dv + seg*32);
            uint4* dst = (uint4*)(Ks + row*136 + seg*32);
            bool ok = kr < LMv;
            #pragma unroll
            for (int i=0;i<4;i++) dst[i] = ok ? src[i] : z4;
        }
        __syncthreads();
        float acc[4][2][4];
        #pragma unroll
        for (int a=0;a<4;a++)
            #pragma unroll
            for (int n=0;n<2;n++)
                #pragma unroll
                for (int q=0;q<4;q++) acc[a][n][q]=0.f;
        #pragma unroll
        for (int ks = 0; ks < 8; ks++) {
            unsigned a[4][4], bb[4];
            #pragma unroll
            for (int mt=0;mt<4;mt++){
                unsigned ad = qbase + (unsigned)(((a_row + mt*16)*136 + ks*16 + a_colsel)*2);
                asm volatile("ldmatrix.sync.aligned.m8n8.x4.shared.b16 {%0,%1,%2,%3}, [%4];"
                    : "=r"(a[mt][0]), "=r"(a[mt][1]), "=r"(a[mt][2]), "=r"(a[mt][3]) : "r"(ad));
            }
            {
                unsigned bd = kbase + (unsigned)((b_row*136 + ks*16 + b_colsel)*2);
                asm volatile("ldmatrix.sync.aligned.m8n8.x4.shared.b16 {%0,%1,%2,%3}, [%4];"
                    : "=r"(bb[0]), "=r"(bb[1]), "=r"(bb[2]), "=r"(bb[3]) : "r"(bd));
            }
            #pragma unroll
            for (int mt=0;mt<4;mt++){
                asm volatile(
                    "mma.sync.aligned.m16n8k16.row.col.f32.f16.f16.f32 "
                    "{%0,%1,%2,%3}, {%4,%5,%6,%7}, {%8,%9}, {%0,%1,%2,%3};"
                    : "+f"(acc[mt][0][0]), "+f"(acc[mt][0][1]), "+f"(acc[mt][0][2]), "+f"(acc[mt][0][3])
                    : "r"(a[mt][0]), "r"(a[mt][1]), "r"(a[mt][2]), "r"(a[mt][3]),
                      "r"(bb[0]), "r"(bb[1]));
                asm volatile(
                    "mma.sync.aligned.m16n8k16.row.col.f32.f16.f16.f32 "
                    "{%0,%1,%2,%3}, {%4,%5,%6,%7}, {%8,%9}, {%0,%1,%2,%3};"
                    : "+f"(acc[mt][1][0]), "+f"(acc[mt][1][1]), "+f"(acc[mt][1][2]), "+f"(acc[mt][1][3])
                    : "r"(a[mt][0]), "r"(a[mt][1]), "r"(a[mt][2]), "r"(a[mt][3]),
                      "r"(bb[2]), "r"(bb[3]));
            }
        }
        // epilogue: band clip + accumulate into skewed scores
        #pragma unroll
        for (int mt=0;mt<4;mt++)
            #pragma unroll
            for (int nt=0;nt<2;nt++)
                #pragma unroll
                for (int q=0;q<4;q++){
                    int mi = wr*64 + mt*16 + g + (q>>1)*8;
                    int o  = wc*16 + nt*8 + tig*2 + (q&1);
                    int j = c*64 + o - mi;
                    if ((unsigned)j < 1024u) {
                        size_t idx = ((size_t)(bh*Mv + m0 + mi))*SKW + c*64 + o;
                        sskew[idx] += acc[mt][nt][q] * 0.03125f;
                    }
                }
        __syncthreads();
    }
}

// ---------------- row softmax over skewed scores -> fp16 skewed probs ----------------
__global__ void softmax_kernel(const float* __restrict__ sskew, __half* __restrict__ p16)
{
    size_t row = blockIdx.x;
    int mi = (int)(row & 127);
    const float* src = sskew + row*SKW + mi;
    __half* dst = p16 + row*SKW + mi;
    int tid = threadIdx.x;
    float x[4];
    #pragma unroll
    for (int i=0;i<4;i++) x[i] = src[tid + i*256];
    __shared__ float red[256];
    float m = fmaxf(fmaxf(x[0],x[1]), fmaxf(x[2],x[3]));
    red[tid] = m; __syncthreads();
    for (int s=128; s>0; s>>=1){ if (tid<s) red[tid]=fmaxf(red[tid],red[tid+s]); __syncthreads(); }
    float mx = red[0]; __syncthreads();
    #pragma unroll
    for (int i=0;i<4;i++) x[i] = expf(x[i]-mx);
    red[tid] = x[0]+x[1]+x[2]+x[3]; __syncthreads();
    for (int s=128; s>0; s>>=1){ if (tid<s) red[tid]+=red[tid+s]; __syncthreads(); }
    float inv = 1.f/red[0];
    #pragma unroll
    for (int i=0;i<4;i++) dst[tid + i*256] = __float2half_rn(x[i]*inv);
    if (tid < 128) {
        int u = tid < mi ? tid : tid + 1024;
        p16[row*SKW + u] = __float2half_rn(0.f);
    }
}

// ---------------- h1 = LN(h + proj); writes fp32 + fp16 ----------------
__global__ void ln1_kernel(const float* __restrict__ h, const float* __restrict__ g,
                           const float* __restrict__ bet)
{
    int row = blockIdx.x;
    int tid = threadIdx.x;
    float4 x = ((const float4*)(h + (size_t)row*Hv))[tid];
    float4 y = ((const float4*)(g_proj + (size_t)row*Hv))[tid];
    x.x+=y.x; x.y+=y.y; x.z+=y.z; x.w+=y.w;
    __shared__ float rs[256], rq[256];
    rs[tid] = x.x+x.y+x.z+x.w;
    rq[tid] = x.x*x.x + x.y*x.y + x.z*x.z + x.w*x.w;
    __syncthreads();
    for (int t=128;t>0;t>>=1){ if(tid<t){rs[tid]+=rs[tid+t]; rq[tid]+=rq[tid+t];} __syncthreads(); }
    float mean = rs[0] * (1.f/(float)Hv);
    float var  = rq[0] * (1.f/(float)Hv) - mean*mean;
    float inv = rsqrtf(var + 1e-5f);
    float4 gg = ((const float4*)g)[tid];
    float4 bb = ((const float4*)bet)[tid];
    float4 o;
    o.x = (x.x-mean)*inv*gg.x + bb.x;
    o.y = (x.y-mean)*inv*gg.y + bb.y;
    o.z = (x.z-mean)*inv*gg.z + bb.z;
    o.w = (x.w-mean)*inv*gg.w + bb.w;
    ((float4*)(g_h1 + (size_t)row*Hv))[tid] = o;
    __half2 h0 = __floats2half2_rn(o.x,o.y);
    __half2 h1 = __floats2half2_rn(o.z,o.w);
    uint2 u; u.x = *(unsigned*)&h0; u.y = *(unsigned*)&h1;
    ((uint2*)(g_h1h + (size_t)row*Hv))[tid] = u;
}

// ---------------- zero moe + counters ----------------
__global__ void zero_kernel()
{
    size_t i = (size_t)blockIdx.x*256 + threadIdx.x;
    ((float4*)g_moe)[i] = make_float4(0.f,0.f,0.f,0.f);
    if (i < Ev) g_cnt[i] = 0;
}

// ---------------- gating: top-2 routing ----------------
__global__ void gate_kernel(const float* __restrict__ gw, const float* __restrict__ gb)
{
    int t = blockIdx.x;
    int tid = threadIdx.x;
    float acc[8];
    #pragma unroll
    for (int e=0;e<8;e++) acc[e]=0.f;
    for (int hh = tid; hh < Hv; hh += 256) {
        float x = g_h1[(size_t)t*Hv + hh];
        const float* gr = gw + (size_t)hh*8;
        #pragma unroll
        for (int e=0;e<8;e++) acc[e] = fmaf(x, gr[e], acc[e]);
    }
    #pragma unroll
    for (int e=0;e<8;e++)
        #pragma unroll
        for (int o=16;o>0;o>>=1) acc[e] += __shfl_xor_sync(0xffffffffu, acc[e], o);
    __shared__ float s[8][8];
    int w = tid >> 5, ln = tid & 31;
    if (ln == 0) {
        #pragma unroll
        for (int e=0;e<8;e++) s[w][e] = acc[e];
    }
    __syncthreads();
    if (tid == 0) {
        float lg[8];
        #pragma unroll
        for (int e=0;e<8;e++){
            float v = gb[e];
            #pragma unroll
            for (int w2=0;w2<8;w2++) v += s[w2][e];
            lg[e] = v;
        }
        int i0 = 0;
        #pragma unroll
        for (int e=1;e<8;e++) if (lg[e] > lg[i0]) i0 = e;
        int i1 = (i0 == 0) ? 1 : 0;
        #pragma unroll
        for (int e=0;e<8;e++) if (e != i0 && lg[e] > lg[i1]) i1 = e;
        float e1 = expf(lg[i1]-lg[i0]);
        float inv = 1.f/(1.f+e1);
        float w0 = inv, w1 = e1*inv;
        int p0 = atomicAdd(&g_cnt[i0],1);
        g_elist[i0*NTOK+p0]=t; g_ew[i0*NTOK+p0]=w0;
        int p1 = atomicAdd(&g_cnt[i1],1);
        g_elist[i1*NTOK+p1]=t; g_ew[i1*NTOK+p1]=w1;
    }
}

// ---------------- final: mom_new = .7*mom + moe ; h2 = LN(h1 - mom_new) ----------------
__global__ void final_kernel(const float* __restrict__ mom, const float* __restrict__ g,
                             const float* __restrict__ bet, float* __restrict__ out, int write_mom)
{
    int row = blockIdx.x, tid = threadIdx.x;
    float4 mo = ((const float4*)(g_moe + (size_t)row*Hv))[tid];
    float4 mm = ((const float4*)(mom + (size_t)row*Hv))[tid];
    float4 mn;
    mn.x = 0.7f*mm.x + mo.x; mn.y = 0.7f*mm.y + mo.y;
    mn.z = 0.7f*mm.z + mo.z; mn.w = 0.7f*mm.w + mo.w;
    float4 h1v = ((const float4*)(g_h1 + (size_t)row*Hv))[tid];
    float4 x;
    x.x = h1v.x - mn.x; x.y = h1v.y - mn.y; x.z = h1v.z - mn.z; x.w = h1v.w - mn.w;
    __shared__ float rs[256], rq[256];
    rs[tid] = x.x+x.y+x.z+x.w;
    rq[tid] = x.x*x.x + x.y*x.y + x.z*x.z + x.w*x.w;
    __syncthreads();
    for (int t=128;t>0;t>>=1){ if(tid<t){rs[tid]+=rs[tid+t]; rq[tid]+=rq[tid+t];} __syncthreads(); }
    float mean = rs[0] * (1.f/(float)Hv);
    float var  = rq[0] * (1.f/(float)Hv) - mean*mean;
    float inv = rsqrtf(var + 1e-5f);
    float4 gg = ((const float4*)g)[tid];
    float4 bb = ((const float4*)bet)[tid];
    float4 o;
    o.x = (x.x-mean)*inv*gg.x + bb.x;
    o.y = (x.y-mean)*inv*gg.y + bb.y;
    o.z = (x.z-mean)*inv*gg.z + bb.z;
    o.w = (x.w-mean)*inv*gg.w + bb.w;
    ((float4*)(out + (size_t)row*Hv))[tid] = o;
    if (write_mom)
        ((float4*)(out + (size_t)NTOK*Hv + (size_t)row*Hv))[tid] = mn;
}

extern "C" void kernel_launch(void* const* d_in, const int* in_sizes, int n_in,
                              void* d_out, int out_size)
{
    const float* h       = (const float*)d_in[0];
    const float* h_cache = (const float*)d_in[1];
    const float* pos     = (const float*)d_in[2];
    const float* mom     = (const float*)d_in[3];
    const float* Wq      = (const float*)d_in[4];
    const float* Wk      = (const float*)d_in[5];
    const float* Wv      = (const float*)d_in[6];
    const float* Wo      = (const float*)d_in[7];
    const float* gw      = (const float*)d_in[8];
    const float* gb      = (const float*)d_in[9];
    const float* w1      = (const float*)d_in[10];
    const float* b1      = (const float*)d_in[11];
    const float* w2      = (const float*)d_in[12];
    const float* b2      = (const float*)d_in[13];
    const float* ln1g    = (const float*)d_in[14];
    const float* ln1b    = (const float*)d_in[15];
    const float* ln2g    = (const float*)d_in[16];
    const float* ln2b    = (const float*)d_in[17];
    float* out = (float*)d_out;

    float *p_sskew, *p_moe, *p_ew, *p_proj;
    __half *p_h16, *p_hall16, *p_q16, *p_k16, *p_v16, *p_pos16, *p_p16;
    __half *p_wq, *p_wk, *p_wv, *p_wo, *p_w1h, *p_w2h, *p_attn16, *p_h1h, *p_act16;
    int *p_cnt, *p_elist;
    cudaGetSymbolAddress((void**)&p_sskew, g_sskew);
    cudaGetSymbolAddress((void**)&p_p16, g_p16);
    cudaGetSymbolAddress((void**)&p_moe, g_moe);
    cudaGetSymbolAddress((void**)&p_ew, g_ew);
    cudaGetSymbolAddress((void**)&p_cnt, g_cnt);
    cudaGetSymbolAddress((void**)&p_elist, g_elist);
    cudaGetSymbolAddress((void**)&p_h16, g_h16);
    cudaGetSymbolAddress((void**)&p_hall16, g_hall16);
    cudaGetSymbolAddress((void**)&p_q16, g_q16);
    cudaGetSymbolAddress((void**)&p_k16, g_k16);
    cudaGetSymbolAddress((void**)&p_v16, g_v16);
    cudaGetSymbolAddress((void**)&p_pos16, g_pos16);
    cudaGetSymbolAddress((void**)&p_wq, g_wq16);
    cudaGetSymbolAddress((void**)&p_wk, g_wk16);
    cudaGetSymbolAddress((void**)&p_wv, g_wv16);
    cudaGetSymbolAddress((void**)&p_wo, g_wo16);
    cudaGetSymbolAddress((void**)&p_w1h, g_w1h);
    cudaGetSymbolAddress((void**)&p_w2h, g_w2h);
    cudaGetSymbolAddress((void**)&p_attn16, g_attn16);
    cudaGetSymbolAddress((void**)&p_h1h, g_h1h);
    cudaGetSymbolAddress((void**)&p_act16, g_act16);
    cudaGetSymbolAddress((void**)&p_proj, g_proj);

    static int smem_set = 0;
    if (!smem_set) {
        cudaFuncSetAttribute(band_kernel, cudaFuncAttributeMaxDynamicSharedMemorySize, (128*136 + 64*136)*2);
        smem_set = 1;
    }

    int write_mom = (out_size >= 2*NTOK*Hv) ? 1 : 0;

    // fp16 operand prep
    concat_kernel<<<8192, 256>>>(h_cache, h);
    cvt_kernel<<<2048, 256>>>(h,   p_h16,   (size_t)NTOK*Hv);
    cvt_kernel<<<64,   256>>>(pos, p_pos16, (size_t)Dv*Lv);
    cvt_kernel<<<512,  256>>>(Wq, p_wq, (size_t)Hv*Hv);
    cvt_kernel<<<512,  256>>>(Wk, p_wk, (size_t)Hv*Hv);
    cvt_kernel<<<512,  256>>>(Wv, p_wv, (size_t)Hv*Hv);
    cvt_kernel<<<512,  256>>>(Wo, p_wo, (size_t)Hv*Hv);
    cvt_kernel<<<16384,256>>>(w1, p_w1h, (size_t)Ev*Hv*Fv);
    cvt_kernel<<<16384,256>>>(w2, p_w2h, (size_t)Ev*Fv*Hv);
    // projections -> fp16
    hgemm<4><<<dim3(8,32), 256>>>(p_h16,    p_wq, nullptr, p_q16, NTOK,   Hv, Hv, Hv, nullptr, nullptr, nullptr, nullptr, nullptr);
    hgemm<4><<<dim3(8,64), 256>>>(p_hall16, p_wk, nullptr, p_k16, Bv*LMv, Hv, Hv, Hv, nullptr, nullptr, nullptr, nullptr, nullptr);
    hgemm<4><<<dim3(8,64), 256>>>(p_hall16, p_wv, nullptr, p_v16, Bv*LMv, Hv, Hv, Hv, nullptr, nullptr, nullptr, nullptr, nullptr);
    // pos scores (batched, skewed store)
    hgemm<3><<<dim3(8,8,32), 256>>>(p_q16, p_pos16, p_sskew, nullptr, Mv, Lv, Dv, Hv, nullptr, nullptr, nullptr, nullptr, nullptr);
    // banded QK^T (tensor cores) += skewed scores
    band_kernel<<<dim3(8,32), 256, (128*136 + 64*136)*2>>>(p_q16, p_k16, p_sskew);
    // softmax -> fp16 skewed probs (zeros OOB)
    softmax_kernel<<<BHv*Mv, 256>>>(p_sskew, p_p16);
    // attn @ V as plain GEMM over skewed probs (batched)
    hgemm<5><<<dim3(1,8,32), 256>>>(p_p16, p_v16, nullptr, p_attn16, Mv, Hv, SKW, SKW, nullptr, nullptr, nullptr, nullptr, nullptr);
    // output projection + LN1
    hgemm<0><<<dim3(8,32), 256>>>(p_attn16, p_wo, p_proj, nullptr, NTOK, Hv, Hv, Hv, nullptr, nullptr, nullptr, nullptr, nullptr);
    ln1_kernel<<<NTOK, 256>>>(h, ln1g, ln1b);
    // MoE
    zero_kernel<<<NTOK, 256>>>();
    gate_kernel<<<NTOK, 256>>>(gw, gb);
    for (int e = 0; e < Ev; e++) {
        hgemm<1><<<dim3(32,32), 256>>>(p_h1h, p_w1h + (size_t)e*Hv*Fv, nullptr, p_act16, NTOK, Fv, Hv, Hv,
                                       p_elist + e*NTOK, p_cnt + e, b1 + (size_t)e*Fv, nullptr, nullptr);
        hgemm<2><<<dim3(8,32), 256>>>(p_act16, p_w2h + (size_t)e*Fv*Hv, p_moe, nullptr, NTOK, Hv, Fv, Fv,
                                      nullptr, p_cnt + e, b2 + (size_t)e*Hv, p_ew + e*NTOK, p_elist + e*NTOK);
    }
    // momentum + LN2 + outputs
    final_kernel<<<NTOK, 256>>>(mom, ln2g, ln2b, out, write_mom);
}

// round 6
// speedup vs baseline: 9.2162x; 1.4966x over previous
#include <cuda_runtime.h>
#include <cuda_fp16.h>
#include <math.h>

#define Bv 4
#define Mv 1024
#define Hv 1024
#define NHv 8
#define Dv 128
#define Lv 1024
#define Ev 8
#define Fv 4096
#define NTOK (Bv*Mv)      /* 4096 */
#define LMv (Lv+Mv)       /* 2048 */
#define BHv (Bv*NHv)      /* 32 */
#define SKW 1152          /* skewed row width = 1024 + 128 */

// ---------------- scratch (device globals; no allocation allowed) ----------------
__device__ float  g_sskew[(size_t)BHv*Mv*SKW];   // skewed scores (fp32)
__device__ __half g_p16[(size_t)BHv*Mv*SKW];     // skewed probabilities (fp16, OOB zeros)
__device__ float  g_proj[(size_t)NTOK*Hv];
__device__ float  g_h1[(size_t)NTOK*Hv];
__device__ float  g_moe[(size_t)NTOK*Hv];
__device__ int    g_cnt[Ev];
__device__ int    g_elist[Ev*NTOK];
__device__ float  g_ew[Ev*NTOK];
// fp16 operands
__device__ __half g_hall16[(size_t)Bv*LMv*Hv];
__device__ __half g_h16[(size_t)NTOK*Hv];
__device__ __half g_q16[(size_t)NTOK*Hv];
__device__ __half g_k16[(size_t)Bv*LMv*Hv];
__device__ __half g_v16[(size_t)Bv*LMv*Hv];
__device__ __half g_pos16[(size_t)Dv*Lv];
__device__ __half g_wq16[(size_t)Hv*Hv];
__device__ __half g_wk16[(size_t)Hv*Hv];
__device__ __half g_wv16[(size_t)Hv*Hv];
__device__ __half g_wo16[(size_t)Hv*Hv];
__device__ __half g_w1h[(size_t)Ev*Hv*Fv];
__device__ __half g_w2h[(size_t)Ev*Fv*Hv];
__device__ __half g_attn16[(size_t)NTOK*Hv];
__device__ __half g_h1h[(size_t)NTOK*Hv];
__device__ __half g_act16[(size_t)Ev*NTOK*Fv];   // per-expert packed activations

__device__ __forceinline__ unsigned sptr(const void* p){
    unsigned r;
    asm("{.reg .u64 t; cvta.to.shared.u64 t, %1; cvt.u32.u64 %0, t;}" : "=r"(r) : "l"(p));
    return r;
}

// ---------------- fp32 -> fp16 conversion (8 elems/thread) ----------------
__global__ void cvt_kernel(const float* __restrict__ src, __half* __restrict__ dst, size_t n)
{
    size_t i = ((size_t)blockIdx.x*256 + threadIdx.x)*8;
    if (i >= n) return;
    float4 a = *(const float4*)(src+i);
    float4 b = *(const float4*)(src+i+4);
    __half2 h0 = __floats2half2_rn(a.x,a.y);
    __half2 h1 = __floats2half2_rn(a.z,a.w);
    __half2 h2 = __floats2half2_rn(b.x,b.y);
    __half2 h3 = __floats2half2_rn(b.z,b.w);
    uint4 o;
    o.x = *(unsigned*)&h0; o.y = *(unsigned*)&h1;
    o.z = *(unsigned*)&h2; o.w = *(unsigned*)&h3;
    *(uint4*)(dst+i) = o;
}

// ---------------- concat h_all = [h_cache ; h] -> fp16 ----------------
__global__ void concat_kernel(const float* __restrict__ h_cache, const float* __restrict__ h)
{
    size_t i4 = (size_t)blockIdx.x * blockDim.x + threadIdx.x;
    size_t total4 = (size_t)Bv*LMv*Hv/4;
    if (i4 >= total4) return;
    size_t gi = i4*4;
    int b = (int)(gi / ((size_t)LMv*Hv));
    size_t off = gi - (size_t)b*LMv*Hv;
    float4 val;
    if (off < (size_t)Lv*Hv)
        val = *(const float4*)(h_cache + (size_t)b*Lv*Hv + off);
    else
        val = *(const float4*)(h + (size_t)b*Mv*Hv + (off - (size_t)Lv*Hv));
    __half2 h0 = __floats2half2_rn(val.x,val.y);
    __half2 h1 = __floats2half2_rn(val.z,val.w);
    uint2 o; o.x = *(unsigned*)&h0; o.y = *(unsigned*)&h1;
    *(uint2*)(g_hall16 + gi) = o;
}

// ---------------- fp16 tensor-core GEMM, 128x128x32 tile, 4-stage cp.async ----------
// MODE 0: C(f32) = acc
// MODE 1: z=expert: A rows gathered via elist; C16=act16+e pack = relu(acc+bias)
// MODE 2: z=expert: A=act16+e pack; atomicAdd C[tok*N+n] += w*(acc+bias)
// MODE 3: z=bh: pos GEMM, A=q16 slice (lda=Hv); C=sskew skewed store *1/32
// MODE 4: C16 = acc
// MODE 5: z=bh: AV GEMM, A=p16skew; B=v16 (+m0 rows, guarded); C16=attn16
#define ASTR 40
#define BSTR 136
#define NSTG 4
#define STAGEA (128*ASTR)
#define STAGEB (32*BSTR)
#define SMEMSZ ((STAGEA+STAGEB)*NSTG*2)
template<int MODE>
__global__ void __launch_bounds__(256,2) hgemm(
    const __half* __restrict__ A, const __half* __restrict__ B,
    float* __restrict__ C, __half* __restrict__ C16,
    int M, int N, int K, int lda,
    const int* __restrict__ rowidx, const int* __restrict__ Mptr,
    const float* __restrict__ bias,
    const float* __restrict__ wrow, const int* __restrict__ srow)
{
    extern __shared__ __half dsm[];
    __half* As = dsm;
    __half* Bs = dsm + (size_t)NSTG*STAGEA;

    int m0 = blockIdx.y * 128;
    int n0 = blockIdx.x * 128;
    int Klim = 1 << 30;
    const __half* Ap = A; const __half* Bp = B;
    float* Cp = C; __half* C16p = C16;
    const int* rix = rowidx;
    const int* sro = srow; const float* wro = wrow;
    if (MODE == 1) {
        int e = blockIdx.z;
        rix   = rowidx + e*NTOK;
        Mptr += e;
        Bp   += (size_t)e*K*N;
        bias += (size_t)e*N;
        C16p += (size_t)e*NTOK*N;
    }
    if (MODE == 2) {
        int e = blockIdx.z;
        Ap   += (size_t)e*NTOK*K;
        Mptr += e;
        Bp   += (size_t)e*K*N;
        bias += (size_t)e*N;
        sro   = srow + e*NTOK;
        wro   = wrow + e*NTOK;
    }
    if (MODE == 3) {
        int z = blockIdx.z;
        Ap  += ((size_t)(z>>3)*Mv)*Hv + (size_t)(z&7)*Dv;
        Cp  += (size_t)z*Mv*SKW;
    }
    if (MODE == 5) {
        int z = blockIdx.z;
        Ap  += (size_t)z*Mv*SKW;
        Bp  += ((size_t)(z>>3)*LMv + m0)*Hv;
        n0   = (z&7)*Dv;
        C16p += (size_t)(z>>3)*Mv*Hv;
        Klim = LMv - m0;
    }
    int Meff = Mptr ? *Mptr : M;
    if (m0 >= Meff) return;

    int tid = threadIdx.x;
    int wid = tid >> 5, lane = tid & 31;
    int wr = wid >> 2, wc = wid & 3;
    int g = lane >> 2, tig = lane & 3;

    int arow0 = tid >> 2,           ach0 = tid & 3;
    int arow1 = (tid+256) >> 2,     ach1 = (tid+256) & 3;
    int gr0 = m0 + arow0, gr1 = m0 + arow1;
    bool v0 = gr0 < Meff, v1 = gr1 < Meff;
    int grr0 = gr0, grr1 = gr1;
    if (MODE == 1) { grr0 = v0 ? rix[gr0] : 0; grr1 = v1 ? rix[gr1] : 0; }
    const __half* asrc0 = Ap + (size_t)grr0*lda + ach0*8;
    const __half* asrc1 = Ap + (size_t)grr1*lda + ach1*8;
    unsigned aS = sptr(As), bS = sptr(Bs);
    unsigned adst0 = aS + (unsigned)((arow0*ASTR + ach0*8)*2);
    unsigned adst1 = aS + (unsigned)((arow1*ASTR + ach1*8)*2);
    int asz0 = v0 ? 16 : 0, asz1 = v1 ? 16 : 0;
    int bk0 = tid >> 4,         bc0 = tid & 15;
    int bk1 = (tid+256) >> 4,   bc1 = (tid+256) & 15;
    const __half* bsrc0 = Bp + (size_t)bk0*N + n0 + bc0*8;
    const __half* bsrc1 = Bp + (size_t)bk1*N + n0 + bc1*8;
    unsigned bdst0 = bS + (unsigned)((bk0*BSTR + bc0*8)*2);
    unsigned bdst1 = bS + (unsigned)((bk1*BSTR + bc1*8)*2);

    float acc[4][4][4];
    #pragma unroll
    for (int a=0;a<4;a++)
        #pragma unroll
        for (int b=0;b<4;b++)
            #pragma unroll
            for (int c=0;c<4;c++) acc[a][b][c]=0.f;

    #define ISSUE(s, kt) do { \
        size_t ka = (size_t)(kt)*32; \
        size_t kb = (size_t)(kt)*32*N; \
        int bs0 = ((kt)*32 + bk0 < Klim) ? 16 : 0; \
        int bs1 = ((kt)*32 + bk1 < Klim) ? 16 : 0; \
        unsigned oa = (unsigned)((s)*STAGEA*2), ob = (unsigned)((s)*STAGEB*2); \
        asm volatile("cp.async.cg.shared.global [%0], [%1], 16, %2;" :: "r"(adst0+oa), "l"(asrc0 + ka), "r"(asz0)); \
        asm volatile("cp.async.cg.shared.global [%0], [%1], 16, %2;" :: "r"(adst1+oa), "l"(asrc1 + ka), "r"(asz1)); \
        asm volatile("cp.async.cg.shared.global [%0], [%1], 16, %2;" :: "r"(bdst0+ob), "l"(bsrc0 + kb), "r"(bs0)); \
        asm volatile("cp.async.cg.shared.global [%0], [%1], 16, %2;" :: "r"(bdst1+ob), "l"(bsrc1 + kb), "r"(bs1)); \
        asm volatile("cp.async.commit_group;"); \
    } while(0)

    int nK = K >> 5;
    #pragma unroll
    for (int t = 0; t < NSTG-1; t++) {
        if (t < nK) ISSUE(t, t);
        else asm volatile("cp.async.commit_group;");
    }
    int arow = wr*64 + (lane & 15);
    int acolbase = (lane >> 4) * 8;
    int brow = lane & 15;

    for (int kt = 0; kt < nK; kt++) {
        int tnext = kt + NSTG - 1;
        if (tnext < nK) ISSUE(tnext & (NSTG-1), tnext);
        else asm volatile("cp.async.commit_group;");
        asm volatile("cp.async.wait_group %0;" :: "n"(NSTG-1));
        __syncthreads();
        int s = kt & (NSTG-1);
        unsigned abase = aS + (unsigned)(s*STAGEA*2);
        unsigned bbase = bS + (unsigned)(s*STAGEB*2);
        #pragma unroll
        for (int ks = 0; ks < 2; ks++) {
            unsigned a[4][4], bfr[2][4];
            int acol = ks*16 + acolbase;
            #pragma unroll
            for (int mt=0;mt<4;mt++){
                unsigned ad = abase + (unsigned)(((arow + mt*16)*ASTR + acol)*2);
                asm volatile("ldmatrix.sync.aligned.m8n8.x4.shared.b16 {%0,%1,%2,%3}, [%4];"
                    : "=r"(a[mt][0]), "=r"(a[mt][1]), "=r"(a[mt][2]), "=r"(a[mt][3]) : "r"(ad));
            }
            #pragma unroll
            for (int pr=0;pr<2;pr++){
                int bcol = wc*32 + pr*16 + acolbase;
                unsigned bd = bbase + (unsigned)(((ks*16 + brow)*BSTR + bcol)*2);
                asm volatile("ldmatrix.sync.aligned.m8n8.x4.trans.shared.b16 {%0,%1,%2,%3}, [%4];"
                    : "=r"(bfr[pr][0]), "=r"(bfr[pr][1]), "=r"(bfr[pr][2]), "=r"(bfr[pr][3]) : "r"(bd));
            }
            #pragma unroll
            for (int mt=0;mt<4;mt++)
                #pragma unroll
                for (int nt=0;nt<4;nt++){
                    unsigned b0 = bfr[nt>>1][(nt&1)*2+0];
                    unsigned b1 = bfr[nt>>1][(nt&1)*2+1];
                    asm volatile(
                        "mma.sync.aligned.m16n8k16.row.col.f32.f16.f16.f32 "
                        "{%0,%1,%2,%3}, {%4,%5,%6,%7}, {%8,%9}, {%0,%1,%2,%3};"
                        : "+f"(acc[mt][nt][0]), "+f"(acc[mt][nt][1]),
                          "+f"(acc[mt][nt][2]), "+f"(acc[mt][nt][3])
                        : "r"(a[mt][0]), "r"(a[mt][1]), "r"(a[mt][2]), "r"(a[mt][3]),
                          "r"(b0), "r"(b1));
                }
        }
        __syncthreads();
    }

    // epilogue
    #pragma unroll
    for (int mt=0;mt<4;mt++){
        #pragma unroll
        for (int half=0; half<2; half++){
            int rm = m0 + wr*64 + mt*16 + g + half*8;
            if (rm >= Meff) continue;
            #pragma unroll
            for (int nt=0;nt<4;nt++){
                int cn = n0 + wc*32 + nt*8 + tig*2;
                float c0 = acc[mt][nt][half*2+0];
                float c1 = acc[mt][nt][half*2+1];
                if (MODE == 0) {
                    float* cp = Cp + (size_t)rm*N + cn;
                    cp[0] = c0; cp[1] = c1;
                } else if (MODE == 1) {
                    __half* cp = C16p + (size_t)rm*N + cn;
                    cp[0] = __float2half_rn(fmaxf(c0 + bias[cn],   0.f));
                    cp[1] = __float2half_rn(fmaxf(c1 + bias[cn+1], 0.f));
                } else if (MODE == 2) {
                    int tok = sro[rm];
                    float w = wro[rm];
                    float* cp = Cp + (size_t)tok*N + cn;
                    atomicAdd(cp,   w * (c0 + bias[cn]));
                    atomicAdd(cp+1, w * (c1 + bias[cn+1]));
                } else if (MODE == 3) {
                    float* cp = Cp + (size_t)rm*SKW + cn + (rm & 127);
                    cp[0] = c0 * 0.03125f;
                    cp[1] = c1 * 0.03125f;
                } else if (MODE == 4) {
                    __half* cp = C16p + (size_t)rm*N + cn;
                    cp[0] = __float2half_rn(c0);
                    cp[1] = __float2half_rn(c1);
                } else { // MODE 5
                    __half* cp = C16p + (size_t)rm*Hv + cn;
                    cp[0] = __float2half_rn(c0);
                    cp[1] = __float2half_rn(c1);
                }
            }
        }
    }
}

// ---------------- banded QK^T via tensor cores, adds into skewed scores ----------------
// grid (8 mtiles, 32 bh, 3 chunk-groups), 256 thr
__global__ void __launch_bounds__(256) band_kernel(const __half* __restrict__ q16,
                                                   const __half* __restrict__ k16,
                                                   float* __restrict__ sskew)
{
    extern __shared__ __half dyn[];
    __half* Qs = dyn;               // [128][136]
    __half* Ks = dyn + 128*136;     // [64][136]
    int m0 = blockIdx.x * 128;
    int bh = blockIdx.y;
    int b = bh >> 3, nh = bh & 7;
    int cbeg = blockIdx.z * 6;
    int tid = threadIdx.x, wid = tid >> 5, lane = tid & 31;
    int wr = wid >> 2, wc = wid & 3;
    int g = lane >> 2, tig = lane & 3;

    // load Q tile (once)
    {
        int row = tid >> 1, seg = tid & 1;
        const uint4* src = (const uint4*)(q16 + ((size_t)(b*Mv + m0 + row))*Hv + nh*Dv + seg*64);
        uint4* dst = (uint4*)(Qs + row*136 + seg*64);
        #pragma unroll
        for (int i=0;i<8;i++) dst[i] = src[i];
    }
    unsigned qbase = sptr(Qs);
    unsigned kbase = sptr(Ks);
    int a_row = wr*64 + (lane & 15);
    int a_colsel = (lane >> 4) * 8;
    int b_row = wc*16 + (lane & 7) + ((lane >> 4) << 3);
    int b_colsel = ((lane >> 3) & 1) * 8;
    __syncthreads();

    for (int c = cbeg; c < cbeg + 6; c++) {
        // load K rows m0+64c .. m0+64c+63 (zero-fill OOB)
        {
            int row = tid >> 2, seg = tid & 3;
            int kr = m0 + c*64 + row;
            uint4 z4 = make_uint4(0,0,0,0);
            const uint4* src = (const uint4*)(k16 + ((size_t)(b*LMv + kr))*Hv + nh*Dv + seg*32);
            uint4* dst = (uint4*)(Ks + row*136 + seg*32);
            bool ok = kr < LMv;
            #pragma unroll
            for (int i=0;i<4;i++) dst[i] = ok ? src[i] : z4;
        }
        __syncthreads();
        float acc[4][2][4];
        #pragma unroll
        for (int a=0;a<4;a++)
            #pragma unroll
            for (int n=0;n<2;n++)
                #pragma unroll
                for (int q=0;q<4;q++) acc[a][n][q]=0.f;
        #pragma unroll
        for (int ks = 0; ks < 8; ks++) {
            unsigned a[4][4], bb[4];
            #pragma unroll
            for (int mt=0;mt<4;mt++){
                unsigned ad = qbase + (unsigned)(((a_row + mt*16)*136 + ks*16 + a_colsel)*2);
                asm volatile("ldmatrix.sync.aligned.m8n8.x4.shared.b16 {%0,%1,%2,%3}, [%4];"
                    : "=r"(a[mt][0]), "=r"(a[mt][1]), "=r"(a[mt][2]), "=r"(a[mt][3]) : "r"(ad));
            }
            {
                unsigned bd = kbase + (unsigned)((b_row*136 + ks*16 + b_colsel)*2);
                asm volatile("ldmatrix.sync.aligned.m8n8.x4.shared.b16 {%0,%1,%2,%3}, [%4];"
                    : "=r"(bb[0]), "=r"(bb[1]), "=r"(bb[2]), "=r"(bb[3]) : "r"(bd));
            }
            #pragma unroll
            for (int mt=0;mt<4;mt++){
                asm volatile(
                    "mma.sync.aligned.m16n8k16.row.col.f32.f16.f16.f32 "
                    "{%0,%1,%2,%3}, {%4,%5,%6,%7}, {%8,%9}, {%0,%1,%2,%3};"
                    : "+f"(acc[mt][0][0]), "+f"(acc[mt][0][1]), "+f"(acc[mt][0][2]), "+f"(acc[mt][0][3])
                    : "r"(a[mt][0]), "r"(a[mt][1]), "r"(a[mt][2]), "r"(a[mt][3]),
                      "r"(bb[0]), "r"(bb[1]));
                asm volatile(
                    "mma.sync.aligned.m16n8k16.row.col.f32.f16.f16.f32 "
                    "{%0,%1,%2,%3}, {%4,%5,%6,%7}, {%8,%9}, {%0,%1,%2,%3};"
                    : "+f"(acc[mt][1][0]), "+f"(acc[mt][1][1]), "+f"(acc[mt][1][2]), "+f"(acc[mt][1][3])
                    : "r"(a[mt][0]), "r"(a[mt][1]), "r"(a[mt][2]), "r"(a[mt][3]),
                      "r"(bb[2]), "r"(bb[3]));
            }
        }
        // epilogue: band clip + accumulate into skewed scores
        #pragma unroll
        for (int mt=0;mt<4;mt++)
            #pragma unroll
            for (int nt=0;nt<2;nt++)
                #pragma unroll
                for (int q=0;q<4;q++){
                    int mi = wr*64 + mt*16 + g + (q>>1)*8;
                    int o  = wc*16 + nt*8 + tig*2 + (q&1);
                    int j = c*64 + o - mi;
                    if ((unsigned)j < 1024u) {
                        size_t idx = ((size_t)(bh*Mv + m0 + mi))*SKW + c*64 + o;
                        sskew[idx] += acc[mt][nt][q] * 0.03125f;
                    }
                }
        __syncthreads();
    }
}

// ---------------- row softmax over skewed scores -> fp16 skewed probs ----------------
__global__ void softmax_kernel(const float* __restrict__ sskew, __half* __restrict__ p16)
{
    size_t row = blockIdx.x;
    int mi = (int)(row & 127);
    const float* src = sskew + row*SKW + mi;
    __half* dst = p16 + row*SKW + mi;
    int tid = threadIdx.x;
    float x[4];
    #pragma unroll
    for (int i=0;i<4;i++) x[i] = src[tid + i*256];
    __shared__ float red[256];
    float m = fmaxf(fmaxf(x[0],x[1]), fmaxf(x[2],x[3]));
    red[tid] = m; __syncthreads();
    for (int s=128; s>0; s>>=1){ if (tid<s) red[tid]=fmaxf(red[tid],red[tid+s]); __syncthreads(); }
    float mx = red[0]; __syncthreads();
    #pragma unroll
    for (int i=0;i<4;i++) x[i] = expf(x[i]-mx);
    red[tid] = x[0]+x[1]+x[2]+x[3]; __syncthreads();
    for (int s=128; s>0; s>>=1){ if (tid<s) red[tid]+=red[tid+s]; __syncthreads(); }
    float inv = 1.f/red[0];
    #pragma unroll
    for (int i=0;i<4;i++) dst[tid + i*256] = __float2half_rn(x[i]*inv);
    if (tid < 128) {
        int u = tid < mi ? tid : tid + 1024;
        p16[row*SKW + u] = __float2half_rn(0.f);
    }
}

// ---------------- h1 = LN(h + proj); writes fp32 + fp16 ----------------
__global__ void ln1_kernel(const float* __restrict__ h, const float* __restrict__ g,
                           const float* __restrict__ bet)
{
    int row = blockIdx.x;
    int tid = threadIdx.x;
    float4 x = ((const float4*)(h + (size_t)row*Hv))[tid];
    float4 y = ((const float4*)(g_proj + (size_t)row*Hv))[tid];
    x.x+=y.x; x.y+=y.y; x.z+=y.z; x.w+=y.w;
    __shared__ float rs[256], rq[256];
    rs[tid] = x.x+x.y+x.z+x.w;
    rq[tid] = x.x*x.x + x.y*x.y + x.z*x.z + x.w*x.w;
    __syncthreads();
    for (int t=128;t>0;t>>=1){ if(tid<t){rs[tid]+=rs[tid+t]; rq[tid]+=rq[tid+t];} __syncthreads(); }
    float mean = rs[0] * (1.f/(float)Hv);
    float var  = rq[0] * (1.f/(float)Hv) - mean*mean;
    float inv = rsqrtf(var + 1e-5f);
    float4 gg = ((const float4*)g)[tid];
    float4 bb = ((const float4*)bet)[tid];
    float4 o;
    o.x = (x.x-mean)*inv*gg.x + bb.x;
    o.y = (x.y-mean)*inv*gg.y + bb.y;
    o.z = (x.z-mean)*inv*gg.z + bb.z;
    o.w = (x.w-mean)*inv*gg.w + bb.w;
    ((float4*)(g_h1 + (size_t)row*Hv))[tid] = o;
    __half2 h0 = __floats2half2_rn(o.x,o.y);
    __half2 h1 = __floats2half2_rn(o.z,o.w);
    uint2 u; u.x = *(unsigned*)&h0; u.y = *(unsigned*)&h1;
    ((uint2*)(g_h1h + (size_t)row*Hv))[tid] = u;
}

// ---------------- zero moe + counters ----------------
__global__ void zero_kernel()
{
    size_t i = (size_t)blockIdx.x*256 + threadIdx.x;
    ((float4*)g_moe)[i] = make_float4(0.f,0.f,0.f,0.f);
    if (i < Ev) g_cnt[i] = 0;
}

// ---------------- gating: top-2 routing ----------------
__global__ void gate_kernel(const float* __restrict__ gw, const float* __restrict__ gb)
{
    int t = blockIdx.x;
    int tid = threadIdx.x;
    float acc[8];
    #pragma unroll
    for (int e=0;e<8;e++) acc[e]=0.f;
    for (int hh = tid; hh < Hv; hh += 256) {
        float x = g_h1[(size_t)t*Hv + hh];
        const float* gr = gw + (size_t)hh*8;
        #pragma unroll
        for (int e=0;e<8;e++) acc[e] = fmaf(x, gr[e], acc[e]);
    }
    #pragma unroll
    for (int e=0;e<8;e++)
        #pragma unroll
        for (int o=16;o>0;o>>=1) acc[e] += __shfl_xor_sync(0xffffffffu, acc[e], o);
    __shared__ float s[8][8];
    int w = tid >> 5, ln = tid & 31;
    if (ln == 0) {
        #pragma unroll
        for (int e=0;e<8;e++) s[w][e] = acc[e];
    }
    __syncthreads();
    if (tid == 0) {
        float lg[8];
        #pragma unroll
        for (int e=0;e<8;e++){
            float v = gb[e];
            #pragma unroll
            for (int w2=0;w2<8;w2++) v += s[w2][e];
            lg[e] = v;
        }
        int i0 = 0;
        #pragma unroll
        for (int e=1;e<8;e++) if (lg[e] > lg[i0]) i0 = e;
        int i1 = (i0 == 0) ? 1 : 0;
        #pragma unroll
        for (int e=0;e<8;e++) if (e != i0 && lg[e] > lg[i1]) i1 = e;
        float e1 = expf(lg[i1]-lg[i0]);
        float inv = 1.f/(1.f+e1);
        float w0 = inv, w1 = e1*inv;
        int p0 = atomicAdd(&g_cnt[i0],1);
        g_elist[i0*NTOK+p0]=t; g_ew[i0*NTOK+p0]=w0;
        int p1 = atomicAdd(&g_cnt[i1],1);
        g_elist[i1*NTOK+p1]=t; g_ew[i1*NTOK+p1]=w1;
    }
}

// ---------------- final: mom_new = .7*mom + moe ; h2 = LN(h1 - mom_new) ----------------
__global__ void final_kernel(const float* __restrict__ mom, const float* __restrict__ g,
                             const float* __restrict__ bet, float* __restrict__ out, int write_mom)
{
    int row = blockIdx.x, tid = threadIdx.x;
    float4 mo = ((const float4*)(g_moe + (size_t)row*Hv))[tid];
    float4 mm = ((const float4*)(mom + (size_t)row*Hv))[tid];
    float4 mn;
    mn.x = 0.7f*mm.x + mo.x; mn.y = 0.7f*mm.y + mo.y;
    mn.z = 0.7f*mm.z + mo.z; mn.w = 0.7f*mm.w + mo.w;
    float4 h1v = ((const float4*)(g_h1 + (size_t)row*Hv))[tid];
    float4 x;
    x.x = h1v.x - mn.x; x.y = h1v.y - mn.y; x.z = h1v.z - mn.z; x.w = h1v.w - mn.w;
    __shared__ float rs[256], rq[256];
    rs[tid] = x.x+x.y+x.z+x.w;
    rq[tid] = x.x*x.x + x.y*x.y + x.z*x.z + x.w*x.w;
    __syncthreads();
    for (int t=128;t>0;t>>=1){ if(tid<t){rs[tid]+=rs[tid+t]; rq[tid]+=rq[tid+t];} __syncthreads(); }
    float mean = rs[0] * (1.f/(float)Hv);
    float var  = rq[0] * (1.f/(float)Hv) - mean*mean;
    float inv = rsqrtf(var + 1e-5f);
    float4 gg = ((const float4*)g)[tid];
    float4 bb = ((const float4*)bet)[tid];
    float4 o;
    o.x = (x.x-mean)*inv*gg.x + bb.x;
    o.y = (x.y-mean)*inv*gg.y + bb.y;
    o.z = (x.z-mean)*inv*gg.z + bb.z;
    o.w = (x.w-mean)*inv*gg.w + bb.w;
    ((float4*)(out + (size_t)row*Hv))[tid] = o;
    if (write_mom)
        ((float4*)(out + (size_t)NTOK*Hv + (size_t)row*Hv))[tid] = mn;
}

extern "C" void kernel_launch(void* const* d_in, const int* in_sizes, int n_in,
                              void* d_out, int out_size)
{
    const float* h       = (const float*)d_in[0];
    const float* h_cache = (const float*)d_in[1];
    const float* pos     = (const float*)d_in[2];
    const float* mom     = (const float*)d_in[3];
    const float* Wq      = (const float*)d_in[4];
    const float* Wk      = (const float*)d_in[5];
    const float* Wv      = (const float*)d_in[6];
    const float* Wo      = (const float*)d_in[7];
    const float* gw      = (const float*)d_in[8];
    const float* gb      = (const float*)d_in[9];
    const float* w1      = (const float*)d_in[10];
    const float* b1      = (const float*)d_in[11];
    const float* w2      = (const float*)d_in[12];
    const float* b2      = (const float*)d_in[13];
    const float* ln1g    = (const float*)d_in[14];
    const float* ln1b    = (const float*)d_in[15];
    const float* ln2g    = (const float*)d_in[16];
    const float* ln2b    = (const float*)d_in[17];
    float* out = (float*)d_out;

    float *p_sskew, *p_moe, *p_ew, *p_proj;
    __half *p_h16, *p_hall16, *p_q16, *p_k16, *p_v16, *p_pos16, *p_p16;
    __half *p_wq, *p_wk, *p_wv, *p_wo, *p_w1h, *p_w2h, *p_attn16, *p_h1h, *p_act16;
    int *p_cnt, *p_elist;
    cudaGetSymbolAddress((void**)&p_sskew, g_sskew);
    cudaGetSymbolAddress((void**)&p_p16, g_p16);
    cudaGetSymbolAddress((void**)&p_moe, g_moe);
    cudaGetSymbolAddress((void**)&p_ew, g_ew);
    cudaGetSymbolAddress((void**)&p_cnt, g_cnt);
    cudaGetSymbolAddress((void**)&p_elist, g_elist);
    cudaGetSymbolAddress((void**)&p_h16, g_h16);
    cudaGetSymbolAddress((void**)&p_hall16, g_hall16);
    cudaGetSymbolAddress((void**)&p_q16, g_q16);
    cudaGetSymbolAddress((void**)&p_k16, g_k16);
    cudaGetSymbolAddress((void**)&p_v16, g_v16);
    cudaGetSymbolAddress((void**)&p_pos16, g_pos16);
    cudaGetSymbolAddress((void**)&p_wq, g_wq16);
    cudaGetSymbolAddress((void**)&p_wk, g_wk16);
    cudaGetSymbolAddress((void**)&p_wv, g_wv16);
    cudaGetSymbolAddress((void**)&p_wo, g_wo16);
    cudaGetSymbolAddress((void**)&p_w1h, g_w1h);
    cudaGetSymbolAddress((void**)&p_w2h, g_w2h);
    cudaGetSymbolAddress((void**)&p_attn16, g_attn16);
    cudaGetSymbolAddress((void**)&p_h1h, g_h1h);
    cudaGetSymbolAddress((void**)&p_act16, g_act16);
    cudaGetSymbolAddress((void**)&p_proj, g_proj);

    cudaFuncSetAttribute(hgemm<0>, cudaFuncAttributeMaxDynamicSharedMemorySize, SMEMSZ);
    cudaFuncSetAttribute(hgemm<1>, cudaFuncAttributeMaxDynamicSharedMemorySize, SMEMSZ);
    cudaFuncSetAttribute(hgemm<2>, cudaFuncAttributeMaxDynamicSharedMemorySize, SMEMSZ);
    cudaFuncSetAttribute(hgemm<3>, cudaFuncAttributeMaxDynamicSharedMemorySize, SMEMSZ);
    cudaFuncSetAttribute(hgemm<4>, cudaFuncAttributeMaxDynamicSharedMemorySize, SMEMSZ);
    cudaFuncSetAttribute(hgemm<5>, cudaFuncAttributeMaxDynamicSharedMemorySize, SMEMSZ);
    cudaFuncSetAttribute(band_kernel, cudaFuncAttributeMaxDynamicSharedMemorySize, (128*136 + 64*136)*2);

    int write_mom = (out_size >= 2*NTOK*Hv) ? 1 : 0;

    // fp16 operand prep
    concat_kernel<<<8192, 256>>>(h_cache, h);
    cvt_kernel<<<2048, 256>>>(h,   p_h16,   (size_t)NTOK*Hv);
    cvt_kernel<<<64,   256>>>(pos, p_pos16, (size_t)Dv*Lv);
    cvt_kernel<<<512,  256>>>(Wq, p_wq, (size_t)Hv*Hv);
    cvt_kernel<<<512,  256>>>(Wk, p_wk, (size_t)Hv*Hv);
    cvt_kernel<<<512,  256>>>(Wv, p_wv, (size_t)Hv*Hv);
    cvt_kernel<<<512,  256>>>(Wo, p_wo, (size_t)Hv*Hv);
    cvt_kernel<<<16384,256>>>(w1, p_w1h, (size_t)Ev*Hv*Fv);
    cvt_kernel<<<16384,256>>>(w2, p_w2h, (size_t)Ev*Fv*Hv);
    // projections -> fp16
    hgemm<4><<<dim3(8,32), 256, SMEMSZ>>>(p_h16,    p_wq, nullptr, p_q16, NTOK,   Hv, Hv, Hv, nullptr, nullptr, nullptr, nullptr, nullptr);
    hgemm<4><<<dim3(8,64), 256, SMEMSZ>>>(p_hall16, p_wk, nullptr, p_k16, Bv*LMv, Hv, Hv, Hv, nullptr, nullptr, nullptr, nullptr, nullptr);
    hgemm<4><<<dim3(8,64), 256, SMEMSZ>>>(p_hall16, p_wv, nullptr, p_v16, Bv*LMv, Hv, Hv, Hv, nullptr, nullptr, nullptr, nullptr, nullptr);
    // pos scores (batched, skewed store)
    hgemm<3><<<dim3(8,8,32), 256, SMEMSZ>>>(p_q16, p_pos16, p_sskew, nullptr, Mv, Lv, Dv, Hv, nullptr, nullptr, nullptr, nullptr, nullptr);
    // banded QK^T (tensor cores) += skewed scores
    band_kernel<<<dim3(8,32,3), 256, (128*136 + 64*136)*2>>>(p_q16, p_k16, p_sskew);
    // softmax -> fp16 skewed probs (zeros OOB)
    softmax_kernel<<<BHv*Mv, 256>>>(p_sskew, p_p16);
    // attn @ V as plain GEMM over skewed probs (batched)
    hgemm<5><<<dim3(1,8,32), 256, SMEMSZ>>>(p_p16, p_v16, nullptr, p_attn16, Mv, Hv, SKW, SKW, nullptr, nullptr, nullptr, nullptr, nullptr);
    // output projection + LN1
    hgemm<0><<<dim3(8,32), 256, SMEMSZ>>>(p_attn16, p_wo, p_proj, nullptr, NTOK, Hv, Hv, Hv, nullptr, nullptr, nullptr, nullptr, nullptr);
    ln1_kernel<<<NTOK, 256>>>(h, ln1g, ln1b);
    // MoE (expert-parallel: z = expert)
    zero_kernel<<<NTOK, 256>>>();
    gate_kernel<<<NTOK, 256>>>(gw, gb);
    hgemm<1><<<dim3(32,32,Ev), 256, SMEMSZ>>>(p_h1h, p_w1h, nullptr, p_act16, NTOK, Fv, Hv, Hv,
                                              p_elist, p_cnt, b1, nullptr, nullptr);
    hgemm<2><<<dim3(8,32,Ev), 256, SMEMSZ>>>(p_act16, p_w2h, p_moe, nullptr, NTOK, Hv, Fv, Fv,
                                             nullptr, p_cnt, b2, p_ew, p_elist);
    // momentum + LN2 + outputs
    final_kernel<<<NTOK, 256>>>(mom, ln2g, ln2b, out, write_mom);
}

// round 8
// speedup vs baseline: 10.6900x; 1.1599x over previous
#include <cuda_runtime.h>
#include <cuda_fp16.h>
#include <math.h>

#define Bv 4
#define Mv 1024
#define Hv 1024
#define NHv 8
#define Dv 128
#define Lv 1024
#define Ev 8
#define Fv 4096
#define NTOK (Bv*Mv)      /* 4096 */
#define LMv (Lv+Mv)       /* 2048 */
#define BHv (Bv*NHv)      /* 32 */
#define SKW 1152          /* skewed row width = 1024 + 128 */

// ---------------- scratch (device globals; no allocation allowed) ----------------
__device__ float  g_sskew[(size_t)BHv*Mv*SKW];   // skewed pos scores (fp32)
__device__ float  g_proj[(size_t)NTOK*Hv];
__device__ float  g_h1[(size_t)NTOK*Hv];
__device__ float  g_moe[(size_t)NTOK*Hv];
__device__ int    g_cnt[Ev];
__device__ int    g_elist[Ev*NTOK];
__device__ float  g_ew[Ev*NTOK];
// fp16 operands
__device__ __half g_hall16[(size_t)Bv*LMv*Hv];
__device__ __half g_h16[(size_t)NTOK*Hv];
__device__ __half g_q16[(size_t)NTOK*Hv];
__device__ __half g_k16[(size_t)Bv*LMv*Hv];
__device__ __half g_v16[(size_t)Bv*LMv*Hv];
__device__ __half g_pos16[(size_t)Dv*Lv];
__device__ __half g_wq16[(size_t)Hv*Hv];
__device__ __half g_wk16[(size_t)Hv*Hv];
__device__ __half g_wv16[(size_t)Hv*Hv];
__device__ __half g_wo16[(size_t)Hv*Hv];
__device__ __half g_w1h[(size_t)Ev*Hv*Fv];
__device__ __half g_w2h[(size_t)Ev*Fv*Hv];
__device__ __half g_attn16[(size_t)NTOK*Hv];
__device__ __half g_h1h[(size_t)NTOK*Hv];
__device__ __half g_act16[(size_t)Ev*NTOK*Fv];   // per-expert packed activations

__device__ __forceinline__ unsigned sptr(const void* p){
    unsigned r;
    asm("{.reg .u64 t; cvta.to.shared.u64 t, %1; cvt.u32.u64 %0, t;}" : "=r"(r) : "l"(p));
    return r;
}

// ---------------- fp32 -> fp16 conversion (8 elems/thread) ----------------
__global__ void cvt_kernel(const float* __restrict__ src, __half* __restrict__ dst, size_t n)
{
    size_t i = ((size_t)blockIdx.x*256 + threadIdx.x)*8;
    if (i >= n) return;
    float4 a = *(const float4*)(src+i);
    float4 b = *(const float4*)(src+i+4);
    __half2 h0 = __floats2half2_rn(a.x,a.y);
    __half2 h1 = __floats2half2_rn(a.z,a.w);
    __half2 h2 = __floats2half2_rn(b.x,b.y);
    __half2 h3 = __floats2half2_rn(b.z,b.w);
    uint4 o;
    o.x = *(unsigned*)&h0; o.y = *(unsigned*)&h1;
    o.z = *(unsigned*)&h2; o.w = *(unsigned*)&h3;
    *(uint4*)(dst+i) = o;
}

// ---------------- concat h_all = [h_cache ; h] -> fp16 ----------------
__global__ void concat_kernel(const float* __restrict__ h_cache, const float* __restrict__ h)
{
    size_t i4 = (size_t)blockIdx.x * blockDim.x + threadIdx.x;
    size_t total4 = (size_t)Bv*LMv*Hv/4;
    if (i4 >= total4) return;
    size_t gi = i4*4;
    int b = (int)(gi / ((size_t)LMv*Hv));
    size_t off = gi - (size_t)b*LMv*Hv;
    float4 val;
    if (off < (size_t)Lv*Hv)
        val = *(const float4*)(h_cache + (size_t)b*Lv*Hv + off);
    else
        val = *(const float4*)(h + (size_t)b*Mv*Hv + (off - (size_t)Lv*Hv));
    __half2 h0 = __floats2half2_rn(val.x,val.y);
    __half2 h1 = __floats2half2_rn(val.z,val.w);
    uint2 o; o.x = *(unsigned*)&h0; o.y = *(unsigned*)&h1;
    *(uint2*)(g_hall16 + gi) = o;
}

// ---------------- fp16 tensor-core GEMM, 128x128x32 tile, 4-stage cp.async ----------
// MODE 0: C(f32) = acc
// MODE 1: z=expert: A rows gathered via elist; C16=act16+e pack = relu(acc+bias)
// MODE 2: z=expert: A=act16+e pack; atomicAdd C[tok*N+n] += w*(acc+bias)
// MODE 3: z=bh: pos GEMM, A=q16 slice (lda=Hv); C=sskew skewed store *1/32
// MODE 4: C16 = acc
#define ASTR 40
#define BSTR 136
#define NSTG 4
#define STAGEA (128*ASTR)
#define STAGEB (32*BSTR)
#define SMEMSZ ((STAGEA+STAGEB)*NSTG*2)
template<int MODE>
__global__ void __launch_bounds__(256,2) hgemm(
    const __half* __restrict__ A, const __half* __restrict__ B,
    float* __restrict__ C, __half* __restrict__ C16,
    int M, int N, int K, int lda,
    const int* __restrict__ rowidx, const int* __restrict__ Mptr,
    const float* __restrict__ bias,
    const float* __restrict__ wrow, const int* __restrict__ srow)
{
    extern __shared__ __half dsm[];
    __half* As = dsm;
    __half* Bs = dsm + (size_t)NSTG*STAGEA;

    int m0 = blockIdx.y * 128;
    int n0 = blockIdx.x * 128;
    int Klim = 1 << 30;
    const __half* Ap = A; const __half* Bp = B;
    float* Cp = C; __half* C16p = C16;
    const int* rix = rowidx;
    const int* sro = srow; const float* wro = wrow;
    if (MODE == 1) {
        int e = blockIdx.z;
        rix   = rowidx + e*NTOK;
        Mptr += e;
        Bp   += (size_t)e*K*N;
        bias += (size_t)e*N;
        C16p += (size_t)e*NTOK*N;
    }
    if (MODE == 2) {
        int e = blockIdx.z;
        Ap   += (size_t)e*NTOK*K;
        Mptr += e;
        Bp   += (size_t)e*K*N;
        bias += (size_t)e*N;
        sro   = srow + e*NTOK;
        wro   = wrow + e*NTOK;
    }
    if (MODE == 3) {
        int z = blockIdx.z;
        Ap  += ((size_t)(z>>3)*Mv)*Hv + (size_t)(z&7)*Dv;
        Cp  += (size_t)z*Mv*SKW;
    }
    int Meff = Mptr ? *Mptr : M;
    if (m0 >= Meff) return;

    int tid = threadIdx.x;
    int wid = tid >> 5, lane = tid & 31;
    int wr = wid >> 2, wc = wid & 3;
    int g = lane >> 2, tig = lane & 3;

    int arow0 = tid >> 2,           ach0 = tid & 3;
    int arow1 = (tid+256) >> 2,     ach1 = (tid+256) & 3;
    int gr0 = m0 + arow0, gr1 = m0 + arow1;
    bool v0 = gr0 < Meff, v1 = gr1 < Meff;
    int grr0 = gr0, grr1 = gr1;
    if (MODE == 1) { grr0 = v0 ? rix[gr0] : 0; grr1 = v1 ? rix[gr1] : 0; }
    const __half* asrc0 = Ap + (size_t)grr0*lda + ach0*8;
    const __half* asrc1 = Ap + (size_t)grr1*lda + ach1*8;
    unsigned aS = sptr(As), bS = sptr(Bs);
    unsigned adst0 = aS + (unsigned)((arow0*ASTR + ach0*8)*2);
    unsigned adst1 = aS + (unsigned)((arow1*ASTR + ach1*8)*2);
    int asz0 = v0 ? 16 : 0, asz1 = v1 ? 16 : 0;
    int bk0 = tid >> 4,         bc0 = tid & 15;
    int bk1 = (tid+256) >> 4,   bc1 = (tid+256) & 15;
    const __half* bsrc0 = Bp + (size_t)bk0*N + n0 + bc0*8;
    const __half* bsrc1 = Bp + (size_t)bk1*N + n0 + bc1*8;
    unsigned bdst0 = bS + (unsigned)((bk0*BSTR + bc0*8)*2);
    unsigned bdst1 = bS + (unsigned)((bk1*BSTR + bc1*8)*2);

    float acc[4][4][4];
    #pragma unroll
    for (int a=0;a<4;a++)
        #pragma unroll
        for (int b=0;b<4;b++)
            #pragma unroll
            for (int c=0;c<4;c++) acc[a][b][c]=0.f;

    #define ISSUE(s, kt) do { \
        size_t ka = (size_t)(kt)*32; \
        size_t kb = (size_t)(kt)*32*N; \
        int bs0 = ((kt)*32 + bk0 < Klim) ? 16 : 0; \
        int bs1 = ((kt)*32 + bk1 < Klim) ? 16 : 0; \
        unsigned oa = (unsigned)((s)*STAGEA*2), ob = (unsigned)((s)*STAGEB*2); \
        asm volatile("cp.async.cg.shared.global [%0], [%1], 16, %2;" :: "r"(adst0+oa), "l"(asrc0 + ka), "r"(asz0)); \
        asm volatile("cp.async.cg.shared.global [%0], [%1], 16, %2;" :: "r"(adst1+oa), "l"(asrc1 + ka), "r"(asz1)); \
        asm volatile("cp.async.cg.shared.global [%0], [%1], 16, %2;" :: "r"(bdst0+ob), "l"(bsrc0 + kb), "r"(bs0)); \
        asm volatile("cp.async.cg.shared.global [%0], [%1], 16, %2;" :: "r"(bdst1+ob), "l"(bsrc1 + kb), "r"(bs1)); \
        asm volatile("cp.async.commit_group;"); \
    } while(0)

    int nK = K >> 5;
    #pragma unroll
    for (int t = 0; t < NSTG-1; t++) {
        if (t < nK) ISSUE(t, t);
        else asm volatile("cp.async.commit_group;");
    }
    int arow = wr*64 + (lane & 15);
    int acolbase = (lane >> 4) * 8;
    int brow = lane & 15;

    for (int kt = 0; kt < nK; kt++) {
        int tnext = kt + NSTG - 1;
        if (tnext < nK) ISSUE(tnext & (NSTG-1), tnext);
        else asm volatile("cp.async.commit_group;");
        asm volatile("cp.async.wait_group %0;" :: "n"(NSTG-1));
        __syncthreads();
        int s = kt & (NSTG-1);
        unsigned abase = aS + (unsigned)(s*STAGEA*2);
        unsigned bbase = bS + (unsigned)(s*STAGEB*2);
        #pragma unroll
        for (int ks = 0; ks < 2; ks++) {
            unsigned a[4][4], bfr[2][4];
            int acol = ks*16 + acolbase;
            #pragma unroll
            for (int mt=0;mt<4;mt++){
                unsigned ad = abase + (unsigned)(((arow + mt*16)*ASTR + acol)*2);
                asm volatile("ldmatrix.sync.aligned.m8n8.x4.shared.b16 {%0,%1,%2,%3}, [%4];"
                    : "=r"(a[mt][0]), "=r"(a[mt][1]), "=r"(a[mt][2]), "=r"(a[mt][3]) : "r"(ad));
            }
            #pragma unroll
            for (int pr=0;pr<2;pr++){
                int bcol = wc*32 + pr*16 + acolbase;
                unsigned bd = bbase + (unsigned)(((ks*16 + brow)*BSTR + bcol)*2);
                asm volatile("ldmatrix.sync.aligned.m8n8.x4.trans.shared.b16 {%0,%1,%2,%3}, [%4];"
                    : "=r"(bfr[pr][0]), "=r"(bfr[pr][1]), "=r"(bfr[pr][2]), "=r"(bfr[pr][3]) : "r"(bd));
            }
            #pragma unroll
            for (int mt=0;mt<4;mt++)
                #pragma unroll
                for (int nt=0;nt<4;nt++){
                    unsigned b0 = bfr[nt>>1][(nt&1)*2+0];
                    unsigned b1 = bfr[nt>>1][(nt&1)*2+1];
                    asm volatile(
                        "mma.sync.aligned.m16n8k16.row.col.f32.f16.f16.f32 "
                        "{%0,%1,%2,%3}, {%4,%5,%6,%7}, {%8,%9}, {%0,%1,%2,%3};"
                        : "+f"(acc[mt][nt][0]), "+f"(acc[mt][nt][1]),
                          "+f"(acc[mt][nt][2]), "+f"(acc[mt][nt][3])
                        : "r"(a[mt][0]), "r"(a[mt][1]), "r"(a[mt][2]), "r"(a[mt][3]),
                          "r"(b0), "r"(b1));
                }
        }
        __syncthreads();
    }

    // epilogue
    #pragma unroll
    for (int mt=0;mt<4;mt++){
        #pragma unroll
        for (int half=0; half<2; half++){
            int rm = m0 + wr*64 + mt*16 + g + half*8;
            if (rm >= Meff) continue;
            #pragma unroll
            for (int nt=0;nt<4;nt++){
                int cn = n0 + wc*32 + nt*8 + tig*2;
                float c0 = acc[mt][nt][half*2+0];
                float c1 = acc[mt][nt][half*2+1];
                if (MODE == 0) {
                    float* cp = Cp + (size_t)rm*N + cn;
                    cp[0] = c0; cp[1] = c1;
                } else if (MODE == 1) {
                    __half* cp = C16p + (size_t)rm*N + cn;
                    cp[0] = __float2half_rn(fmaxf(c0 + bias[cn],   0.f));
                    cp[1] = __float2half_rn(fmaxf(c1 + bias[cn+1], 0.f));
                } else if (MODE == 2) {
                    int tok = sro[rm];
                    float w = wro[rm];
                    float* cp = Cp + (size_t)tok*N + cn;
                    atomicAdd(cp,   w * (c0 + bias[cn]));
                    atomicAdd(cp+1, w * (c1 + bias[cn+1]));
                } else if (MODE == 3) {
                    float* cp = Cp + (size_t)rm*SKW + cn + (rm & 127);
                    cp[0] = c0 * 0.03125f;
                    cp[1] = c1 * 0.03125f;
                } else { // MODE 4
                    __half* cp = C16p + (size_t)rm*N + cn;
                    cp[0] = __float2half_rn(c0);
                    cp[1] = __float2half_rn(c1);
                }
            }
        }
    }
}

// ---------------- fused flash attention: band QK^T + pos + softmax + PV ----------------
// grid (8 mtiles, 32 bh), 256 thr (8 warps: warp w = rows w*16..w*16+15)
#define FSTR 136
#define FSMEM ((128*FSTR + 2*64*FSTR + 2*64*FSTR)*2)
__global__ void __launch_bounds__(256,1) flash_kernel(
    const __half* __restrict__ q16, const __half* __restrict__ k16,
    const __half* __restrict__ v16, const float* __restrict__ sskew,
    __half* __restrict__ attn16)
{
    extern __shared__ __half fsm[];
    __half* Qs = fsm;                       // [128][FSTR]
    __half* Ks = fsm + 128*FSTR;            // [2][64][FSTR]
    __half* Vs = Ks + 2*64*FSTR;            // [2][64][FSTR]
    int m0 = blockIdx.x * 128;
    int bh = blockIdx.y;
    int b = bh >> 3, nh = bh & 7;
    int tid = threadIdx.x, wid = tid >> 5, lane = tid & 31;
    int g = lane >> 2, tig = lane & 3;
    int R0 = wid * 16;

    // load Q tile into smem
    {
        int row = tid >> 1, seg = tid & 1;
        const uint4* src = (const uint4*)(q16 + ((size_t)(b*Mv + m0 + row))*Hv + nh*Dv + seg*64);
        uint4* dst = (uint4*)(Qs + row*FSTR + seg*64);
        #pragma unroll
        for (int i=0;i<8;i++) dst[i] = src[i];
    }
    // per-thread cp.async slots for K/V chunks: 4 × 16B each
    const __half* ksrc[4]; const __half* vsrc[4]; unsigned kvoff[4];
    #pragma unroll
    for (int i=0;i<4;i++){
        int lin = tid + i*256;
        int row = lin >> 4, ch = lin & 15;
        ksrc[i] = k16 + ((size_t)(b*LMv + m0 + row))*Hv + nh*Dv + ch*8;
        vsrc[i] = v16 + ((size_t)(b*LMv + m0 + row))*Hv + nh*Dv + ch*8;
        kvoff[i] = (unsigned)((row*FSTR + ch*8)*2);
    }
    unsigned kS = sptr(Ks), vS = sptr(Vs);

    #define FLD(s, c) do { \
        size_t go = (size_t)(c)*64*Hv; \
        unsigned so = (unsigned)((s)*64*FSTR*2); \
        _Pragma("unroll") \
        for (int i=0;i<4;i++) \
            asm volatile("cp.async.cg.shared.global [%0], [%1], 16;" :: "r"(kS + so + kvoff[i]), "l"(ksrc[i] + go)); \
        _Pragma("unroll") \
        for (int i=0;i<4;i++) \
            asm volatile("cp.async.cg.shared.global [%0], [%1], 16;" :: "r"(vS + so + kvoff[i]), "l"(vsrc[i] + go)); \
        asm volatile("cp.async.commit_group;"); \
    } while(0)

    FLD(0, 0);
    __syncthreads();

    // Q fragments (8 ksteps x 4 regs), from smem once
    unsigned qf[8][4];
    {
        unsigned qbase = sptr(Qs);
        int arow = R0 + (lane & 15);
        int acolsel = (lane >> 4) * 8;
        #pragma unroll
        for (int ks=0; ks<8; ks++){
            unsigned ad = qbase + (unsigned)((arow*FSTR + ks*16 + acolsel)*2);
            asm volatile("ldmatrix.sync.aligned.m8n8.x4.shared.b16 {%0,%1,%2,%3}, [%4];"
                : "=r"(qf[ks][0]), "=r"(qf[ks][1]), "=r"(qf[ks][2]), "=r"(qf[ks][3]) : "r"(ad));
        }
    }

    float of[16][4];
    #pragma unroll
    for (int i=0;i<16;i++)
        #pragma unroll
        for (int q=0;q<4;q++) of[i][q]=0.f;
    float mrun0 = -1e30f, mrun1 = -1e30f;
    float lrun0 = 0.f, lrun1 = 0.f;

    int r0l = R0 + g, r1l = R0 + g + 8;   // tile-local rows
    const float* posr0 = sskew + ((size_t)(bh*Mv + m0 + r0l))*SKW;
    const float* posr1 = sskew + ((size_t)(bh*Mv + m0 + r1l))*SKW;
    int kb_row = (lane & 7) + ((lane >> 4) << 3);
    int kb_csel = ((lane >> 3) & 1) * 8;

    for (int c = 0; c < 18; c++) {
        int s = c & 1;
        if (c + 1 < 18) { FLD(1-s, c+1); asm volatile("cp.async.wait_group 1;"); }
        else             asm volatile("cp.async.wait_group 0;");
        __syncthreads();
        unsigned kbase = kS + (unsigned)(s*64*FSTR*2);
        unsigned vbase = vS + (unsigned)(s*64*FSTR*2);

        // S = Q K^T (chunk 64 cols)
        float sacc[8][4];
        #pragma unroll
        for (int nt=0;nt<8;nt++)
            #pragma unroll
            for (int q=0;q<4;q++) sacc[nt][q]=0.f;
        #pragma unroll
        for (int ks=0; ks<8; ks++){
            #pragma unroll
            for (int np=0; np<4; np++){
                unsigned bb0,bb1,bb2,bb3;
                unsigned bd = kbase + (unsigned)(((np*16 + kb_row)*FSTR + ks*16 + kb_csel)*2);
                asm volatile("ldmatrix.sync.aligned.m8n8.x4.shared.b16 {%0,%1,%2,%3}, [%4];"
                    : "=r"(bb0), "=r"(bb1), "=r"(bb2), "=r"(bb3) : "r"(bd));
                asm volatile(
                    "mma.sync.aligned.m16n8k16.row.col.f32.f16.f16.f32 "
                    "{%0,%1,%2,%3}, {%4,%5,%6,%7}, {%8,%9}, {%0,%1,%2,%3};"
                    : "+f"(sacc[np*2][0]), "+f"(sacc[np*2][1]), "+f"(sacc[np*2][2]), "+f"(sacc[np*2][3])
                    : "r"(qf[ks][0]), "r"(qf[ks][1]), "r"(qf[ks][2]), "r"(qf[ks][3]),
                      "r"(bb0), "r"(bb1));
                asm volatile(
                    "mma.sync.aligned.m16n8k16.row.col.f32.f16.f16.f32 "
                    "{%0,%1,%2,%3}, {%4,%5,%6,%7}, {%8,%9}, {%0,%1,%2,%3};"
                    : "+f"(sacc[np*2+1][0]), "+f"(sacc[np*2+1][1]), "+f"(sacc[np*2+1][2]), "+f"(sacc[np*2+1][3])
                    : "r"(qf[ks][0]), "r"(qf[ks][1]), "r"(qf[ks][2]), "r"(qf[ks][3]),
                      "r"(bb2), "r"(bb3));
            }
        }

        // pos add + band mask -> scores; chunk row maxima
        float cm0 = -1e30f, cm1 = -1e30f;
        #pragma unroll
        for (int nt=0;nt<8;nt++){
            int o0 = nt*8 + tig*2;
            int u0 = c*64 + o0, u1 = u0 + 1;
            int ja = u0 - r0l, jb = u1 - r0l;
            float s0 = ((unsigned)ja < 1024u) ? sacc[nt][0]*0.03125f + posr0[u0] : -1e30f;
            float s1 = ((unsigned)jb < 1024u) ? sacc[nt][1]*0.03125f + posr0[u1] : -1e30f;
            int jc = u0 - r1l, jd = u1 - r1l;
            float s2 = ((unsigned)jc < 1024u) ? sacc[nt][2]*0.03125f + posr1[u0] : -1e30f;
            float s3 = ((unsigned)jd < 1024u) ? sacc[nt][3]*0.03125f + posr1[u1] : -1e30f;
            sacc[nt][0]=s0; sacc[nt][1]=s1; sacc[nt][2]=s2; sacc[nt][3]=s3;
            cm0 = fmaxf(cm0, fmaxf(s0, s1));
            cm1 = fmaxf(cm1, fmaxf(s2, s3));
        }
        cm0 = fmaxf(cm0, __shfl_xor_sync(0xffffffffu, cm0, 1));
        cm0 = fmaxf(cm0, __shfl_xor_sync(0xffffffffu, cm0, 2));
        cm1 = fmaxf(cm1, __shfl_xor_sync(0xffffffffu, cm1, 1));
        cm1 = fmaxf(cm1, __shfl_xor_sync(0xffffffffu, cm1, 2));
        float mn0 = fmaxf(mrun0, cm0), mn1 = fmaxf(mrun1, cm1);
        float sc0 = (mrun0 == mn0) ? 1.f : __expf(mrun0 - mn0);
        float sc1 = (mrun1 == mn1) ? 1.f : __expf(mrun1 - mn1);
        float me0 = (mn0 == -1e30f) ? 0.f : mn0;
        float me1 = (mn1 == -1e30f) ? 0.f : mn1;
        float ls0 = 0.f, ls1 = 0.f;
        #pragma unroll
        for (int nt=0;nt<8;nt++){
            float p0 = __expf(sacc[nt][0] - me0);
            float p1 = __expf(sacc[nt][1] - me0);
            float p2 = __expf(sacc[nt][2] - me1);
            float p3 = __expf(sacc[nt][3] - me1);
            sacc[nt][0]=p0; sacc[nt][1]=p1; sacc[nt][2]=p2; sacc[nt][3]=p3;
            ls0 += p0 + p1; ls1 += p2 + p3;
        }
        lrun0 = lrun0*sc0 + ls0;
        lrun1 = lrun1*sc1 + ls1;
        mrun0 = mn0; mrun1 = mn1;
        #pragma unroll
        for (int i=0;i<16;i++){
            of[i][0]*=sc0; of[i][1]*=sc0; of[i][2]*=sc1; of[i][3]*=sc1;
        }

        // PV: P (from sacc) x V chunk
        #pragma unroll
        for (int kc=0; kc<4; kc++){
            __half2 h0 = __floats2half2_rn(sacc[2*kc][0],   sacc[2*kc][1]);
            __half2 h1 = __floats2half2_rn(sacc[2*kc][2],   sacc[2*kc][3]);
            __half2 h2 = __floats2half2_rn(sacc[2*kc+1][0], sacc[2*kc+1][1]);
            __half2 h3 = __floats2half2_rn(sacc[2*kc+1][2], sacc[2*kc+1][3]);
            unsigned pa0 = *(unsigned*)&h0, pa1 = *(unsigned*)&h1;
            unsigned pa2 = *(unsigned*)&h2, pa3 = *(unsigned*)&h3;
            #pragma unroll
            for (int np=0; np<8; np++){
                unsigned vb0,vb1,vb2,vb3;
                unsigned bd = vbase + (unsigned)(((kc*16 + (lane & 15))*FSTR + np*16 + (lane>>4)*8)*2);
                asm volatile("ldmatrix.sync.aligned.m8n8.x4.trans.shared.b16 {%0,%1,%2,%3}, [%4];"
                    : "=r"(vb0), "=r"(vb1), "=r"(vb2), "=r"(vb3) : "r"(bd));
                asm volatile(
                    "mma.sync.aligned.m16n8k16.row.col.f32.f16.f16.f32 "
                    "{%0,%1,%2,%3}, {%4,%5,%6,%7}, {%8,%9}, {%0,%1,%2,%3};"
                    : "+f"(of[np*2][0]), "+f"(of[np*2][1]), "+f"(of[np*2][2]), "+f"(of[np*2][3])
                    : "r"(pa0), "r"(pa1), "r"(pa2), "r"(pa3), "r"(vb0), "r"(vb1));
                asm volatile(
                    "mma.sync.aligned.m16n8k16.row.col.f32.f16.f16.f32 "
                    "{%0,%1,%2,%3}, {%4,%5,%6,%7}, {%8,%9}, {%0,%1,%2,%3};"
                    : "+f"(of[np*2+1][0]), "+f"(of[np*2+1][1]), "+f"(of[np*2+1][2]), "+f"(of[np*2+1][3])
                    : "r"(pa0), "r"(pa1), "r"(pa2), "r"(pa3), "r"(vb2), "r"(vb3));
            }
        }
        __syncthreads();
    }

    // finalize: divide by row sums, write
    lrun0 += __shfl_xor_sync(0xffffffffu, lrun0, 1);
    lrun0 += __shfl_xor_sync(0xffffffffu, lrun0, 2);
    lrun1 += __shfl_xor_sync(0xffffffffu, lrun1, 1);
    lrun1 += __shfl_xor_sync(0xffffffffu, lrun1, 2);
    float inv0 = 1.f / lrun0, inv1 = 1.f / lrun1;
    __half* o0p = attn16 + ((size_t)(b*Mv + m0 + r0l))*Hv + nh*Dv;
    __half* o1p = attn16 + ((size_t)(b*Mv + m0 + r1l))*Hv + nh*Dv;
    #pragma unroll
    for (int nt=0; nt<16; nt++){
        int colb = nt*8 + tig*2;
        __half2 a = __floats2half2_rn(of[nt][0]*inv0, of[nt][1]*inv0);
        __half2 bq = __floats2half2_rn(of[nt][2]*inv1, of[nt][3]*inv1);
        *(__half2*)(o0p + colb) = a;
        *(__half2*)(o1p + colb) = bq;
    }
}

// ---------------- h1 = LN(h + proj); writes fp32 + fp16 ----------------
__global__ void ln1_kernel(const float* __restrict__ h, const float* __restrict__ g,
                           const float* __restrict__ bet)
{
    int row = blockIdx.x;
    int tid = threadIdx.x;
    float4 x = ((const float4*)(h + (size_t)row*Hv))[tid];
    float4 y = ((const float4*)(g_proj + (size_t)row*Hv))[tid];
    x.x+=y.x; x.y+=y.y; x.z+=y.z; x.w+=y.w;
    __shared__ float rs[256], rq[256];
    rs[tid] = x.x+x.y+x.z+x.w;
    rq[tid] = x.x*x.x + x.y*x.y + x.z*x.z + x.w*x.w;
    __syncthreads();
    for (int t=128;t>0;t>>=1){ if(tid<t){rs[tid]+=rs[tid+t]; rq[tid]+=rq[tid+t];} __syncthreads(); }
    float mean = rs[0] * (1.f/(float)Hv);
    float var  = rq[0] * (1.f/(float)Hv) - mean*mean;
    float inv = rsqrtf(var + 1e-5f);
    float4 gg = ((const float4*)g)[tid];
    float4 bb = ((const float4*)bet)[tid];
    float4 o;
    o.x = (x.x-mean)*inv*gg.x + bb.x;
    o.y = (x.y-mean)*inv*gg.y + bb.y;
    o.z = (x.z-mean)*inv*gg.z + bb.z;
    o.w = (x.w-mean)*inv*gg.w + bb.w;
    ((float4*)(g_h1 + (size_t)row*Hv))[tid] = o;
    __half2 h0 = __floats2half2_rn(o.x,o.y);
    __half2 h1 = __floats2half2_rn(o.z,o.w);
    uint2 u; u.x = *(unsigned*)&h0; u.y = *(unsigned*)&h1;
    ((uint2*)(g_h1h + (size_t)row*Hv))[tid] = u;
}

// ---------------- zero moe + counters ----------------
__global__ void zero_kernel()
{
    size_t i = (size_t)blockIdx.x*256 + threadIdx.x;
    ((float4*)g_moe)[i] = make_float4(0.f,0.f,0.f,0.f);
    if (i < Ev) g_cnt[i] = 0;
}

// ---------------- gating: top-2 routing ----------------
__global__ void gate_kernel(const float* __restrict__ gw, const float* __restrict__ gb)
{
    int t = blockIdx.x;
    int tid = threadIdx.x;
    float acc[8];
    #pragma unroll
    for (int e=0;e<8;e++) acc[e]=0.f;
    for (int hh = tid; hh < Hv; hh += 256) {
        float x = g_h1[(size_t)t*Hv + hh];
        const float* gr = gw + (size_t)hh*8;
        #pragma unroll
        for (int e=0;e<8;e++) acc[e] = fmaf(x, gr[e], acc[e]);
    }
    #pragma unroll
    for (int e=0;e<8;e++)
        #pragma unroll
        for (int o=16;o>0;o>>=1) acc[e] += __shfl_xor_sync(0xffffffffu, acc[e], o);
    __shared__ float s[8][8];
    int w = tid >> 5, ln = tid & 31;
    if (ln == 0) {
        #pragma unroll
        for (int e=0;e<8;e++) s[w][e] = acc[e];
    }
    __syncthreads();
    if (tid == 0) {
        float lg[8];
        #pragma unroll
        for (int e=0;e<8;e++){
            float v = gb[e];
            #pragma unroll
            for (int w2=0;w2<8;w2++) v += s[w2][e];
            lg[e] = v;
        }
        int i0 = 0;
        #pragma unroll
        for (int e=1;e<8;e++) if (lg[e] > lg[i0]) i0 = e;
        int i1 = (i0 == 0) ? 1 : 0;
        #pragma unroll
        for (int e=0;e<8;e++) if (e != i0 && lg[e] > lg[i1]) i1 = e;
        float e1 = expf(lg[i1]-lg[i0]);
        float inv = 1.f/(1.f+e1);
        float w0 = inv, w1 = e1*inv;
        int p0 = atomicAdd(&g_cnt[i0],1);
        g_elist[i0*NTOK+p0]=t; g_ew[i0*NTOK+p0]=w0;
        int p1 = atomicAdd(&g_cnt[i1],1);
        g_elist[i1*NTOK+p1]=t; g_ew[i1*NTOK+p1]=w1;
    }
}

// ---------------- final: mom_new = .7*mom + moe ; h2 = LN(h1 - mom_new) ----------------
__global__ void final_kernel(const float* __restrict__ mom, const float* __restrict__ g,
                             const float* __restrict__ bet, float* __restrict__ out, int write_mom)
{
    int row = blockIdx.x, tid = threadIdx.x;
    float4 mo = ((const float4*)(g_moe + (size_t)row*Hv))[tid];
    float4 mm = ((const float4*)(mom + (size_t)row*Hv))[tid];
    float4 mn;
    mn.x = 0.7f*mm.x + mo.x; mn.y = 0.7f*mm.y + mo.y;
    mn.z = 0.7f*mm.z + mo.z; mn.w = 0.7f*mm.w + mo.w;
    float4 h1v = ((const float4*)(g_h1 + (size_t)row*Hv))[tid];
    float4 x;
    x.x = h1v.x - mn.x; x.y = h1v.y - mn.y; x.z = h1v.z - mn.z; x.w = h1v.w - mn.w;
    __shared__ float rs[256], rq[256];
    rs[tid] = x.x+x.y+x.z+x.w;
    rq[tid] = x.x*x.x + x.y*x.y + x.z*x.z + x.w*x.w;
    __syncthreads();
    for (int t=128;t>0;t>>=1){ if(tid<t){rs[tid]+=rs[tid+t]; rq[tid]+=rq[tid+t];} __syncthreads(); }
    float mean = rs[0] * (1.f/(float)Hv);
    float var  = rq[0] * (1.f/(float)Hv) - mean*mean;
    float inv = rsqrtf(var + 1e-5f);
    float4 gg = ((const float4*)g)[tid];
    float4 bb = ((const float4*)bet)[tid];
    float4 o;
    o.x = (x.x-mean)*inv*gg.x + bb.x;
    o.y = (x.y-mean)*inv*gg.y + bb.y;
    o.z = (x.z-mean)*inv*gg.z + bb.z;
    o.w = (x.w-mean)*inv*gg.w + bb.w;
    ((float4*)(out + (size_t)row*Hv))[tid] = o;
    if (write_mom)
        ((float4*)(out + (size_t)NTOK*Hv + (size_t)row*Hv))[tid] = mn;
}

extern "C" void kernel_launch(void* const* d_in, const int* in_sizes, int n_in,
                              void* d_out, int out_size)
{
    const float* h       = (const float*)d_in[0];
    const float* h_cache = (const float*)d_in[1];
    const float* pos     = (const float*)d_in[2];
    const float* mom     = (const float*)d_in[3];
    const float* Wq      = (const float*)d_in[4];
    const float* Wk      = (const float*)d_in[5];
    const float* Wv      = (const float*)d_in[6];
    const float* Wo      = (const float*)d_in[7];
    const float* gw      = (const float*)d_in[8];
    const float* gb      = (const float*)d_in[9];
    const float* w1      = (const float*)d_in[10];
    const float* b1      = (const float*)d_in[11];
    const float* w2      = (const float*)d_in[12];
    const float* b2      = (const float*)d_in[13];
    const float* ln1g    = (const float*)d_in[14];
    const float* ln1b    = (const float*)d_in[15];
    const float* ln2g    = (const float*)d_in[16];
    const float* ln2b    = (const float*)d_in[17];
    float* out = (float*)d_out;

    float *p_sskew, *p_moe, *p_ew, *p_proj;
    __half *p_h16, *p_hall16, *p_q16, *p_k16, *p_v16, *p_pos16;
    __half *p_wq, *p_wk, *p_wv, *p_wo, *p_w1h, *p_w2h, *p_attn16, *p_h1h, *p_act16;
    int *p_cnt, *p_elist;
    cudaGetSymbolAddress((void**)&p_sskew, g_sskew);
    cudaGetSymbolAddress((void**)&p_moe, g_moe);
    cudaGetSymbolAddress((void**)&p_ew, g_ew);
    cudaGetSymbolAddress((void**)&p_cnt, g_cnt);
    cudaGetSymbolAddress((void**)&p_elist, g_elist);
    cudaGetSymbolAddress((void**)&p_h16, g_h16);
    cudaGetSymbolAddress((void**)&p_hall16, g_hall16);
    cudaGetSymbolAddress((void**)&p_q16, g_q16);
    cudaGetSymbolAddress((void**)&p_k16, g_k16);
    cudaGetSymbolAddress((void**)&p_v16, g_v16);
    cudaGetSymbolAddress((void**)&p_pos16, g_pos16);
    cudaGetSymbolAddress((void**)&p_wq, g_wq16);
    cudaGetSymbolAddress((void**)&p_wk, g_wk16);
    cudaGetSymbolAddress((void**)&p_wv, g_wv16);
    cudaGetSymbolAddress((void**)&p_wo, g_wo16);
    cudaGetSymbolAddress((void**)&p_w1h, g_w1h);
    cudaGetSymbolAddress((void**)&p_w2h, g_w2h);
    cudaGetSymbolAddress((void**)&p_attn16, g_attn16);
    cudaGetSymbolAddress((void**)&p_h1h, g_h1h);
    cudaGetSymbolAddress((void**)&p_act16, g_act16);
    cudaGetSymbolAddress((void**)&p_proj, g_proj);

    cudaFuncSetAttribute(hgemm<0>, cudaFuncAttributeMaxDynamicSharedMemorySize, SMEMSZ);
    cudaFuncSetAttribute(hgemm<1>, cudaFuncAttributeMaxDynamicSharedMemorySize, SMEMSZ);
    cudaFuncSetAttribute(hgemm<2>, cudaFuncAttributeMaxDynamicSharedMemorySize, SMEMSZ);
    cudaFuncSetAttribute(hgemm<3>, cudaFuncAttributeMaxDynamicSharedMemorySize, SMEMSZ);
    cudaFuncSetAttribute(hgemm<4>, cudaFuncAttributeMaxDynamicSharedMemorySize, SMEMSZ);
    cudaFuncSetAttribute(flash_kernel, cudaFuncAttributeMaxDynamicSharedMemorySize, FSMEM);

    int write_mom = (out_size >= 2*NTOK*Hv) ? 1 : 0;

    // fp16 operand prep
    concat_kernel<<<8192, 256>>>(h_cache, h);
    cvt_kernel<<<2048, 256>>>(h,   p_h16,   (size_t)NTOK*Hv);
    cvt_kernel<<<64,   256>>>(pos, p_pos16, (size_t)Dv*Lv);
    cvt_kernel<<<512,  256>>>(Wq, p_wq, (size_t)Hv*Hv);
    cvt_kernel<<<512,  256>>>(Wk, p_wk, (size_t)Hv*Hv);
    cvt_kernel<<<512,  256>>>(Wv, p_wv, (size_t)Hv*Hv);
    cvt_kernel<<<512,  256>>>(Wo, p_wo, (size_t)Hv*Hv);
    cvt_kernel<<<16384,256>>>(w1, p_w1h, (size_t)Ev*Hv*Fv);
    cvt_kernel<<<16384,256>>>(w2, p_w2h, (size_t)Ev*Fv*Hv);
    // projections -> fp16
    hgemm<4><<<dim3(8,32), 256, SMEMSZ>>>(p_h16,    p_wq, nullptr, p_q16, NTOK,   Hv, Hv, Hv, nullptr, nullptr, nullptr, nullptr, nullptr);
    hgemm<4><<<dim3(8,64), 256, SMEMSZ>>>(p_hall16, p_wk, nullptr, p_k16, Bv*LMv, Hv, Hv, Hv, nullptr, nullptr, nullptr, nullptr, nullptr);
    hgemm<4><<<dim3(8,64), 256, SMEMSZ>>>(p_hall16, p_wv, nullptr, p_v16, Bv*LMv, Hv, Hv, Hv, nullptr, nullptr, nullptr, nullptr, nullptr);
    // pos scores (batched, skewed store)
    hgemm<3><<<dim3(8,8,32), 256, SMEMSZ>>>(p_q16, p_pos16, p_sskew, nullptr, Mv, Lv, Dv, Hv, nullptr, nullptr, nullptr, nullptr, nullptr);
    // fused banded attention (QK^T + pos + softmax + PV)
    flash_kernel<<<dim3(8,32), 256, FSMEM>>>(p_q16, p_k16, p_v16, p_sskew, p_attn16);
    // output projection + LN1
    hgemm<0><<<dim3(8,32), 256, SMEMSZ>>>(p_attn16, p_wo, p_proj, nullptr, NTOK, Hv, Hv, Hv, nullptr, nullptr, nullptr, nullptr, nullptr);
    ln1_kernel<<<NTOK, 256>>>(h, ln1g, ln1b);
    // MoE (expert-parallel: z = expert)
    zero_kernel<<<NTOK, 256>>>();
    gate_kernel<<<NTOK, 256>>>(gw, gb);
    hgemm<1><<<dim3(32,32,Ev), 256, SMEMSZ>>>(p_h1h, p_w1h, nullptr, p_act16, NTOK, Fv, Hv, Hv,
                                              p_elist, p_cnt, b1, nullptr, nullptr);
    hgemm<2><<<dim3(8,32,Ev), 256, SMEMSZ>>>(p_act16, p_w2h, p_moe, nullptr, NTOK, Hv, Fv, Fv,
                                             nullptr, p_cnt, b2, p_ew, p_elist);
    // momentum + LN2 + outputs
    final_kernel<<<NTOK, 256>>>(mom, ln2g, ln2b, out, write_mom);
}

// round 12
// speedup vs baseline: 11.4390x; 1.0701x over previous
#include <cuda_runtime.h>
#include <cuda_fp16.h>
#include <math.h>

#define Bv 4
#define Mv 1024
#define Hv 1024
#define NHv 8
#define Dv 128
#define Lv 1024
#define Ev 8
#define Fv 4096
#define NTOK (Bv*Mv)      /* 4096 */
#define LMv (Lv+Mv)       /* 2048 */
#define BHv (Bv*NHv)      /* 32 */
#define SKW 1152          /* skewed row width = 1024 + 128 */

// ---------------- scratch (device globals; no allocation allowed) ----------------
__device__ float  g_sskew[(size_t)BHv*Mv*SKW];   // skewed pos scores (fp32)
__device__ float  g_proj[(size_t)NTOK*Hv];
__device__ float  g_h1[(size_t)NTOK*Hv];
__device__ float  g_y[(size_t)Ev*NTOK*Hv];       // per-slot weighted expert outputs
__device__ int    g_cnt[Ev];
__device__ int    g_elist[Ev*NTOK];
__device__ float  g_ew[Ev*NTOK];
__device__ int    g_tslot[NTOK*2];               // token -> 2 global slot rows
// fp16 operands
__device__ __half g_hall16[(size_t)Bv*LMv*Hv];
__device__ __half g_h16[(size_t)NTOK*Hv];
__device__ __half g_q16[(size_t)NTOK*Hv];
__device__ __half g_k16[(size_t)Bv*LMv*Hv];
__device__ __half g_v16[(size_t)Bv*LMv*Hv];
__device__ __half g_pos16[(size_t)Dv*Lv];
__device__ __half g_wq16[(size_t)Hv*Hv];
__device__ __half g_wk16[(size_t)Hv*Hv];
__device__ __half g_wv16[(size_t)Hv*Hv];
__device__ __half g_wo16[(size_t)Hv*Hv];
__device__ __half g_w1h[(size_t)Ev*Hv*Fv];
__device__ __half g_w2h[(size_t)Ev*Fv*Hv];
__device__ __half g_attn16[(size_t)NTOK*Hv];
__device__ __half g_h1h[(size_t)NTOK*Hv];
__device__ __half g_act16[(size_t)Ev*NTOK*Fv];   // per-expert packed activations

__device__ __forceinline__ unsigned sptr(const void* p){
    unsigned r;
    asm("{.reg .u64 t; cvta.to.shared.u64 t, %1; cvt.u32.u64 %0, t;}" : "=r"(r) : "l"(p));
    return r;
}

// ---------------- fp32 -> fp16 conversion (8 elems/thread) ----------------
__global__ void cvt_kernel(const float* __restrict__ src, __half* __restrict__ dst, size_t n)
{
    size_t i = ((size_t)blockIdx.x*256 + threadIdx.x)*8;
    if (i >= n) return;
    float4 a = *(const float4*)(src+i);
    float4 b = *(const float4*)(src+i+4);
    __half2 h0 = __floats2half2_rn(a.x,a.y);
    __half2 h1 = __floats2half2_rn(a.z,a.w);
    __half2 h2 = __floats2half2_rn(b.x,b.y);
    __half2 h3 = __floats2half2_rn(b.z,b.w);
    uint4 o;
    o.x = *(unsigned*)&h0; o.y = *(unsigned*)&h1;
    o.z = *(unsigned*)&h2; o.w = *(unsigned*)&h3;
    *(uint4*)(dst+i) = o;
}

// ---------------- concat h_all = [h_cache ; h] -> fp16 ----------------
__global__ void concat_kernel(const float* __restrict__ h_cache, const float* __restrict__ h)
{
    size_t i4 = (size_t)blockIdx.x * blockDim.x + threadIdx.x;
    size_t total4 = (size_t)Bv*LMv*Hv/4;
    if (i4 >= total4) return;
    size_t gi = i4*4;
    int b = (int)(gi / ((size_t)LMv*Hv));
    size_t off = gi - (size_t)b*LMv*Hv;
    float4 val;
    if (off < (size_t)Lv*Hv)
        val = *(const float4*)(h_cache + (size_t)b*Lv*Hv + off);
    else
        val = *(const float4*)(h + (size_t)b*Mv*Hv + (off - (size_t)Lv*Hv));
    __half2 h0 = __floats2half2_rn(val.x,val.y);
    __half2 h1 = __floats2half2_rn(val.z,val.w);
    uint2 o; o.x = *(unsigned*)&h0; o.y = *(unsigned*)&h1;
    *(uint2*)(g_hall16 + gi) = o;
}

// ---------------- fp16 tensor-core GEMM, 128x128x32 tile, 4-stage cp.async ----------
// MODE 0: C(f32) = acc
// MODE 1: z=expert: A rows gathered via elist; C16=act16+e pack = relu(acc+bias)
// MODE 2: z=expert: A=act16+e pack; C(f32)=y pack: y[e*NTOK+rm] = w*(acc+bias)
// MODE 3: z=bh: pos GEMM, A=q16 slice (lda=Hv); C=sskew skewed store *1/32
// MODE 4: C16 = acc
#define ASTR 40
#define BSTR 136
#define NSTG 4
#define STAGEA (128*ASTR)
#define STAGEB (32*BSTR)
#define SMEMSZ ((STAGEA+STAGEB)*NSTG*2)
template<int MODE>
__global__ void __launch_bounds__(256,2) hgemm(
    const __half* __restrict__ A, const __half* __restrict__ B,
    float* __restrict__ C, __half* __restrict__ C16,
    int M, int N, int K, int lda,
    const int* __restrict__ rowidx, const int* __restrict__ Mptr,
    const float* __restrict__ bias,
    const float* __restrict__ wrow)
{
    extern __shared__ __half dsm[];
    __half* As = dsm;
    __half* Bs = dsm + (size_t)NSTG*STAGEA;

    int m0 = blockIdx.y * 128;
    int n0 = blockIdx.x * 128;
    int Klim = 1 << 30;
    const __half* Ap = A; const __half* Bp = B;
    float* Cp = C; __half* C16p = C16;
    const int* rix = rowidx;
    const float* wro = wrow;
    if (MODE == 1) {
        int e = blockIdx.z;
        rix   = rowidx + e*NTOK;
        Mptr += e;
        Bp   += (size_t)e*K*N;
        bias += (size_t)e*N;
        C16p += (size_t)e*NTOK*N;
    }
    if (MODE == 2) {
        int e = blockIdx.z;
        Ap   += (size_t)e*NTOK*K;
        Mptr += e;
        Bp   += (size_t)e*K*N;
        bias += (size_t)e*N;
        wro   = wrow + e*NTOK;
        Cp   += (size_t)e*NTOK*N;
    }
    if (MODE == 3) {
        int z = blockIdx.z;
        Ap  += ((size_t)(z>>3)*Mv)*Hv + (size_t)(z&7)*Dv;
        Cp  += (size_t)z*Mv*SKW;
    }
    int Meff = Mptr ? *Mptr : M;
    if (m0 >= Meff) return;

    int tid = threadIdx.x;
    int wid = tid >> 5, lane = tid & 31;
    int wr = wid >> 2, wc = wid & 3;
    int g = lane >> 2, tig = lane & 3;

    int arow0 = tid >> 2,           ach0 = tid & 3;
    int arow1 = (tid+256) >> 2,     ach1 = (tid+256) & 3;
    int gr0 = m0 + arow0, gr1 = m0 + arow1;
    bool v0 = gr0 < Meff, v1 = gr1 < Meff;
    int grr0 = gr0, grr1 = gr1;
    if (MODE == 1) { grr0 = v0 ? rix[gr0] : 0; grr1 = v1 ? rix[gr1] : 0; }
    const __half* asrc0 = Ap + (size_t)grr0*lda + ach0*8;
    const __half* asrc1 = Ap + (size_t)grr1*lda + ach1*8;
    unsigned aS = sptr(As), bS = sptr(Bs);
    unsigned adst0 = aS + (unsigned)((arow0*ASTR + ach0*8)*2);
    unsigned adst1 = aS + (unsigned)((arow1*ASTR + ach1*8)*2);
    int asz0 = v0 ? 16 : 0, asz1 = v1 ? 16 : 0;
    int bk0 = tid >> 4,         bc0 = tid & 15;
    int bk1 = (tid+256) >> 4,   bc1 = (tid+256) & 15;
    const __half* bsrc0 = Bp + (size_t)bk0*N + n0 + bc0*8;
    const __half* bsrc1 = Bp + (size_t)bk1*N + n0 + bc1*8;
    unsigned bdst0 = bS + (unsigned)((bk0*BSTR + bc0*8)*2);
    unsigned bdst1 = bS + (unsigned)((bk1*BSTR + bc1*8)*2);

    float acc[4][4][4];
    #pragma unroll
    for (int a=0;a<4;a++)
        #pragma unroll
        for (int b=0;b<4;b++)
            #pragma unroll
            for (int c=0;c<4;c++) acc[a][b][c]=0.f;

    #define ISSUE(s, kt) do { \
        size_t ka = (size_t)(kt)*32; \
        size_t kb = (size_t)(kt)*32*N; \
        int bs0 = ((kt)*32 + bk0 < Klim) ? 16 : 0; \
        int bs1 = ((kt)*32 + bk1 < Klim) ? 16 : 0; \
        unsigned oa = (unsigned)((s)*STAGEA*2), ob = (unsigned)((s)*STAGEB*2); \
        asm volatile("cp.async.cg.shared.global [%0], [%1], 16, %2;" :: "r"(adst0+oa), "l"(asrc0 + ka), "r"(asz0)); \
        asm volatile("cp.async.cg.shared.global [%0], [%1], 16, %2;" :: "r"(adst1+oa), "l"(asrc1 + ka), "r"(asz1)); \
        asm volatile("cp.async.cg.shared.global [%0], [%1], 16, %2;" :: "r"(bdst0+ob), "l"(bsrc0 + kb), "r"(bs0)); \
        asm volatile("cp.async.cg.shared.global [%0], [%1], 16, %2;" :: "r"(bdst1+ob), "l"(bsrc1 + kb), "r"(bs1)); \
        asm volatile("cp.async.commit_group;"); \
    } while(0)

    int nK = K >> 5;
    #pragma unroll
    for (int t = 0; t < NSTG-1; t++) {
        if (t < nK) ISSUE(t, t);
        else asm volatile("cp.async.commit_group;");
    }
    int arow = wr*64 + (lane & 15);
    int acolbase = (lane >> 4) * 8;
    int brow = lane & 15;

    for (int kt = 0; kt < nK; kt++) {
        int tnext = kt + NSTG - 1;
        if (tnext < nK) ISSUE(tnext & (NSTG-1), tnext);
        else asm volatile("cp.async.commit_group;");
        asm volatile("cp.async.wait_group %0;" :: "n"(NSTG-1));
        __syncthreads();
        int s = kt & (NSTG-1);
        unsigned abase = aS + (unsigned)(s*STAGEA*2);
        unsigned bbase = bS + (unsigned)(s*STAGEB*2);
        #pragma unroll
        for (int ks = 0; ks < 2; ks++) {
            unsigned a[4][4], bfr[2][4];
            int acol = ks*16 + acolbase;
            #pragma unroll
            for (int mt=0;mt<4;mt++){
                unsigned ad = abase + (unsigned)(((arow + mt*16)*ASTR + acol)*2);
                asm volatile("ldmatrix.sync.aligned.m8n8.x4.shared.b16 {%0,%1,%2,%3}, [%4];"
                    : "=r"(a[mt][0]), "=r"(a[mt][1]), "=r"(a[mt][2]), "=r"(a[mt][3]) : "r"(ad));
            }
            #pragma unroll
            for (int pr=0;pr<2;pr++){
                int bcol = wc*32 + pr*16 + acolbase;
                unsigned bd = bbase + (unsigned)(((ks*16 + brow)*BSTR + bcol)*2);
                asm volatile("ldmatrix.sync.aligned.m8n8.x4.trans.shared.b16 {%0,%1,%2,%3}, [%4];"
                    : "=r"(bfr[pr][0]), "=r"(bfr[pr][1]), "=r"(bfr[pr][2]), "=r"(bfr[pr][3]) : "r"(bd));
            }
            #pragma unroll
            for (int mt=0;mt<4;mt++)
                #pragma unroll
                for (int nt=0;nt<4;nt++){
                    unsigned b0 = bfr[nt>>1][(nt&1)*2+0];
                    unsigned b1 = bfr[nt>>1][(nt&1)*2+1];
                    asm volatile(
                        "mma.sync.aligned.m16n8k16.row.col.f32.f16.f16.f32 "
                        "{%0,%1,%2,%3}, {%4,%5,%6,%7}, {%8,%9}, {%0,%1,%2,%3};"
                        : "+f"(acc[mt][nt][0]), "+f"(acc[mt][nt][1]),
                          "+f"(acc[mt][nt][2]), "+f"(acc[mt][nt][3])
                        : "r"(a[mt][0]), "r"(a[mt][1]), "r"(a[mt][2]), "r"(a[mt][3]),
                          "r"(b0), "r"(b1));
                }
        }
        __syncthreads();
    }

    // epilogue
    #pragma unroll
    for (int mt=0;mt<4;mt++){
        #pragma unroll
        for (int half=0; half<2; half++){
            int rm = m0 + wr*64 + mt*16 + g + half*8;
            if (rm >= Meff) continue;
            #pragma unroll
            for (int nt=0;nt<4;nt++){
                int cn = n0 + wc*32 + nt*8 + tig*2;
                float c0 = acc[mt][nt][half*2+0];
                float c1 = acc[mt][nt][half*2+1];
                if (MODE == 0) {
                    float* cp = Cp + (size_t)rm*N + cn;
                    cp[0] = c0; cp[1] = c1;
                } else if (MODE == 1) {
                    __half* cp = C16p + (size_t)rm*N + cn;
                    cp[0] = __float2half_rn(fmaxf(c0 + bias[cn],   0.f));
                    cp[1] = __float2half_rn(fmaxf(c1 + bias[cn+1], 0.f));
                } else if (MODE == 2) {
                    float w = wro[rm];
                    float* cp = Cp + (size_t)rm*N + cn;
                    cp[0] = w * (c0 + bias[cn]);
                    cp[1] = w * (c1 + bias[cn+1]);
                } else if (MODE == 3) {
                    float* cp = Cp + (size_t)rm*SKW + cn + (rm & 127);
                    cp[0] = c0 * 0.03125f;
                    cp[1] = c1 * 0.03125f;
                } else { // MODE 4
                    __half* cp = C16p + (size_t)rm*N + cn;
                    cp[0] = __float2half_rn(c0);
                    cp[1] = __float2half_rn(c1);
                }
            }
        }
    }
}

// ---------------- fused flash attention: band QK^T + pos + softmax + PV ----------------
#define FSTR 136
#define FSMEM ((128*FSTR + 2*64*FSTR + 2*64*FSTR)*2)
__global__ void __launch_bounds__(256,1) flash_kernel(
    const __half* __restrict__ q16, const __half* __restrict__ k16,
    const __half* __restrict__ v16, const float* __restrict__ sskew,
    __half* __restrict__ attn16)
{
    extern __shared__ __half fsm[];
    __half* Qs = fsm;
    __half* Ks = fsm + 128*FSTR;
    __half* Vs = Ks + 2*64*FSTR;
    int m0 = blockIdx.x * 128;
    int bh = blockIdx.y;
    int b = bh >> 3, nh = bh & 7;
    int tid = threadIdx.x, wid = tid >> 5, lane = tid & 31;
    int g = lane >> 2, tig = lane & 3;
    int R0 = wid * 16;

    {
        int row = tid >> 1, seg = tid & 1;
        const uint4* src = (const uint4*)(q16 + ((size_t)(b*Mv + m0 + row))*Hv + nh*Dv + seg*64);
        uint4* dst = (uint4*)(Qs + row*FSTR + seg*64);
        #pragma unroll
        for (int i=0;i<8;i++) dst[i] = src[i];
    }
    const __half* ksrc[4]; const __half* vsrc[4]; unsigned kvoff[4];
    #pragma unroll
    for (int i=0;i<4;i++){
        int lin = tid + i*256;
        int row = lin >> 4, ch = lin & 15;
        ksrc[i] = k16 + ((size_t)(b*LMv + m0 + row))*Hv + nh*Dv + ch*8;
        vsrc[i] = v16 + ((size_t)(b*LMv + m0 + row))*Hv + nh*Dv + ch*8;
        kvoff[i] = (unsigned)((row*FSTR + ch*8)*2);
    }
    unsigned kS = sptr(Ks), vS = sptr(Vs);

    #define FLD(s, c) do { \
        size_t go = (size_t)(c)*64*Hv; \
        unsigned so = (unsigned)((s)*64*FSTR*2); \
        _Pragma("unroll") \
        for (int i=0;i<4;i++) \
            asm volatile("cp.async.cg.shared.global [%0], [%1], 16;" :: "r"(kS + so + kvoff[i]), "l"(ksrc[i] + go)); \
        _Pragma("unroll") \
        for (int i=0;i<4;i++) \
            asm volatile("cp.async.cg.shared.global [%0], [%1], 16;" :: "r"(vS + so + kvoff[i]), "l"(vsrc[i] + go)); \
        asm volatile("cp.async.commit_group;"); \
    } while(0)

    FLD(0, 0);
    __syncthreads();

    unsigned qf[8][4];
    {
        unsigned qbase = sptr(Qs);
        int arow = R0 + (lane & 15);
        int acolsel = (lane >> 4) * 8;
        #pragma unroll
        for (int ks=0; ks<8; ks++){
            unsigned ad = qbase + (unsigned)((arow*FSTR + ks*16 + acolsel)*2);
            asm volatile("ldmatrix.sync.aligned.m8n8.x4.shared.b16 {%0,%1,%2,%3}, [%4];"
                : "=r"(qf[ks][0]), "=r"(qf[ks][1]), "=r"(qf[ks][2]), "=r"(qf[ks][3]) : "r"(ad));
        }
    }

    float of[16][4];
    #pragma unroll
    for (int i=0;i<16;i++)
        #pragma unroll
        for (int q=0;q<4;q++) of[i][q]=0.f;
    float mrun0 = -1e30f, mrun1 = -1e30f;
    float lrun0 = 0.f, lrun1 = 0.f;

    int r0l = R0 + g, r1l = R0 + g + 8;
    const float* posr0 = sskew + ((size_t)(bh*Mv + m0 + r0l))*SKW;
    const float* posr1 = sskew + ((size_t)(bh*Mv + m0 + r1l))*SKW;
    int kb_row = (lane & 7) + ((lane >> 4) << 3);
    int kb_csel = ((lane >> 3) & 1) * 8;

    for (int c = 0; c < 18; c++) {
        int s = c & 1;
        if (c + 1 < 18) { FLD(1-s, c+1); asm volatile("cp.async.wait_group 1;"); }
        else             asm volatile("cp.async.wait_group 0;");
        __syncthreads();
        unsigned kbase = kS + (unsigned)(s*64*FSTR*2);
        unsigned vbase = vS + (unsigned)(s*64*FSTR*2);

        float sacc[8][4];
        #pragma unroll
        for (int nt=0;nt<8;nt++)
            #pragma unroll
            for (int q=0;q<4;q++) sacc[nt][q]=0.f;
        #pragma unroll
        for (int ks=0; ks<8; ks++){
            #pragma unroll
            for (int np=0; np<4; np++){
                unsigned bb0,bb1,bb2,bb3;
                unsigned bd = kbase + (unsigned)(((np*16 + kb_row)*FSTR + ks*16 + kb_csel)*2);
                asm volatile("ldmatrix.sync.aligned.m8n8.x4.shared.b16 {%0,%1,%2,%3}, [%4];"
                    : "=r"(bb0), "=r"(bb1), "=r"(bb2), "=r"(bb3) : "r"(bd));
                asm volatile(
                    "mma.sync.aligned.m16n8k16.row.col.f32.f16.f16.f32 "
                    "{%0,%1,%2,%3}, {%4,%5,%6,%7}, {%8,%9}, {%0,%1,%2,%3};"
                    : "+f"(sacc[np*2][0]), "+f"(sacc[np*2][1]), "+f"(sacc[np*2][2]), "+f"(sacc[np*2][3])
                    : "r"(qf[ks][0]), "r"(qf[ks][1]), "r"(qf[ks][2]), "r"(qf[ks][3]),
                      "r"(bb0), "r"(bb1));
                asm volatile(
                    "mma.sync.aligned.m16n8k16.row.col.f32.f16.f16.f32 "
                    "{%0,%1,%2,%3}, {%4,%5,%6,%7}, {%8,%9}, {%0,%1,%2,%3};"
                    : "+f"(sacc[np*2+1][0]), "+f"(sacc[np*2+1][1]), "+f"(sacc[np*2+1][2]), "+f"(sacc[np*2+1][3])
                    : "r"(qf[ks][0]), "r"(qf[ks][1]), "r"(qf[ks][2]), "r"(qf[ks][3]),
                      "r"(bb2), "r"(bb3));
            }
        }

        float cm0 = -1e30f, cm1 = -1e30f;
        #pragma unroll
        for (int nt=0;nt<8;nt++){
            int o0 = nt*8 + tig*2;
            int u0 = c*64 + o0, u1 = u0 + 1;
            int ja = u0 - r0l, jb = u1 - r0l;
            float s0 = ((unsigned)ja < 1024u) ? sacc[nt][0]*0.03125f + posr0[u0] : -1e30f;
            float s1 = ((unsigned)jb < 1024u) ? sacc[nt][1]*0.03125f + posr0[u1] : -1e30f;
            int jc = u0 - r1l, jd = u1 - r1l;
            float s2 = ((unsigned)jc < 1024u) ? sacc[nt][2]*0.03125f + posr1[u0] : -1e30f;
            float s3 = ((unsigned)jd < 1024u) ? sacc[nt][3]*0.03125f + posr1[u1] : -1e30f;
            sacc[nt][0]=s0; sacc[nt][1]=s1; sacc[nt][2]=s2; sacc[nt][3]=s3;
            cm0 = fmaxf(cm0, fmaxf(s0, s1));
            cm1 = fmaxf(cm1, fmaxf(s2, s3));
        }
        cm0 = fmaxf(cm0, __shfl_xor_sync(0xffffffffu, cm0, 1));
        cm0 = fmaxf(cm0, __shfl_xor_sync(0xffffffffu, cm0, 2));
        cm1 = fmaxf(cm1, __shfl_xor_sync(0xffffffffu, cm1, 1));
        cm1 = fmaxf(cm1, __shfl_xor_sync(0xffffffffu, cm1, 2));
        float mn0 = fmaxf(mrun0, cm0), mn1 = fmaxf(mrun1, cm1);
        float sc0 = (mrun0 == mn0) ? 1.f : __expf(mrun0 - mn0);
        float sc1 = (mrun1 == mn1) ? 1.f : __expf(mrun1 - mn1);
        float me0 = (mn0 == -1e30f) ? 0.f : mn0;
        float me1 = (mn1 == -1e30f) ? 0.f : mn1;
        float ls0 = 0.f, ls1 = 0.f;
        #pragma unroll
        for (int nt=0;nt<8;nt++){
            float p0 = __expf(sacc[nt][0] - me0);
            float p1 = __expf(sacc[nt][1] - me0);
            float p2 = __expf(sacc[nt][2] - me1);
            float p3 = __expf(sacc[nt][3] - me1);
            sacc[nt][0]=p0; sacc[nt][1]=p1; sacc[nt][2]=p2; sacc[nt][3]=p3;
            ls0 += p0 + p1; ls1 += p2 + p3;
        }
        lrun0 = lrun0*sc0 + ls0;
        lrun1 = lrun1*sc1 + ls1;
        mrun0 = mn0; mrun1 = mn1;
        #pragma unroll
        for (int i=0;i<16;i++){
            of[i][0]*=sc0; of[i][1]*=sc0; of[i][2]*=sc1; of[i][3]*=sc1;
        }

        #pragma unroll
        for (int kc=0; kc<4; kc++){
            __half2 h0 = __floats2half2_rn(sacc[2*kc][0],   sacc[2*kc][1]);
            __half2 h1 = __floats2half2_rn(sacc[2*kc][2],   sacc[2*kc][3]);
            __half2 h2 = __floats2half2_rn(sacc[2*kc+1][0], sacc[2*kc+1][1]);
            __half2 h3 = __floats2half2_rn(sacc[2*kc+1][2], sacc[2*kc+1][3]);
            unsigned pa0 = *(unsigned*)&h0, pa1 = *(unsigned*)&h1;
            unsigned pa2 = *(unsigned*)&h2, pa3 = *(unsigned*)&h3;
            #pragma unroll
            for (int np=0; np<8; np++){
                unsigned vb0,vb1,vb2,vb3;
                unsigned bd = vbase + (unsigned)(((kc*16 + (lane & 15))*FSTR + np*16 + (lane>>4)*8)*2);
                asm volatile("ldmatrix.sync.aligned.m8n8.x4.trans.shared.b16 {%0,%1,%2,%3}, [%4];"
                    : "=r"(vb0), "=r"(vb1), "=r"(vb2), "=r"(vb3) : "r"(bd));
                asm volatile(
                    "mma.sync.aligned.m16n8k16.row.col.f32.f16.f16.f32 "
                    "{%0,%1,%2,%3}, {%4,%5,%6,%7}, {%8,%9}, {%0,%1,%2,%3};"
                    : "+f"(of[np*2][0]), "+f"(of[np*2][1]), "+f"(of[np*2][2]), "+f"(of[np*2][3])
                    : "r"(pa0), "r"(pa1), "r"(pa2), "r"(pa3), "r"(vb0), "r"(vb1));
                asm volatile(
                    "mma.sync.aligned.m16n8k16.row.col.f32.f16.f16.f32 "
                    "{%0,%1,%2,%3}, {%4,%5,%6,%7}, {%8,%9}, {%0,%1,%2,%3};"
                    : "+f"(of[np*2+1][0]), "+f"(of[np*2+1][1]), "+f"(of[np*2+1][2]), "+f"(of[np*2+1][3])
                    : "r"(pa0), "r"(pa1), "r"(pa2), "r"(pa3), "r"(vb2), "r"(vb3));
            }
        }
        __syncthreads();
    }

    lrun0 += __shfl_xor_sync(0xffffffffu, lrun0, 1);
    lrun0 += __shfl_xor_sync(0xffffffffu, lrun0, 2);
    lrun1 += __shfl_xor_sync(0xffffffffu, lrun1, 1);
    lrun1 += __shfl_xor_sync(0xffffffffu, lrun1, 2);
    float inv0 = 1.f / lrun0, inv1 = 1.f / lrun1;
    __half* o0p = attn16 + ((size_t)(b*Mv + m0 + r0l))*Hv + nh*Dv;
    __half* o1p = attn16 + ((size_t)(b*Mv + m0 + r1l))*Hv + nh*Dv;
    #pragma unroll
    for (int nt=0; nt<16; nt++){
        int colb = nt*8 + tig*2;
        __half2 a = __floats2half2_rn(of[nt][0]*inv0, of[nt][1]*inv0);
        __half2 bq = __floats2half2_rn(of[nt][2]*inv1, of[nt][3]*inv1);
        *(__half2*)(o0p + colb) = a;
        *(__half2*)(o1p + colb) = bq;
    }
}

// ---------------- h1 = LN(h + proj); writes fp32 + fp16 ----------------
__global__ void ln1_kernel(const float* __restrict__ h, const float* __restrict__ g,
                           const float* __restrict__ bet)
{
    int row = blockIdx.x;
    int tid = threadIdx.x;
    float4 x = ((const float4*)(h + (size_t)row*Hv))[tid];
    float4 y = ((const float4*)(g_proj + (size_t)row*Hv))[tid];
    x.x+=y.x; x.y+=y.y; x.z+=y.z; x.w+=y.w;
    __shared__ float rs[256], rq[256];
    rs[tid] = x.x+x.y+x.z+x.w;
    rq[tid] = x.x*x.x + x.y*x.y + x.z*x.z + x.w*x.w;
    __syncthreads();
    for (int t=128;t>0;t>>=1){ if(tid<t){rs[tid]+=rs[tid+t]; rq[tid]+=rq[tid+t];} __syncthreads(); }
    float mean = rs[0] * (1.f/(float)Hv);
    float var  = rq[0] * (1.f/(float)Hv) - mean*mean;
    float inv = rsqrtf(var + 1e-5f);
    float4 gg = ((const float4*)g)[tid];
    float4 bb = ((const float4*)bet)[tid];
    float4 o;
    o.x = (x.x-mean)*inv*gg.x + bb.x;
    o.y = (x.y-mean)*inv*gg.y + bb.y;
    o.z = (x.z-mean)*inv*gg.z + bb.z;
    o.w = (x.w-mean)*inv*gg.w + bb.w;
    ((float4*)(g_h1 + (size_t)row*Hv))[tid] = o;
    __half2 h0 = __floats2half2_rn(o.x,o.y);
    __half2 h1 = __floats2half2_rn(o.z,o.w);
    uint2 u; u.x = *(unsigned*)&h0; u.y = *(unsigned*)&h1;
    ((uint2*)(g_h1h + (size_t)row*Hv))[tid] = u;
}

// ---------------- gating: top-2 routing ----------------
__global__ void gate_kernel(const float* __restrict__ gw, const float* __restrict__ gb)
{
    int t = blockIdx.x;
    int tid = threadIdx.x;
    if (t == 0 && tid < Ev) g_cnt[tid] = g_cnt[tid];  // no-op keep
    float acc[8];
    #pragma unroll
    for (int e=0;e<8;e++) acc[e]=0.f;
    for (int hh = tid; hh < Hv; hh += 256) {
        float x = g_h1[(size_t)t*Hv + hh];
        const float* gr = gw + (size_t)hh*8;
        #pragma unroll
        for (int e=0;e<8;e++) acc[e] = fmaf(x, gr[e], acc[e]);
    }
    #pragma unroll
    for (int e=0;e<8;e++)
        #pragma unroll
        for (int o=16;o>0;o>>=1) acc[e] += __shfl_xor_sync(0xffffffffu, acc[e], o);
    __shared__ float s[8][8];
    int w = tid >> 5, ln = tid & 31;
    if (ln == 0) {
        #pragma unroll
        for (int e=0;e<8;e++) s[w][e] = acc[e];
    }
    __syncthreads();
    if (tid == 0) {
        float lg[8];
        #pragma unroll
        for (int e=0;e<8;e++){
            float v = gb[e];
            #pragma unroll
            for (int w2=0;w2<8;w2++) v += s[w2][e];
            lg[e] = v;
        }
        int i0 = 0;
        #pragma unroll
        for (int e=1;e<8;e++) if (lg[e] > lg[i0]) i0 = e;
        int i1 = (i0 == 0) ? 1 : 0;
        #pragma unroll
        for (int e=0;e<8;e++) if (e != i0 && lg[e] > lg[i1]) i1 = e;
        float e1 = expf(lg[i1]-lg[i0]);
        float inv = 1.f/(1.f+e1);
        float w0 = inv, w1 = e1*inv;
        int p0 = atomicAdd(&g_cnt[i0],1);
        g_elist[i0*NTOK+p0]=t; g_ew[i0*NTOK+p0]=w0;
        g_tslot[t*2]   = i0*NTOK + p0;
        int p1 = atomicAdd(&g_cnt[i1],1);
        g_elist[i1*NTOK+p1]=t; g_ew[i1*NTOK+p1]=w1;
        g_tslot[t*2+1] = i1*NTOK + p1;
    }
}

// ---------------- zero counters ----------------
__global__ void zcnt_kernel(){ if (threadIdx.x < Ev) g_cnt[threadIdx.x] = 0; }

// ---------------- final: gather 2 expert slots; mom_new; h2 = LN(h1 - mom_new) ----------------
__global__ void final_kernel(const float* __restrict__ mom, const float* __restrict__ g,
                             const float* __restrict__ bet, float* __restrict__ out, int write_mom)
{
    int row = blockIdx.x, tid = threadIdx.x;
    int s0 = g_tslot[row*2], s1 = g_tslot[row*2+1];
    float4 y0 = ((const float4*)(g_y + (size_t)s0*Hv))[tid];
    float4 y1 = ((const float4*)(g_y + (size_t)s1*Hv))[tid];
    float4 mm = ((const float4*)(mom + (size_t)row*Hv))[tid];
    float4 mn;
    mn.x = 0.7f*mm.x + y0.x + y1.x; mn.y = 0.7f*mm.y + y0.y + y1.y;
    mn.z = 0.7f*mm.z + y0.z + y1.z; mn.w = 0.7f*mm.w + y0.w + y1.w;
    float4 h1v = ((const float4*)(g_h1 + (size_t)row*Hv))[tid];
    float4 x;
    x.x = h1v.x - mn.x; x.y = h1v.y - mn.y; x.z = h1v.z - mn.z; x.w = h1v.w - mn.w;
    __shared__ float rs[256], rq[256];
    rs[tid] = x.x+x.y+x.z+x.w;
    rq[tid] = x.x*x.x + x.y*x.y + x.z*x.z + x.w*x.w;
    __syncthreads();
    for (int t=128;t>0;t>>=1){ if(tid<t){rs[tid]+=rs[tid+t]; rq[tid]+=rq[tid+t];} __syncthreads(); }
    float mean = rs[0] * (1.f/(float)Hv);
    float var  = rq[0] * (1.f/(float)Hv) - mean*mean;
    float inv = rsqrtf(var + 1e-5f);
    float4 gg = ((const float4*)g)[tid];
    float4 bb = ((const float4*)bet)[tid];
    float4 o;
    o.x = (x.x-mean)*inv*gg.x + bb.x;
    o.y = (x.y-mean)*inv*gg.y + bb.y;
    o.z = (x.z-mean)*inv*gg.z + bb.z;
    o.w = (x.w-mean)*inv*gg.w + bb.w;
    ((float4*)(out + (size_t)row*Hv))[tid] = o;
    if (write_mom)
        ((float4*)(out + (size_t)NTOK*Hv + (size_t)row*Hv))[tid] = mn;
}

extern "C" void kernel_launch(void* const* d_in, const int* in_sizes, int n_in,
                              void* d_out, int out_size)
{
    const float* h       = (const float*)d_in[0];
    const float* h_cache = (const float*)d_in[1];
    const float* pos     = (const float*)d_in[2];
    const float* mom     = (const float*)d_in[3];
    const float* Wq      = (const float*)d_in[4];
    const float* Wk      = (const float*)d_in[5];
    const float* Wv      = (const float*)d_in[6];
    const float* Wo      = (const float*)d_in[7];
    const float* gw      = (const float*)d_in[8];
    const float* gb      = (const float*)d_in[9];
    const float* w1      = (const float*)d_in[10];
    const float* b1      = (const float*)d_in[11];
    const float* w2      = (const float*)d_in[12];
    const float* b2      = (const float*)d_in[13];
    const float* ln1g    = (const float*)d_in[14];
    const float* ln1b    = (const float*)d_in[15];
    const float* ln2g    = (const float*)d_in[16];
    const float* ln2b    = (const float*)d_in[17];
    float* out = (float*)d_out;

    float *p_sskew, *p_y, *p_ew, *p_proj;
    __half *p_h16, *p_hall16, *p_q16, *p_k16, *p_v16, *p_pos16;
    __half *p_wq, *p_wk, *p_wv, *p_wo, *p_w1h, *p_w2h, *p_attn16, *p_h1h, *p_act16;
    int *p_cnt, *p_elist;
    cudaGetSymbolAddress((void**)&p_sskew, g_sskew);
    cudaGetSymbolAddress((void**)&p_y, g_y);
    cudaGetSymbolAddress((void**)&p_ew, g_ew);
    cudaGetSymbolAddress((void**)&p_cnt, g_cnt);
    cudaGetSymbolAddress((void**)&p_elist, g_elist);
    cudaGetSymbolAddress((void**)&p_h16, g_h16);
    cudaGetSymbolAddress((void**)&p_hall16, g_hall16);
    cudaGetSymbolAddress((void**)&p_q16, g_q16);
    cudaGetSymbolAddress((void**)&p_k16, g_k16);
    cudaGetSymbolAddress((void**)&p_v16, g_v16);
    cudaGetSymbolAddress((void**)&p_pos16, g_pos16);
    cudaGetSymbolAddress((void**)&p_wq, g_wq16);
    cudaGetSymbolAddress((void**)&p_wk, g_wk16);
    cudaGetSymbolAddress((void**)&p_wv, g_wv16);
    cudaGetSymbolAddress((void**)&p_wo, g_wo16);
    cudaGetSymbolAddress((void**)&p_w1h, g_w1h);
    cudaGetSymbolAddress((void**)&p_w2h, g_w2h);
    cudaGetSymbolAddress((void**)&p_attn16, g_attn16);
    cudaGetSymbolAddress((void**)&p_h1h, g_h1h);
    cudaGetSymbolAddress((void**)&p_act16, g_act16);
    cudaGetSymbolAddress((void**)&p_proj, g_proj);

    cudaFuncSetAttribute(hgemm<0>, cudaFuncAttributeMaxDynamicSharedMemorySize, SMEMSZ);
    cudaFuncSetAttribute(hgemm<1>, cudaFuncAttributeMaxDynamicSharedMemorySize, SMEMSZ);
    cudaFuncSetAttribute(hgemm<2>, cudaFuncAttributeMaxDynamicSharedMemorySize, SMEMSZ);
    cudaFuncSetAttribute(hgemm<3>, cudaFuncAttributeMaxDynamicSharedMemorySize, SMEMSZ);
    cudaFuncSetAttribute(hgemm<4>, cudaFuncAttributeMaxDynamicSharedMemorySize, SMEMSZ);
    cudaFuncSetAttribute(flash_kernel, cudaFuncAttributeMaxDynamicSharedMemorySize, FSMEM);

    // side stream + events: created once on the first (uncaptured) correctness call
    static cudaStream_t s2 = nullptr;
    static cudaEvent_t evF = nullptr, evH = nullptr, evPos = nullptr, evWo = nullptr, evW12 = nullptr;
    if (!s2) {
        cudaStreamCreateWithFlags(&s2, cudaStreamNonBlocking);
        cudaEventCreateWithFlags(&evF,   cudaEventDisableTiming);
        cudaEventCreateWithFlags(&evH,   cudaEventDisableTiming);
        cudaEventCreateWithFlags(&evPos, cudaEventDisableTiming);
        cudaEventCreateWithFlags(&evWo,  cudaEventDisableTiming);
        cudaEventCreateWithFlags(&evW12, cudaEventDisableTiming);
    }

    int write_mom = (out_size >= 2*NTOK*Hv) ? 1 : 0;

    // ---- fork ----
    cudaEventRecord(evF, 0);
    cudaStreamWaitEvent(s2, evF, 0);

    // main stream: concat + h16 -> K/V projections
    concat_kernel<<<8192, 256>>>(h_cache, h);
    cvt_kernel<<<2048, 256>>>(h, p_h16, (size_t)NTOK*Hv);
    cudaEventRecord(evH, 0);
    zcnt_kernel<<<1, 32>>>();
    cvt_kernel<<<512, 256>>>(Wk, p_wk, (size_t)Hv*Hv);
    hgemm<4><<<dim3(8,64), 256, SMEMSZ>>>(p_hall16, p_wk, nullptr, p_k16, Bv*LMv, Hv, Hv, Hv, nullptr, nullptr, nullptr, nullptr);
    cvt_kernel<<<512, 256>>>(Wv, p_wv, (size_t)Hv*Hv);
    hgemm<4><<<dim3(8,64), 256, SMEMSZ>>>(p_hall16, p_wv, nullptr, p_v16, Bv*LMv, Hv, Hv, Hv, nullptr, nullptr, nullptr, nullptr);

    // side stream: Wq/pos cvt -> Q proj -> pos GEMM -> Wo/w1/w2 cvt
    cvt_kernel<<<512, 256, 0, s2>>>(Wq, p_wq, (size_t)Hv*Hv);
    cvt_kernel<<<64,  256, 0, s2>>>(pos, p_pos16, (size_t)Dv*Lv);
    cudaStreamWaitEvent(s2, evH, 0);
    hgemm<4><<<dim3(8,32), 256, SMEMSZ, s2>>>(p_h16, p_wq, nullptr, p_q16, NTOK, Hv, Hv, Hv, nullptr, nullptr, nullptr, nullptr);
    hgemm<3><<<dim3(8,8,32), 256, SMEMSZ, s2>>>(p_q16, p_pos16, p_sskew, nullptr, Mv, Lv, Dv, Hv, nullptr, nullptr, nullptr, nullptr);
    cudaEventRecord(evPos, s2);
    cvt_kernel<<<512, 256, 0, s2>>>(Wo, p_wo, (size_t)Hv*Hv);
    cudaEventRecord(evWo, s2);
    cvt_kernel<<<16384, 256, 0, s2>>>(w1, p_w1h, (size_t)Ev*Hv*Fv);
    cvt_kernel<<<16384, 256, 0, s2>>>(w2, p_w2h, (size_t)Ev*Fv*Hv);
    cudaEventRecord(evW12, s2);

    // main stream: flash (needs Q/K/V + sskew)
    cudaStreamWaitEvent(0, evPos, 0);
    flash_kernel<<<dim3(8,32), 256, FSMEM>>>(p_q16, p_k16, p_v16, p_sskew, p_attn16);
    // Wo projection + LN1 + gate
    cudaStreamWaitEvent(0, evWo, 0);
    hgemm<0><<<dim3(8,32), 256, SMEMSZ>>>(p_attn16, p_wo, p_proj, nullptr, NTOK, Hv, Hv, Hv, nullptr, nullptr, nullptr, nullptr);
    ln1_kernel<<<NTOK, 256>>>(h, ln1g, ln1b);
    gate_kernel<<<NTOK, 256>>>(gw, gb);
    // MoE (expert-parallel; atomic-free combine)
    cudaStreamWaitEvent(0, evW12, 0);
    hgemm<1><<<dim3(32,32,Ev), 256, SMEMSZ>>>(p_h1h, p_w1h, nullptr, p_act16, NTOK, Fv, Hv, Hv,
                                              p_elist, p_cnt, b1, nullptr);
    hgemm<2><<<dim3(8,32,Ev), 256, SMEMSZ>>>(p_act16, p_w2h, p_y, nullptr, NTOK, Hv, Fv, Fv,
                                             nullptr, p_cnt, b2, p_ew);
    // gather + momentum + LN2 + outputs
    final_kernel<<<NTOK, 256>>>(mom, ln2g, ln2b, out, write_mom);
}